// round 6
// baseline (speedup 1.0000x reference)
#include <cuda_runtime.h>
#include <math.h>

#define B_   2
#define T_   2048
#define BT   4096
#define DIM  512
#define H_   8
#define DH   64
#define NH   8
#define NB   32
#define NCH  256      // NH*NB chunks per bh
#define BH   16
#define NHT  16384    // NH*T
#define KC   704      // padded conv K (229*3=687 -> 704)
#define FF   2048

// scalar Kahan merge: sum s, compensation c, incoming value p
#define KAHAN(s, c, p) { float y_ = (p) - (c); float t_ = (s) + y_; (c) = (t_ - (s)) - y_; (s) = t_; }

// ------------------------- scratch (static device) -------------------------
__device__ float g_x1[BT*DIM];
__device__ float g_x2[BT*DIM];
__device__ float g_tmp[BT*DIM];
__device__ float g_qk[BT*DIM];
__device__ float g_v [BT*DIM];
__device__ float g_at[BT*DIM];
__device__ float g_ffb[BT*FF];
__device__ float g_im[BT*KC];
__device__ float g_wT[KC*DIM];
__device__ int   g_bk[BH*NHT];
__device__ int   g_st[BH*NHT];
__device__ float g_o [BH*NHT*DH];
__device__ float g_lg[BH*NHT];

// ------------------------- SGEMM: C = act(A@B + bias) + resid --------------
// Block-8 compensated accumulation, double-buffered smem.
// BM=64, BN=64, BK=16, 128 threads, 8x4 microtile.
// act: 0 none, 1 relu, 2 gelu(exact). heads: output permuted to (b,H,t,DH).
// Nsplit>0: blocks with n0>=Nsplit use Bm2/C2 (fused dual-weight GEMM).
__global__ __launch_bounds__(128) void sgemm(
    const float* __restrict__ A, const float* __restrict__ Bm,
    const float* __restrict__ bias, const float* __restrict__ resid,
    float* __restrict__ C, int M, int N, int K, int act, int heads,
    const float* __restrict__ Bm2, float* __restrict__ C2, int Nsplit)
{
    __shared__ float As[2][16][68];
    __shared__ float Bs[2][16][68];
    const int tid = threadIdx.x;
    const int tx = tid & 15, ty = tid >> 4;
    const int m0 = blockIdx.y * 64;
    int n0 = blockIdx.x * 64;
    if (Nsplit && n0 >= Nsplit) { Bm = Bm2; C = C2; n0 -= Nsplit; }

    float acc[8][4], cmp[8][4];
    #pragma unroll
    for (int i = 0; i < 8; i++)
        #pragma unroll
        for (int j = 0; j < 4; j++) { acc[i][j] = 0.f; cmp[i][j] = 0.f; }

    const int arow = tid >> 1, ac = (tid & 1) * 8;          // A: 64 rows x 16 k
    const int brow = tid >> 3, bc = (tid & 7) * 8;          // B: 16 k x 64 cols
    const int nk = K >> 4;

    // prologue: chunk 0 -> buf 0
    {
        float4 a0 = *(const float4*)(A + (size_t)(m0 + arow) * K + ac);
        float4 a1 = *(const float4*)(A + (size_t)(m0 + arow) * K + ac + 4);
        As[0][ac + 0][arow] = a0.x; As[0][ac + 1][arow] = a0.y;
        As[0][ac + 2][arow] = a0.z; As[0][ac + 3][arow] = a0.w;
        As[0][ac + 4][arow] = a1.x; As[0][ac + 5][arow] = a1.y;
        As[0][ac + 6][arow] = a1.z; As[0][ac + 7][arow] = a1.w;
        float4 b0 = make_float4(0.f,0.f,0.f,0.f), b1 = b0;
        if (n0 + bc < N) {
            b0 = *(const float4*)(Bm + (size_t)brow * N + n0 + bc);
            b1 = *(const float4*)(Bm + (size_t)brow * N + n0 + bc + 4);
        }
        *(float4*)(&Bs[0][brow][bc])     = b0;
        *(float4*)(&Bs[0][brow][bc + 4]) = b1;
    }
    __syncthreads();

    for (int c = 0; c < nk; c++) {
        const int buf = c & 1;
        float4 pa0, pa1, pb0, pb1;
        if (c + 1 < nk) {
            int k0 = (c + 1) << 4;
            pa0 = *(const float4*)(A + (size_t)(m0 + arow) * K + k0 + ac);
            pa1 = *(const float4*)(A + (size_t)(m0 + arow) * K + k0 + ac + 4);
            pb0 = make_float4(0.f,0.f,0.f,0.f); pb1 = pb0;
            if (n0 + bc < N) {
                pb0 = *(const float4*)(Bm + (size_t)(k0 + brow) * N + n0 + bc);
                pb1 = *(const float4*)(Bm + (size_t)(k0 + brow) * N + n0 + bc + 4);
            }
        }
        #pragma unroll
        for (int kb = 0; kb < 2; kb++) {
            float pb[8][4];
            #pragma unroll
            for (int kk = 0; kk < 8; kk++) {
                int k = kb * 8 + kk;
                float4 a4 = *(const float4*)(&As[buf][k][ty * 8]);
                float4 a5 = *(const float4*)(&As[buf][k][ty * 8 + 4]);
                float4 b4 = *(const float4*)(&Bs[buf][k][tx * 4]);
                float av[8] = {a4.x, a4.y, a4.z, a4.w, a5.x, a5.y, a5.z, a5.w};
                float bw[4] = {b4.x, b4.y, b4.z, b4.w};
                if (kk == 0) {
                    #pragma unroll
                    for (int i = 0; i < 8; i++)
                        #pragma unroll
                        for (int j = 0; j < 4; j++) pb[i][j] = av[i] * bw[j];
                } else {
                    #pragma unroll
                    for (int i = 0; i < 8; i++)
                        #pragma unroll
                        for (int j = 0; j < 4; j++) pb[i][j] = fmaf(av[i], bw[j], pb[i][j]);
                }
            }
            #pragma unroll
            for (int i = 0; i < 8; i++)
                #pragma unroll
                for (int j = 0; j < 4; j++) KAHAN(acc[i][j], cmp[i][j], pb[i][j]);
        }
        if (c + 1 < nk) {
            const int nb = buf ^ 1;
            As[nb][ac + 0][arow] = pa0.x; As[nb][ac + 1][arow] = pa0.y;
            As[nb][ac + 2][arow] = pa0.z; As[nb][ac + 3][arow] = pa0.w;
            As[nb][ac + 4][arow] = pa1.x; As[nb][ac + 5][arow] = pa1.y;
            As[nb][ac + 6][arow] = pa1.z; As[nb][ac + 7][arow] = pa1.w;
            *(float4*)(&Bs[nb][brow][bc])     = pb0;
            *(float4*)(&Bs[nb][brow][bc + 4]) = pb1;
            __syncthreads();
        }
    }

    #pragma unroll
    for (int i = 0; i < 8; i++) {
        int row = m0 + ty * 8 + i;
        #pragma unroll
        for (int j = 0; j < 4; j++) {
            int col = n0 + tx * 4 + j;
            if (col >= N) continue;
            float v = acc[i][j] + cmp[i][j];
            if (bias) v += bias[col];
            if (act == 1) v = fmaxf(v, 0.f);
            else if (act == 2) v = 0.5f * v * (1.f + erff(v * 0.70710678118654752f));
            if (resid) v += resid[(size_t)row * N + col];
            if (heads) {
                int b = row >> 11, t = row & 2047;
                int h = col >> 6, d = col & 63;
                C[((((size_t)b * H_ + h) * T_ + t) << 6) + d] = v;
            } else {
                C[(size_t)row * N + col] = v;
            }
        }
    }
}

// ------------------------- LayerNorm (row of 512) ---------------------------
__global__ __launch_bounds__(256) void ln_kernel(
    const float* __restrict__ x, const float* __restrict__ g,
    const float* __restrict__ bb, float* __restrict__ y)
{
    __shared__ float sh[8];
    int row = blockIdx.x, tid = threadIdx.x;
    const float* xr = x + (size_t)row * DIM;
    float v0 = xr[tid], v1 = xr[tid + 256];
    float s = v0 + v1;
    #pragma unroll
    for (int o = 16; o; o >>= 1) s += __shfl_down_sync(0xffffffffu, s, o);
    if ((tid & 31) == 0) sh[tid >> 5] = s;
    __syncthreads();
    if (tid < 32) {
        float t = (tid < 8) ? sh[tid] : 0.f;
        #pragma unroll
        for (int o = 4; o; o >>= 1) t += __shfl_down_sync(0xffffffffu, t, o);
        if (tid == 0) sh[0] = t;
    }
    __syncthreads();
    float mean = sh[0] * (1.f / DIM);
    __syncthreads();
    float d0 = v0 - mean, d1 = v1 - mean;
    float s2 = d0 * d0 + d1 * d1;
    #pragma unroll
    for (int o = 16; o; o >>= 1) s2 += __shfl_down_sync(0xffffffffu, s2, o);
    if ((tid & 31) == 0) sh[tid >> 5] = s2;
    __syncthreads();
    if (tid < 32) {
        float t = (tid < 8) ? sh[tid] : 0.f;
        #pragma unroll
        for (int o = 4; o; o >>= 1) t += __shfl_down_sync(0xffffffffu, t, o);
        if (tid == 0) sh[0] = t;
    }
    __syncthreads();
    float inv = 1.f / sqrtf(sh[0] * (1.f / DIM) + 1e-5f);
    float* yr = y + (size_t)row * DIM;
    yr[tid]       = d0 * inv * g[tid]       + bb[tid];
    yr[tid + 256] = d1 * inv * g[tid + 256] + bb[tid + 256];
}

// ------------------------- LSH hashing (full Kahan: decides argmax) ---------
#define TCH 16
__global__ __launch_bounds__(128) void hash_kernel(
    const float* __restrict__ qk, const float* __restrict__ rot, int* __restrict__ bkt)
{
    __shared__ float q[4][DH];
    int blk = blockIdx.x;
    int bh = blk / (T_ / TCH);
    int t0 = (blk % (T_ / TCH)) * TCH;
    int tid = threadIdx.x;
    int h = tid >> 4, j = tid & 15;
    float rv[64];
    #pragma unroll
    for (int f = 0; f < 64; f++) rv[f] = rot[f * 128 + h * 16 + j];

    for (int tg = 0; tg < TCH; tg += 4) {
        __syncthreads();
        for (int idx = tid; idx < 4 * DH; idx += 128) {
            int r = idx >> 6, d = idx & 63;
            q[r][d] = qk[((size_t)bh * T_ + t0 + tg + r) * DH + d];
        }
        __syncthreads();
        float a0 = 0.f, a1 = 0.f, a2 = 0.f, a3 = 0.f;
        float c0 = 0.f, c1 = 0.f, c2 = 0.f, c3 = 0.f;
        #pragma unroll
        for (int f = 0; f < 64; f++) {
            float r = rv[f];
            float p0 = q[0][f] * r; KAHAN(a0, c0, p0);
            float p1 = q[1][f] * r; KAHAN(a1, c1, p1);
            float p2 = q[2][f] * r; KAHAN(a2, c2, p2);
            float p3 = q[3][f] * r; KAHAN(a3, c3, p3);
        }
        float vals[4] = {a0 + c0, a1 + c1, a2 + c2, a3 + c3};
        #pragma unroll
        for (int r = 0; r < 4; r++) {
            float v = vals[r]; int idx = j;
            float nv = -v;
            if (nv > v) { v = nv; idx = j + 16; }   // ties keep +r (smaller index)
            #pragma unroll
            for (int o = 8; o; o >>= 1) {
                float ov = __shfl_down_sync(0xffffffffu, v, o, 16);
                int   oi = __shfl_down_sync(0xffffffffu, idx, o, 16);
                if (ov > v || (ov == v && oi < idx)) { v = ov; idx = oi; }
            }
            if (j == 0) bkt[(size_t)bh * NHT + h * T_ + t0 + tg + r] = idx + h * NB;
        }
    }
}

// ------------------------- stable counting sort by (bucket, pos) ------------
__global__ __launch_bounds__(256) void sort_kernel(
    const int* __restrict__ bkt, int* __restrict__ st)
{
    __shared__ int hist[256];
    __shared__ int off[256];
    int bh = blockIdx.x, tid = threadIdx.x;
    const int* bb = bkt + (size_t)bh * NHT;
    hist[tid] = 0;
    __syncthreads();
    for (int i = tid; i < NHT; i += 256) atomicAdd(&hist[bb[i]], 1);
    __syncthreads();
    if (tid == 0) {
        int s = 0;
        for (int i = 0; i < 256; i++) { off[i] = s; s += hist[i]; }
    }
    __syncthreads();
    // bucket beta lives entirely inside hash round h = beta/NB; tickers there
    // are in increasing pos order -> sequential scan is stable sort.
    int beta = tid, h = tid >> 5;
    int o = off[beta];
    int* out2 = st + (size_t)bh * NHT;
    int base = h * T_;
    for (int k = 0; k < T_; k++)
        if (bb[base + k] == beta) out2[o++] = base + k;
}

// ------------------------- chunked LSH attention ----------------------------
#define RS 68
#define DS 129
__global__ __launch_bounds__(128) void attn_kernel(
    const float* __restrict__ qk, const float* __restrict__ vg,
    const int* __restrict__ st, float* __restrict__ og, float* __restrict__ lgg)
{
    extern __shared__ float sm[];
    float* r     = sm;                  // 128 x RS   raw qk rows (q + keys)
    float* vv    = r + 128 * RS;        // 128 x 64   v rows
    float* dots  = vv + 128 * 64;       // 64 x DS
    float* inorm = dots + 64 * DS;      // 128
    float* logit = inorm + 128;         // 64
    int*   kpos  = (int*)(logit + 64);  // 128
    int*   qh    = kpos + 128;          // 64

    int tid = threadIdx.x;
    int bh = blockIdx.x >> 8, c = blockIdx.x & 255;
    int cp = (c + NCH - 1) & 255;

    {
        int lc = (tid < 64) ? c : cp;
        int tk = st[(size_t)bh * NHT + lc * 64 + (tid & 63)];
        kpos[tid] = tk & (T_ - 1);
        if (tid < 64) qh[tid] = tk >> 11;
    }
    __syncthreads();

    const float* qb = qk + ((size_t)bh << 17);
    const float* vb = vg + ((size_t)bh << 17);
    for (int it = 0; it < 64; it++) {
        int idx = it * 128 + tid;
        int jj = idx >> 6, d = idx & 63;
        int pos = kpos[jj];
        r[jj * RS + d]    = qb[(pos << 6) + d];
        vv[(jj << 6) + d] = vb[(pos << 6) + d];
    }
    __syncthreads();
    {
        float s = 0.f, cs = 0.f;
        #pragma unroll 8
        for (int d = 0; d < 64; d++) {
            float x = r[tid * RS + d];
            float p = x * x; KAHAN(s, cs, p);
        }
        inorm[tid] = 1.f / fmaxf(sqrtf(s + cs), 1e-12f);
    }
    __syncthreads();

    int tx = tid & 15, ty = tid >> 4;
    float acc[8][8], cmp[8][8];
    #pragma unroll
    for (int i = 0; i < 8; i++)
        #pragma unroll
        for (int m = 0; m < 8; m++) { acc[i][m] = 0.f; cmp[i][m] = 0.f; }

    for (int db = 0; db < 16; db++) {
        float kvb[4][8];
        #pragma unroll
        for (int dd = 0; dd < 4; dd++)
            #pragma unroll
            for (int m = 0; m < 8; m++)
                kvb[dd][m] = r[(tx + 16 * m) * RS + db * 4 + dd];
        #pragma unroll
        for (int i = 0; i < 8; i++) {
            float qv[4];
            #pragma unroll
            for (int dd = 0; dd < 4; dd++) qv[dd] = r[(ty * 8 + i) * RS + db * 4 + dd];
            float pb[8];
            #pragma unroll
            for (int m = 0; m < 8; m++) {
                float p = qv[0] * kvb[0][m];
                p = fmaf(qv[1], kvb[1][m], p);
                p = fmaf(qv[2], kvb[2][m], p);
                p = fmaf(qv[3], kvb[3][m], p);
                pb[m] = p;
            }
            #pragma unroll
            for (int m = 0; m < 8; m++) KAHAN(acc[i][m], cmp[i][m], pb[m]);
        }
    }
    #pragma unroll
    for (int i = 0; i < 8; i++) {
        int row = ty * 8 + i; int rp = kpos[row];
        #pragma unroll
        for (int m = 0; m < 8; m++) {
            int col = tx + 16 * m;
            float dv = (acc[i][m] + cmp[i][m]) * inorm[col] * 0.125f;
            if (rp == kpos[col]) dv = -5e4f;
            dots[row * DS + col] = dv;
        }
    }
    __syncthreads();

    if (tid < 64) {
        float mx = -1e30f;
        #pragma unroll 8
        for (int j2 = 0; j2 < 128; j2++) mx = fmaxf(mx, dots[tid * DS + j2]);
        float s = 0.f;
        #pragma unroll 8
        for (int j2 = 0; j2 < 128; j2++) s += expf(dots[tid * DS + j2] - mx);
        float lg = mx + logf(s);
        logit[tid] = lg;
        lgg[((size_t)bh * NH + qh[tid]) * T_ + kpos[tid]] = lg;
    }
    __syncthreads();
    for (int it = 0; it < 64; it++) {
        int idx = it * 128 + tid; int i = idx >> 7, j2 = idx & 127;
        dots[i * DS + j2] = expf(dots[i * DS + j2] - logit[i]);
    }
    __syncthreads();

    float a2[8][4], c2[8][4];
    #pragma unroll
    for (int i = 0; i < 8; i++)
        #pragma unroll
        for (int m = 0; m < 4; m++) { a2[i][m] = 0.f; c2[i][m] = 0.f; }
    for (int jb = 0; jb < 32; jb++) {
        float vwb[4][4];
        #pragma unroll
        for (int dd = 0; dd < 4; dd++)
            #pragma unroll
            for (int m = 0; m < 4; m++)
                vwb[dd][m] = vv[(((jb * 4 + dd)) << 6) + tx + 16 * m];
        #pragma unroll
        for (int i = 0; i < 8; i++) {
            float pv[4];
            #pragma unroll
            for (int dd = 0; dd < 4; dd++) pv[dd] = dots[(ty * 8 + i) * DS + jb * 4 + dd];
            float pb[4];
            #pragma unroll
            for (int m = 0; m < 4; m++) {
                float p = pv[0] * vwb[0][m];
                p = fmaf(pv[1], vwb[1][m], p);
                p = fmaf(pv[2], vwb[2][m], p);
                p = fmaf(pv[3], vwb[3][m], p);
                pb[m] = p;
            }
            #pragma unroll
            for (int m = 0; m < 4; m++) KAHAN(a2[i][m], c2[i][m], pb[m]);
        }
    }
    #pragma unroll
    for (int i = 0; i < 8; i++) {
        int row = ty * 8 + i;
        size_t base = (((size_t)bh * NH + qh[row]) * T_ + kpos[row]) << 6;
        #pragma unroll
        for (int m = 0; m < 4; m++) og[base + tx + 16 * m] = a2[i][m] + c2[i][m];
    }
}

// ------------------------- combine hash rounds ------------------------------
__global__ __launch_bounds__(64) void combine_kernel(
    const float* __restrict__ og, const float* __restrict__ lgg, float* __restrict__ at)
{
    __shared__ float w[8];
    int bh = blockIdx.x >> 11, pos = blockIdx.x & 2047;
    int tid = threadIdx.x;
    if (tid == 0) {
        float v[8]; float mx = -1e30f;
        #pragma unroll
        for (int h = 0; h < 8; h++) {
            v[h] = lgg[((size_t)bh * NH + h) * T_ + pos];
            mx = fmaxf(mx, v[h]);
        }
        float s = 0.f;
        #pragma unroll
        for (int h = 0; h < 8; h++) { v[h] = expf(v[h] - mx); s += v[h]; }
        float is = 1.f / s;
        #pragma unroll
        for (int h = 0; h < 8; h++) w[h] = v[h] * is;
    }
    __syncthreads();
    float acc = 0.f, cc = 0.f;
    #pragma unroll
    for (int h = 0; h < 8; h++) {
        float p = w[h] * og[(((size_t)bh * NH + h) * T_ + pos) * 64 + tid];
        KAHAN(acc, cc, p);
    }
    int b = bh >> 3, hd = bh & 7;
    at[((size_t)(b * T_ + pos)) * DIM + hd * 64 + tid] = acc + cc;
}

// ------------------------- frontend helpers ---------------------------------
__global__ void wt_kernel(const float* __restrict__ w, float* __restrict__ wT)
{
    int idx = blockIdx.x * 256 + threadIdx.x;     // KC*DIM
    int c = idx / DIM, o2 = idx - c * DIM;
    wT[idx] = (c < 687) ? w[(size_t)o2 * 687 + c] : 0.f;
}

__global__ void im2col_kernel(const float* __restrict__ spec, float* __restrict__ im)
{
    int idx = blockIdx.x * 256 + threadIdx.x;     // BT*KC
    int row = idx / KC, c = idx - row * KC;
    int b = row >> 11, t = row & 2047;
    float val = 0.f;
    if (c < 687) {
        int i = c / 3, k = c - i * 3;
        int tt = t + k - 1;
        if (tt >= 0 && tt < T_) val = spec[((size_t)b * T_ + tt) * 229 + i];
    }
    im[idx] = val;
}

__global__ void pe_kernel(float* __restrict__ x1, float* __restrict__ x2,
                          const float* __restrict__ per, const float* __restrict__ pec)
{
    int idx = blockIdx.x * 256 + threadIdx.x;     // BT*DIM
    int c = idx & 511;
    int t = (idx >> 9) & 2047;
    float p = (c < 256) ? per[(t >> 6) * 256 + c] : pec[(t & 63) * 256 + (c - 256)];
    float v = x1[idx] + p;
    x1[idx] = v; x2[idx] = v;
}

__global__ void avg_kernel(const float* __restrict__ a, const float* __restrict__ b,
                           float* __restrict__ y)
{
    int idx = blockIdx.x * 256 + threadIdx.x;
    y[idx] = 0.5f * (a[idx] + b[idx]);
}

// ------------------------- driver -------------------------------------------
extern "C" void kernel_launch(void* const* d_in, const int* in_sizes, int n_in,
                              void* d_out, int out_size)
{
    const float* spec   = (const float*)d_in[0];
    const float* conv_w = (const float*)d_in[1];
    const float* conv_b = (const float*)d_in[2];
    const float* pe_row = (const float*)d_in[3];
    const float* pe_col = (const float*)d_in[4];
    const float* lnA_g  = (const float*)d_in[5];
    const float* lnA_b  = (const float*)d_in[6];
    const float* wqk    = (const float*)d_in[7];
    const float* wv     = (const float*)d_in[8];
    const float* wo     = (const float*)d_in[9];
    const float* bo     = (const float*)d_in[10];
    const float* lnF_g  = (const float*)d_in[11];
    const float* lnF_b  = (const float*)d_in[12];
    const float* w1     = (const float*)d_in[13];
    const float* b1     = (const float*)d_in[14];
    const float* w2     = (const float*)d_in[15];
    const float* b2     = (const float*)d_in[16];
    const float* lin_w  = (const float*)d_in[17];
    const float* lin_b  = (const float*)d_in[18];
    const float* rot    = (const float*)d_in[19];
    float* out = (float*)d_out;

    float *x1, *x2, *tmp, *qk, *v, *at, *ff, *im, *wT, *o, *lg;
    int *bk, *st;
    cudaGetSymbolAddress((void**)&x1, g_x1);
    cudaGetSymbolAddress((void**)&x2, g_x2);
    cudaGetSymbolAddress((void**)&tmp, g_tmp);
    cudaGetSymbolAddress((void**)&qk, g_qk);
    cudaGetSymbolAddress((void**)&v,  g_v);
    cudaGetSymbolAddress((void**)&at, g_at);
    cudaGetSymbolAddress((void**)&ff, g_ffb);
    cudaGetSymbolAddress((void**)&im, g_im);
    cudaGetSymbolAddress((void**)&wT, g_wT);
    cudaGetSymbolAddress((void**)&o,  g_o);
    cudaGetSymbolAddress((void**)&lg, g_lg);
    cudaGetSymbolAddress((void**)&bk, g_bk);
    cudaGetSymbolAddress((void**)&st, g_st);

    size_t asmem = (size_t)(128 * RS + 128 * 64 + 64 * DS + 128 + 64 + 128 + 64) * 4;
    cudaFuncSetAttribute(attn_kernel, cudaFuncAttributeMaxDynamicSharedMemorySize, (int)asmem);

    // frontend: conv1d (im2col GEMM) + relu + axial positional embedding
    wt_kernel<<<(KC * DIM) / 256, 256>>>(conv_w, wT);
    im2col_kernel<<<(BT * KC) / 256, 256>>>(spec, im);
    sgemm<<<dim3(DIM / 64, BT / 64), 128>>>(im, wT, conv_b, nullptr, x1,
                                            BT, DIM, KC, 1, 0, nullptr, nullptr, 0);
    pe_kernel<<<(BT * DIM) / 256, 256>>>(x1, x2, pe_row, pe_col);

    for (int i = 0; i < 8; i++) {
        ln_kernel<<<BT, 256>>>(x2, lnA_g + i * DIM, lnA_b + i * DIM, tmp);
        // fused QK + V projection (heads layout), 1024 CTAs
        sgemm<<<dim3(16, 64), 128>>>(tmp, wqk + (size_t)i * DIM * DIM, nullptr, nullptr,
                                     qk, BT, DIM, DIM, 0, 1,
                                     wv + (size_t)i * DIM * DIM, v, DIM);
        hash_kernel<<<BH * (T_ / TCH), 128>>>(qk, rot + (size_t)i * 64 * 128, bk);
        sort_kernel<<<BH, 256>>>(bk, st);
        attn_kernel<<<BH * NCH, 128, asmem>>>(qk, v, st, o, lg);
        combine_kernel<<<BH * T_, 64>>>(o, lg, at);
        sgemm<<<dim3(8, 64), 128>>>(at, wo + (size_t)i * DIM * DIM, bo + i * DIM,
                                    x1, x1, BT, DIM, DIM, 0, 0, nullptr, nullptr, 0);
        ln_kernel<<<BT, 256>>>(x1, lnF_g + i * DIM, lnF_b + i * DIM, tmp);
        sgemm<<<dim3(FF / 64, 64), 128>>>(tmp, w1 + (size_t)i * DIM * FF, b1 + i * FF,
                                          nullptr, ff, BT, FF, DIM, 2, 0, nullptr, nullptr, 0);
        sgemm<<<dim3(8, 64), 128>>>(ff, w2 + (size_t)i * DIM * FF, b2 + i * DIM,
                                    x2, x2, BT, DIM, FF, 0, 0, nullptr, nullptr, 0);
    }

    avg_kernel<<<(BT * DIM) / 256, 256>>>(x1, x2, tmp);
    sgemm<<<dim3(2, 64), 128>>>(tmp, lin_w, lin_b, nullptr, out, BT, 88, DIM, 0, 0,
                                nullptr, nullptr, 0);
}

// round 7
// speedup vs baseline: 1.0170x; 1.0170x over previous
#include <cuda_runtime.h>
#include <math.h>

#define B_   2
#define T_   2048
#define BT   4096
#define DIM  512
#define H_   8
#define DH   64
#define NH   8
#define NB   32
#define NCH  256      // NH*NB chunks per bh
#define BH   16
#define NHT  16384    // NH*T
#define KC   704      // padded conv K (229*3=687 -> 704)
#define FF   2048

// scalar Kahan merge: sum s, compensation c, incoming value p
#define KAHAN(s, c, p) { float y_ = (p) - (c); float t_ = (s) + y_; (c) = (t_ - (s)) - y_; (s) = t_; }

// ------------------------- scratch (static device) -------------------------
__device__ float g_x1[BT*DIM];
__device__ float g_x2[BT*DIM];
__device__ float g_tmp[BT*DIM];
__device__ float g_qk[BT*DIM];
__device__ float g_v [BT*DIM];
__device__ float g_at[BT*DIM];
__device__ float g_ffb[BT*FF];
__device__ float g_im[BT*KC];
__device__ float g_wT[KC*DIM];
__device__ int   g_bk[BH*NHT];
__device__ int   g_st[BH*NHT];
__device__ float g_o [BH*NHT*DH];
__device__ float g_lg[BH*NHT];

// ------------------------- SGEMM: C = act(A@B + bias) + resid --------------
// Block-16 compensated accumulation (16 plain FMAs per smem chunk, then one
// Kahan merge), double-buffered smem. BM=64, BN=64, BK=16, 256 threads,
// 4x4 microtile. act: 0 none, 1 relu, 2 gelu(exact).
// heads: output permuted to (b,H,t,DH).
// Nsplit>0: blocks with n0>=Nsplit use Bm2/C2 (fused dual-weight GEMM).
__global__ __launch_bounds__(256) void sgemm(
    const float* __restrict__ A, const float* __restrict__ Bm,
    const float* __restrict__ bias, const float* __restrict__ resid,
    float* __restrict__ C, int M, int N, int K, int act, int heads,
    const float* __restrict__ Bm2, float* __restrict__ C2, int Nsplit)
{
    __shared__ float As[2][16][68];
    __shared__ float Bs[2][16][68];
    const int tid = threadIdx.x;
    const int tx = tid & 15, ty = tid >> 4;
    const int m0 = blockIdx.y * 64;
    int n0 = blockIdx.x * 64;
    if (Nsplit && n0 >= Nsplit) { Bm = Bm2; C = C2; n0 -= Nsplit; }

    float acc[4][4], cmp[4][4];
    #pragma unroll
    for (int i = 0; i < 4; i++)
        #pragma unroll
        for (int j = 0; j < 4; j++) { acc[i][j] = 0.f; cmp[i][j] = 0.f; }

    const int arow = tid >> 2, ac4 = (tid & 3) * 4;   // A: 64 rows x 16 k
    const int brow = tid >> 4, bc4 = (tid & 15) * 4;  // B: 16 k x 64 cols
    const int bcol = n0 + bc4;
    const int nk = K >> 4;

    // prologue: chunk 0 -> buf 0
    {
        float4 a = *(const float4*)(A + (size_t)(m0 + arow) * K + ac4);
        As[0][ac4 + 0][arow] = a.x; As[0][ac4 + 1][arow] = a.y;
        As[0][ac4 + 2][arow] = a.z; As[0][ac4 + 3][arow] = a.w;
        float4 bv = make_float4(0.f, 0.f, 0.f, 0.f);
        if (bcol < N) bv = *(const float4*)(Bm + (size_t)brow * N + bcol);
        *(float4*)(&Bs[0][brow][bc4]) = bv;
    }
    __syncthreads();

    for (int c = 0; c < nk; c++) {
        const int buf = c & 1;
        float4 pa, pbv;
        const bool more = (c + 1 < nk);
        if (more) {
            int k0 = (c + 1) << 4;
            pa = *(const float4*)(A + (size_t)(m0 + arow) * K + k0 + ac4);
            pbv = make_float4(0.f, 0.f, 0.f, 0.f);
            if (bcol < N) pbv = *(const float4*)(Bm + (size_t)(k0 + brow) * N + bcol);
        }
        float pb[4][4];
        #pragma unroll
        for (int kk = 0; kk < 16; kk++) {
            float4 a4 = *(const float4*)(&As[buf][kk][ty * 4]);
            float4 b4 = *(const float4*)(&Bs[buf][kk][tx * 4]);
            float av[4] = {a4.x, a4.y, a4.z, a4.w};
            float bw[4] = {b4.x, b4.y, b4.z, b4.w};
            if (kk == 0) {
                #pragma unroll
                for (int i = 0; i < 4; i++)
                    #pragma unroll
                    for (int j = 0; j < 4; j++) pb[i][j] = av[i] * bw[j];
            } else {
                #pragma unroll
                for (int i = 0; i < 4; i++)
                    #pragma unroll
                    for (int j = 0; j < 4; j++) pb[i][j] = fmaf(av[i], bw[j], pb[i][j]);
            }
        }
        #pragma unroll
        for (int i = 0; i < 4; i++)
            #pragma unroll
            for (int j = 0; j < 4; j++) KAHAN(acc[i][j], cmp[i][j], pb[i][j]);
        if (more) {
            const int nb = buf ^ 1;
            As[nb][ac4 + 0][arow] = pa.x; As[nb][ac4 + 1][arow] = pa.y;
            As[nb][ac4 + 2][arow] = pa.z; As[nb][ac4 + 3][arow] = pa.w;
            *(float4*)(&Bs[nb][brow][bc4]) = pbv;
            __syncthreads();
        }
    }

    #pragma unroll
    for (int i = 0; i < 4; i++) {
        int row = m0 + ty * 4 + i;
        #pragma unroll
        for (int j = 0; j < 4; j++) {
            int col = n0 + tx * 4 + j;
            if (col >= N) continue;
            float v = acc[i][j] + cmp[i][j];
            if (bias) v += bias[col];
            if (act == 1) v = fmaxf(v, 0.f);
            else if (act == 2) v = 0.5f * v * (1.f + erff(v * 0.70710678118654752f));
            if (resid) v += resid[(size_t)row * N + col];
            if (heads) {
                int b = row >> 11, t = row & 2047;
                int h = col >> 6, d = col & 63;
                C[((((size_t)b * H_ + h) * T_ + t) << 6) + d] = v;
            } else {
                C[(size_t)row * N + col] = v;
            }
        }
    }
}

// ------------------------- LayerNorm (row of 512) ---------------------------
__global__ __launch_bounds__(256) void ln_kernel(
    const float* __restrict__ x, const float* __restrict__ g,
    const float* __restrict__ bb, float* __restrict__ y)
{
    __shared__ float sh[8];
    int row = blockIdx.x, tid = threadIdx.x;
    const float* xr = x + (size_t)row * DIM;
    float v0 = xr[tid], v1 = xr[tid + 256];
    float s = v0 + v1;
    #pragma unroll
    for (int o = 16; o; o >>= 1) s += __shfl_down_sync(0xffffffffu, s, o);
    if ((tid & 31) == 0) sh[tid >> 5] = s;
    __syncthreads();
    if (tid < 32) {
        float t = (tid < 8) ? sh[tid] : 0.f;
        #pragma unroll
        for (int o = 4; o; o >>= 1) t += __shfl_down_sync(0xffffffffu, t, o);
        if (tid == 0) sh[0] = t;
    }
    __syncthreads();
    float mean = sh[0] * (1.f / DIM);
    __syncthreads();
    float d0 = v0 - mean, d1 = v1 - mean;
    float s2 = d0 * d0 + d1 * d1;
    #pragma unroll
    for (int o = 16; o; o >>= 1) s2 += __shfl_down_sync(0xffffffffu, s2, o);
    if ((tid & 31) == 0) sh[tid >> 5] = s2;
    __syncthreads();
    if (tid < 32) {
        float t = (tid < 8) ? sh[tid] : 0.f;
        #pragma unroll
        for (int o = 4; o; o >>= 1) t += __shfl_down_sync(0xffffffffu, t, o);
        if (tid == 0) sh[0] = t;
    }
    __syncthreads();
    float inv = 1.f / sqrtf(sh[0] * (1.f / DIM) + 1e-5f);
    float* yr = y + (size_t)row * DIM;
    yr[tid]       = d0 * inv * g[tid]       + bb[tid];
    yr[tid + 256] = d1 * inv * g[tid + 256] + bb[tid + 256];
}

// ------------------------- LSH hashing (full Kahan: decides argmax) ---------
#define TCH 16
__global__ __launch_bounds__(128) void hash_kernel(
    const float* __restrict__ qk, const float* __restrict__ rot, int* __restrict__ bkt)
{
    __shared__ float q[4][DH];
    int blk = blockIdx.x;
    int bh = blk / (T_ / TCH);
    int t0 = (blk % (T_ / TCH)) * TCH;
    int tid = threadIdx.x;
    int h = tid >> 4, j = tid & 15;
    float rv[64];
    #pragma unroll
    for (int f = 0; f < 64; f++) rv[f] = rot[f * 128 + h * 16 + j];

    for (int tg = 0; tg < TCH; tg += 4) {
        __syncthreads();
        for (int idx = tid; idx < 4 * DH; idx += 128) {
            int r = idx >> 6, d = idx & 63;
            q[r][d] = qk[((size_t)bh * T_ + t0 + tg + r) * DH + d];
        }
        __syncthreads();
        float a0 = 0.f, a1 = 0.f, a2 = 0.f, a3 = 0.f;
        float c0 = 0.f, c1 = 0.f, c2 = 0.f, c3 = 0.f;
        #pragma unroll
        for (int f = 0; f < 64; f++) {
            float r = rv[f];
            float p0 = q[0][f] * r; KAHAN(a0, c0, p0);
            float p1 = q[1][f] * r; KAHAN(a1, c1, p1);
            float p2 = q[2][f] * r; KAHAN(a2, c2, p2);
            float p3 = q[3][f] * r; KAHAN(a3, c3, p3);
        }
        float vals[4] = {a0 + c0, a1 + c1, a2 + c2, a3 + c3};
        #pragma unroll
        for (int r = 0; r < 4; r++) {
            float v = vals[r]; int idx = j;
            float nv = -v;
            if (nv > v) { v = nv; idx = j + 16; }   // ties keep +r (smaller index)
            #pragma unroll
            for (int o = 8; o; o >>= 1) {
                float ov = __shfl_down_sync(0xffffffffu, v, o, 16);
                int   oi = __shfl_down_sync(0xffffffffu, idx, o, 16);
                if (ov > v || (ov == v && oi < idx)) { v = ov; idx = oi; }
            }
            if (j == 0) bkt[(size_t)bh * NHT + h * T_ + t0 + tg + r] = idx + h * NB;
        }
    }
}

// ------------------------- stable counting sort by (bucket, pos) ------------
__global__ __launch_bounds__(256) void sort_kernel(
    const int* __restrict__ bkt, int* __restrict__ st)
{
    __shared__ int hist[256];
    __shared__ int off[256];
    int bh = blockIdx.x, tid = threadIdx.x;
    const int* bb = bkt + (size_t)bh * NHT;
    hist[tid] = 0;
    __syncthreads();
    for (int i = tid; i < NHT; i += 256) atomicAdd(&hist[bb[i]], 1);
    __syncthreads();
    if (tid == 0) {
        int s = 0;
        for (int i = 0; i < 256; i++) { off[i] = s; s += hist[i]; }
    }
    __syncthreads();
    // bucket beta lives entirely inside hash round h = beta/NB; tickers there
    // are in increasing pos order -> sequential scan is stable sort.
    int beta = tid, h = tid >> 5;
    int o = off[beta];
    int* out2 = st + (size_t)bh * NHT;
    int base = h * T_;
    for (int k = 0; k < T_; k++)
        if (bb[base + k] == beta) out2[o++] = base + k;
}

// ------------------------- chunked LSH attention ----------------------------
#define RS 68
#define DS 129
__global__ __launch_bounds__(128) void attn_kernel(
    const float* __restrict__ qk, const float* __restrict__ vg,
    const int* __restrict__ st, float* __restrict__ og, float* __restrict__ lgg)
{
    extern __shared__ float sm[];
    float* r     = sm;                  // 128 x RS   raw qk rows (q + keys)
    float* vv    = r + 128 * RS;        // 128 x 64   v rows
    float* dots  = vv + 128 * 64;       // 64 x DS
    float* inorm = dots + 64 * DS;      // 128
    float* logit = inorm + 128;         // 64
    int*   kpos  = (int*)(logit + 64);  // 128
    int*   qh    = kpos + 128;          // 64

    int tid = threadIdx.x;
    int bh = blockIdx.x >> 8, c = blockIdx.x & 255;
    int cp = (c + NCH - 1) & 255;

    {
        int lc = (tid < 64) ? c : cp;
        int tk = st[(size_t)bh * NHT + lc * 64 + (tid & 63)];
        kpos[tid] = tk & (T_ - 1);
        if (tid < 64) qh[tid] = tk >> 11;
    }
    __syncthreads();

    const float* qb = qk + ((size_t)bh << 17);
    const float* vb = vg + ((size_t)bh << 17);
    for (int it = 0; it < 64; it++) {
        int idx = it * 128 + tid;
        int jj = idx >> 6, d = idx & 63;
        int pos = kpos[jj];
        r[jj * RS + d]    = qb[(pos << 6) + d];
        vv[(jj << 6) + d] = vb[(pos << 6) + d];
    }
    __syncthreads();
    {
        float s = 0.f, cs = 0.f;
        #pragma unroll 8
        for (int d = 0; d < 64; d++) {
            float x = r[tid * RS + d];
            float p = x * x; KAHAN(s, cs, p);
        }
        inorm[tid] = 1.f / fmaxf(sqrtf(s + cs), 1e-12f);
    }
    __syncthreads();

    int tx = tid & 15, ty = tid >> 4;
    float acc[8][8], cmp[8][8];
    #pragma unroll
    for (int i = 0; i < 8; i++)
        #pragma unroll
        for (int m = 0; m < 8; m++) { acc[i][m] = 0.f; cmp[i][m] = 0.f; }

    for (int db = 0; db < 16; db++) {
        float kvb[4][8];
        #pragma unroll
        for (int dd = 0; dd < 4; dd++)
            #pragma unroll
            for (int m = 0; m < 8; m++)
                kvb[dd][m] = r[(tx + 16 * m) * RS + db * 4 + dd];
        #pragma unroll
        for (int i = 0; i < 8; i++) {
            float qv[4];
            #pragma unroll
            for (int dd = 0; dd < 4; dd++) qv[dd] = r[(ty * 8 + i) * RS + db * 4 + dd];
            float pb[8];
            #pragma unroll
            for (int m = 0; m < 8; m++) {
                float p = qv[0] * kvb[0][m];
                p = fmaf(qv[1], kvb[1][m], p);
                p = fmaf(qv[2], kvb[2][m], p);
                p = fmaf(qv[3], kvb[3][m], p);
                pb[m] = p;
            }
            #pragma unroll
            for (int m = 0; m < 8; m++) KAHAN(acc[i][m], cmp[i][m], pb[m]);
        }
    }
    #pragma unroll
    for (int i = 0; i < 8; i++) {
        int row = ty * 8 + i; int rp = kpos[row];
        #pragma unroll
        for (int m = 0; m < 8; m++) {
            int col = tx + 16 * m;
            float dv = (acc[i][m] + cmp[i][m]) * inorm[col] * 0.125f;
            if (rp == kpos[col]) dv = -5e4f;
            dots[row * DS + col] = dv;
        }
    }
    __syncthreads();

    if (tid < 64) {
        float mx = -1e30f;
        #pragma unroll 8
        for (int j2 = 0; j2 < 128; j2++) mx = fmaxf(mx, dots[tid * DS + j2]);
        float s = 0.f;
        #pragma unroll 8
        for (int j2 = 0; j2 < 128; j2++) s += expf(dots[tid * DS + j2] - mx);
        float lg = mx + logf(s);
        logit[tid] = lg;
        lgg[((size_t)bh * NH + qh[tid]) * T_ + kpos[tid]] = lg;
    }
    __syncthreads();
    for (int it = 0; it < 64; it++) {
        int idx = it * 128 + tid; int i = idx >> 7, j2 = idx & 127;
        dots[i * DS + j2] = expf(dots[i * DS + j2] - logit[i]);
    }
    __syncthreads();

    float a2[8][4], c2[8][4];
    #pragma unroll
    for (int i = 0; i < 8; i++)
        #pragma unroll
        for (int m = 0; m < 4; m++) { a2[i][m] = 0.f; c2[i][m] = 0.f; }
    for (int jb = 0; jb < 32; jb++) {
        float vwb[4][4];
        #pragma unroll
        for (int dd = 0; dd < 4; dd++)
            #pragma unroll
            for (int m = 0; m < 4; m++)
                vwb[dd][m] = vv[(((jb * 4 + dd)) << 6) + tx + 16 * m];
        #pragma unroll
        for (int i = 0; i < 8; i++) {
            float pv[4];
            #pragma unroll
            for (int dd = 0; dd < 4; dd++) pv[dd] = dots[(ty * 8 + i) * DS + jb * 4 + dd];
            float pb[4];
            #pragma unroll
            for (int m = 0; m < 4; m++) {
                float p = pv[0] * vwb[0][m];
                p = fmaf(pv[1], vwb[1][m], p);
                p = fmaf(pv[2], vwb[2][m], p);
                p = fmaf(pv[3], vwb[3][m], p);
                pb[m] = p;
            }
            #pragma unroll
            for (int m = 0; m < 4; m++) KAHAN(a2[i][m], c2[i][m], pb[m]);
        }
    }
    #pragma unroll
    for (int i = 0; i < 8; i++) {
        int row = ty * 8 + i;
        size_t base = (((size_t)bh * NH + qh[row]) * T_ + kpos[row]) << 6;
        #pragma unroll
        for (int m = 0; m < 4; m++) og[base + tx + 16 * m] = a2[i][m] + c2[i][m];
    }
}

// ------------------------- combine hash rounds ------------------------------
__global__ __launch_bounds__(64) void combine_kernel(
    const float* __restrict__ og, const float* __restrict__ lgg, float* __restrict__ at)
{
    __shared__ float w[8];
    int bh = blockIdx.x >> 11, pos = blockIdx.x & 2047;
    int tid = threadIdx.x;
    if (tid == 0) {
        float v[8]; float mx = -1e30f;
        #pragma unroll
        for (int h = 0; h < 8; h++) {
            v[h] = lgg[((size_t)bh * NH + h) * T_ + pos];
            mx = fmaxf(mx, v[h]);
        }
        float s = 0.f;
        #pragma unroll
        for (int h = 0; h < 8; h++) { v[h] = expf(v[h] - mx); s += v[h]; }
        float is = 1.f / s;
        #pragma unroll
        for (int h = 0; h < 8; h++) w[h] = v[h] * is;
    }
    __syncthreads();
    float acc = 0.f, cc = 0.f;
    #pragma unroll
    for (int h = 0; h < 8; h++) {
        float p = w[h] * og[(((size_t)bh * NH + h) * T_ + pos) * 64 + tid];
        KAHAN(acc, cc, p);
    }
    int b = bh >> 3, hd = bh & 7;
    at[((size_t)(b * T_ + pos)) * DIM + hd * 64 + tid] = acc + cc;
}

// ------------------------- frontend helpers ---------------------------------
__global__ void wt_kernel(const float* __restrict__ w, float* __restrict__ wT)
{
    int idx = blockIdx.x * 256 + threadIdx.x;     // KC*DIM
    int c = idx / DIM, o2 = idx - c * DIM;
    wT[idx] = (c < 687) ? w[(size_t)o2 * 687 + c] : 0.f;
}

__global__ void im2col_kernel(const float* __restrict__ spec, float* __restrict__ im)
{
    int idx = blockIdx.x * 256 + threadIdx.x;     // BT*KC
    int row = idx / KC, c = idx - row * KC;
    int b = row >> 11, t = row & 2047;
    float val = 0.f;
    if (c < 687) {
        int i = c / 3, k = c - i * 3;
        int tt = t + k - 1;
        if (tt >= 0 && tt < T_) val = spec[((size_t)b * T_ + tt) * 229 + i];
    }
    im[idx] = val;
}

__global__ void pe_kernel(float* __restrict__ x1, float* __restrict__ x2,
                          const float* __restrict__ per, const float* __restrict__ pec)
{
    int idx = blockIdx.x * 256 + threadIdx.x;     // BT*DIM
    int c = idx & 511;
    int t = (idx >> 9) & 2047;
    float p = (c < 256) ? per[(t >> 6) * 256 + c] : pec[(t & 63) * 256 + (c - 256)];
    float v = x1[idx] + p;
    x1[idx] = v; x2[idx] = v;
}

__global__ void avg_kernel(const float* __restrict__ a, const float* __restrict__ b,
                           float* __restrict__ y)
{
    int idx = blockIdx.x * 256 + threadIdx.x;
    y[idx] = 0.5f * (a[idx] + b[idx]);
}

// ------------------------- driver -------------------------------------------
extern "C" void kernel_launch(void* const* d_in, const int* in_sizes, int n_in,
                              void* d_out, int out_size)
{
    const float* spec   = (const float*)d_in[0];
    const float* conv_w = (const float*)d_in[1];
    const float* conv_b = (const float*)d_in[2];
    const float* pe_row = (const float*)d_in[3];
    const float* pe_col = (const float*)d_in[4];
    const float* lnA_g  = (const float*)d_in[5];
    const float* lnA_b  = (const float*)d_in[6];
    const float* wqk    = (const float*)d_in[7];
    const float* wv     = (const float*)d_in[8];
    const float* wo     = (const float*)d_in[9];
    const float* bo     = (const float*)d_in[10];
    const float* lnF_g  = (const float*)d_in[11];
    const float* lnF_b  = (const float*)d_in[12];
    const float* w1     = (const float*)d_in[13];
    const float* b1     = (const float*)d_in[14];
    const float* w2     = (const float*)d_in[15];
    const float* b2     = (const float*)d_in[16];
    const float* lin_w  = (const float*)d_in[17];
    const float* lin_b  = (const float*)d_in[18];
    const float* rot    = (const float*)d_in[19];
    float* out = (float*)d_out;

    float *x1, *x2, *tmp, *qk, *v, *at, *ff, *im, *wT, *o, *lg;
    int *bk, *st;
    cudaGetSymbolAddress((void**)&x1, g_x1);
    cudaGetSymbolAddress((void**)&x2, g_x2);
    cudaGetSymbolAddress((void**)&tmp, g_tmp);
    cudaGetSymbolAddress((void**)&qk, g_qk);
    cudaGetSymbolAddress((void**)&v,  g_v);
    cudaGetSymbolAddress((void**)&at, g_at);
    cudaGetSymbolAddress((void**)&ff, g_ffb);
    cudaGetSymbolAddress((void**)&im, g_im);
    cudaGetSymbolAddress((void**)&wT, g_wT);
    cudaGetSymbolAddress((void**)&o,  g_o);
    cudaGetSymbolAddress((void**)&lg, g_lg);
    cudaGetSymbolAddress((void**)&bk, g_bk);
    cudaGetSymbolAddress((void**)&st, g_st);

    size_t asmem = (size_t)(128 * RS + 128 * 64 + 64 * DS + 128 + 64 + 128 + 64) * 4;
    cudaFuncSetAttribute(attn_kernel, cudaFuncAttributeMaxDynamicSharedMemorySize, (int)asmem);

    // frontend: conv1d (im2col GEMM) + relu + axial positional embedding
    wt_kernel<<<(KC * DIM) / 256, 256>>>(conv_w, wT);
    im2col_kernel<<<(BT * KC) / 256, 256>>>(spec, im);
    sgemm<<<dim3(DIM / 64, BT / 64), 256>>>(im, wT, conv_b, nullptr, x1,
                                            BT, DIM, KC, 1, 0, nullptr, nullptr, 0);
    pe_kernel<<<(BT * DIM) / 256, 256>>>(x1, x2, pe_row, pe_col);

    for (int i = 0; i < 8; i++) {
        ln_kernel<<<BT, 256>>>(x2, lnA_g + i * DIM, lnA_b + i * DIM, tmp);
        // fused QK + V projection (heads layout), 1024 CTAs
        sgemm<<<dim3(16, 64), 256>>>(tmp, wqk + (size_t)i * DIM * DIM, nullptr, nullptr,
                                     qk, BT, DIM, DIM, 0, 1,
                                     wv + (size_t)i * DIM * DIM, v, DIM);
        hash_kernel<<<BH * (T_ / TCH), 128>>>(qk, rot + (size_t)i * 64 * 128, bk);
        sort_kernel<<<BH, 256>>>(bk, st);
        attn_kernel<<<BH * NCH, 128, asmem>>>(qk, v, st, o, lg);
        combine_kernel<<<BH * T_, 64>>>(o, lg, at);
        sgemm<<<dim3(8, 64), 256>>>(at, wo + (size_t)i * DIM * DIM, bo + i * DIM,
                                    x1, x1, BT, DIM, DIM, 0, 0, nullptr, nullptr, 0);
        ln_kernel<<<BT, 256>>>(x1, lnF_g + i * DIM, lnF_b + i * DIM, tmp);
        sgemm<<<dim3(FF / 64, 64), 256>>>(tmp, w1 + (size_t)i * DIM * FF, b1 + i * FF,
                                          nullptr, ff, BT, FF, DIM, 2, 0, nullptr, nullptr, 0);
        sgemm<<<dim3(8, 64), 256>>>(ff, w2 + (size_t)i * DIM * FF, b2 + i * DIM,
                                    x2, x2, BT, DIM, FF, 0, 0, nullptr, nullptr, 0);
    }

    avg_kernel<<<(BT * DIM) / 256, 256>>>(x1, x2, tmp);
    sgemm<<<dim3(2, 64), 256>>>(tmp, lin_w, lin_b, nullptr, out, BT, 88, DIM, 0, 0,
                                nullptr, nullptr, 0);
}

// round 8
// speedup vs baseline: 1.5360x; 1.5104x over previous
#include <cuda_runtime.h>
#include <math.h>

#define B_   2
#define T_   2048
#define BT   4096
#define DIM  512
#define H_   8
#define DH   64
#define NH   8
#define NB   32
#define NCH  256      // NH*NB chunks per bh
#define BH   16
#define NHT  16384    // NH*T
#define KC   704      // padded conv K (229*3=687 -> 704)
#define FF   2048

// scalar Kahan merge: sum s, compensation c, incoming value p
#define KAHAN(s, c, p) { float y_ = (p) - (c); float t_ = (s) + y_; (c) = (t_ - (s)) - y_; (s) = t_; }

// ------------------------- scratch (static device) -------------------------
__device__ float g_x1[BT*DIM];
__device__ float g_x2[BT*DIM];
__device__ float g_tmp[BT*DIM];
__device__ float g_qk[BT*DIM];
__device__ float g_v [BT*DIM];
__device__ float g_at[BT*DIM];
__device__ float g_ffb[BT*FF];
__device__ float g_im[BT*KC];
__device__ float g_wT[KC*DIM];
__device__ int   g_bk[BH*NHT];
__device__ int   g_st[BH*NHT];
__device__ float g_o [BH*NHT*DH];
__device__ float g_lg[BH*NHT];

// ------------------------- SGEMM: C = act(A@B + bias) + resid --------------
// Block-16 compensated accumulation: 16 plain FMAs per BK chunk into a block
// partial, then ONE Kahan merge. BM=128, BN=64, BK=16, 256 threads, 8x4
// microtile, single-buffered (R4 skeleton - measured FMA-pipe-bound).
// act: 0 none, 1 relu, 2 gelu(exact). heads: output permuted to (b,H,t,DH).
// Nsplit>0: blocks with n0>=Nsplit use Bm2/C2 (fused dual-weight GEMM).
__global__ __launch_bounds__(256) void sgemm(
    const float* __restrict__ A, const float* __restrict__ Bm,
    const float* __restrict__ bias, const float* __restrict__ resid,
    float* __restrict__ C, int M, int N, int K, int act, int heads,
    const float* __restrict__ Bm2, float* __restrict__ C2, int Nsplit)
{
    __shared__ float As[16][132];
    __shared__ float Bs[16][64];
    const int tid = threadIdx.x;
    const int tx = tid & 15, ty = tid >> 4;
    const int m0 = blockIdx.y * 128;
    int n0 = blockIdx.x * 64;
    if (Nsplit && n0 >= Nsplit) { Bm = Bm2; C = C2; n0 -= Nsplit; }

    float acc[8][4], cmp[8][4];
    #pragma unroll
    for (int i = 0; i < 8; i++)
        #pragma unroll
        for (int j = 0; j < 4; j++) { acc[i][j] = 0.f; cmp[i][j] = 0.f; }

    const int arow0 = tid >> 2, ac4 = (tid & 3) * 4;
    const int brow = tid >> 4, bc4 = (tid & 15) * 4;
    const int bcol = n0 + bc4;

    for (int k0 = 0; k0 < K; k0 += 16) {
        #pragma unroll
        for (int s = 0; s < 2; s++) {
            int row = arow0 + s * 64;
            float4 a = *(const float4*)(A + (size_t)(m0 + row) * K + k0 + ac4);
            As[ac4 + 0][row] = a.x; As[ac4 + 1][row] = a.y;
            As[ac4 + 2][row] = a.z; As[ac4 + 3][row] = a.w;
        }
        float4 bv;
        if (bcol < N) bv = *(const float4*)(Bm + (size_t)(k0 + brow) * N + bcol);
        else          bv = make_float4(0.f, 0.f, 0.f, 0.f);
        *(float4*)(&Bs[brow][bc4]) = bv;
        __syncthreads();
        float pb[8][4];
        #pragma unroll
        for (int kk = 0; kk < 16; kk++) {
            float4 a0 = *(const float4*)(&As[kk][ty * 8]);
            float4 a1 = *(const float4*)(&As[kk][ty * 8 + 4]);
            float4 bb = *(const float4*)(&Bs[kk][tx * 4]);
            float av[8] = {a0.x, a0.y, a0.z, a0.w, a1.x, a1.y, a1.z, a1.w};
            float bw[4] = {bb.x, bb.y, bb.z, bb.w};
            if (kk == 0) {
                #pragma unroll
                for (int i = 0; i < 8; i++)
                    #pragma unroll
                    for (int j = 0; j < 4; j++) pb[i][j] = av[i] * bw[j];
            } else {
                #pragma unroll
                for (int i = 0; i < 8; i++)
                    #pragma unroll
                    for (int j = 0; j < 4; j++) pb[i][j] = fmaf(av[i], bw[j], pb[i][j]);
            }
        }
        #pragma unroll
        for (int i = 0; i < 8; i++)
            #pragma unroll
            for (int j = 0; j < 4; j++) KAHAN(acc[i][j], cmp[i][j], pb[i][j]);
        __syncthreads();
    }

    #pragma unroll
    for (int i = 0; i < 8; i++) {
        int row = m0 + ty * 8 + i;
        #pragma unroll
        for (int j = 0; j < 4; j++) {
            int col = n0 + tx * 4 + j;
            if (col >= N) continue;
            float v = acc[i][j] + cmp[i][j];
            if (bias) v += bias[col];
            if (act == 1) v = fmaxf(v, 0.f);
            else if (act == 2) v = 0.5f * v * (1.f + erff(v * 0.70710678118654752f));
            if (resid) v += resid[(size_t)row * N + col];
            if (heads) {
                int b = row >> 11, t = row & 2047;
                int h = col >> 6, d = col & 63;
                C[((((size_t)b * H_ + h) * T_ + t) << 6) + d] = v;
            } else {
                C[(size_t)row * N + col] = v;
            }
        }
    }
}

// ------------------------- LayerNorm (row of 512) ---------------------------
__global__ __launch_bounds__(256) void ln_kernel(
    const float* __restrict__ x, const float* __restrict__ g,
    const float* __restrict__ bb, float* __restrict__ y)
{
    __shared__ float sh[8];
    int row = blockIdx.x, tid = threadIdx.x;
    const float* xr = x + (size_t)row * DIM;
    float v0 = xr[tid], v1 = xr[tid + 256];
    float s = v0 + v1;
    #pragma unroll
    for (int o = 16; o; o >>= 1) s += __shfl_down_sync(0xffffffffu, s, o);
    if ((tid & 31) == 0) sh[tid >> 5] = s;
    __syncthreads();
    if (tid < 32) {
        float t = (tid < 8) ? sh[tid] : 0.f;
        #pragma unroll
        for (int o = 4; o; o >>= 1) t += __shfl_down_sync(0xffffffffu, t, o);
        if (tid == 0) sh[0] = t;
    }
    __syncthreads();
    float mean = sh[0] * (1.f / DIM);
    __syncthreads();
    float d0 = v0 - mean, d1 = v1 - mean;
    float s2 = d0 * d0 + d1 * d1;
    #pragma unroll
    for (int o = 16; o; o >>= 1) s2 += __shfl_down_sync(0xffffffffu, s2, o);
    if ((tid & 31) == 0) sh[tid >> 5] = s2;
    __syncthreads();
    if (tid < 32) {
        float t = (tid < 8) ? sh[tid] : 0.f;
        #pragma unroll
        for (int o = 4; o; o >>= 1) t += __shfl_down_sync(0xffffffffu, t, o);
        if (tid == 0) sh[0] = t;
    }
    __syncthreads();
    float inv = 1.f / sqrtf(sh[0] * (1.f / DIM) + 1e-5f);
    float* yr = y + (size_t)row * DIM;
    yr[tid]       = d0 * inv * g[tid]       + bb[tid];
    yr[tid + 256] = d1 * inv * g[tid + 256] + bb[tid + 256];
}

// ------------------------- LSH hashing (full Kahan: decides argmax) ---------
#define TCH 16
__global__ __launch_bounds__(128) void hash_kernel(
    const float* __restrict__ qk, const float* __restrict__ rot, int* __restrict__ bkt)
{
    __shared__ float q[4][DH];
    int blk = blockIdx.x;
    int bh = blk / (T_ / TCH);
    int t0 = (blk % (T_ / TCH)) * TCH;
    int tid = threadIdx.x;
    int h = tid >> 4, j = tid & 15;
    float rv[64];
    #pragma unroll
    for (int f = 0; f < 64; f++) rv[f] = rot[f * 128 + h * 16 + j];

    for (int tg = 0; tg < TCH; tg += 4) {
        __syncthreads();
        for (int idx = tid; idx < 4 * DH; idx += 128) {
            int r = idx >> 6, d = idx & 63;
            q[r][d] = qk[((size_t)bh * T_ + t0 + tg + r) * DH + d];
        }
        __syncthreads();
        float a0 = 0.f, a1 = 0.f, a2 = 0.f, a3 = 0.f;
        float c0 = 0.f, c1 = 0.f, c2 = 0.f, c3 = 0.f;
        #pragma unroll
        for (int f = 0; f < 64; f++) {
            float r = rv[f];
            float p0 = q[0][f] * r; KAHAN(a0, c0, p0);
            float p1 = q[1][f] * r; KAHAN(a1, c1, p1);
            float p2 = q[2][f] * r; KAHAN(a2, c2, p2);
            float p3 = q[3][f] * r; KAHAN(a3, c3, p3);
        }
        float vals[4] = {a0 + c0, a1 + c1, a2 + c2, a3 + c3};
        #pragma unroll
        for (int r = 0; r < 4; r++) {
            float v = vals[r]; int idx = j;
            float nv = -v;
            if (nv > v) { v = nv; idx = j + 16; }   // ties keep +r (smaller index)
            #pragma unroll
            for (int o = 8; o; o >>= 1) {
                float ov = __shfl_down_sync(0xffffffffu, v, o, 16);
                int   oi = __shfl_down_sync(0xffffffffu, idx, o, 16);
                if (ov > v || (ov == v && oi < idx)) { v = ov; idx = oi; }
            }
            if (j == 0) bkt[(size_t)bh * NHT + h * T_ + t0 + tg + r] = idx + h * NB;
        }
    }
}

// ------------------------- stable counting sort by (bucket, pos) ------------
__global__ __launch_bounds__(256) void sort_kernel(
    const int* __restrict__ bkt, int* __restrict__ st)
{
    __shared__ int hist[256];
    __shared__ int off[256];
    int bh = blockIdx.x, tid = threadIdx.x;
    const int* bb = bkt + (size_t)bh * NHT;
    hist[tid] = 0;
    __syncthreads();
    for (int i = tid; i < NHT; i += 256) atomicAdd(&hist[bb[i]], 1);
    __syncthreads();
    if (tid == 0) {
        int s = 0;
        for (int i = 0; i < 256; i++) { off[i] = s; s += hist[i]; }
    }
    __syncthreads();
    // bucket beta lives entirely inside hash round h = beta/NB; tickers there
    // are in increasing pos order -> sequential scan is stable sort.
    int beta = tid, h = tid >> 5;
    int o = off[beta];
    int* out2 = st + (size_t)bh * NHT;
    int base = h * T_;
    for (int k = 0; k < T_; k++)
        if (bb[base + k] == beta) out2[o++] = base + k;
}

// ------------------------- chunked LSH attention ----------------------------
#define RS 68
#define DS 129
__global__ __launch_bounds__(128) void attn_kernel(
    const float* __restrict__ qk, const float* __restrict__ vg,
    const int* __restrict__ st, float* __restrict__ og, float* __restrict__ lgg)
{
    extern __shared__ float sm[];
    float* r     = sm;                  // 128 x RS   raw qk rows (q + keys)
    float* vv    = r + 128 * RS;        // 128 x 64   v rows
    float* dots  = vv + 128 * 64;       // 64 x DS
    float* inorm = dots + 64 * DS;      // 128
    float* logit = inorm + 128;         // 64
    int*   kpos  = (int*)(logit + 64);  // 128
    int*   qh    = kpos + 128;          // 64

    int tid = threadIdx.x;
    int bh = blockIdx.x >> 8, c = blockIdx.x & 255;
    int cp = (c + NCH - 1) & 255;

    {
        int lc = (tid < 64) ? c : cp;
        int tk = st[(size_t)bh * NHT + lc * 64 + (tid & 63)];
        kpos[tid] = tk & (T_ - 1);
        if (tid < 64) qh[tid] = tk >> 11;
    }
    __syncthreads();

    const float* qb = qk + ((size_t)bh << 17);
    const float* vb = vg + ((size_t)bh << 17);
    for (int it = 0; it < 64; it++) {
        int idx = it * 128 + tid;
        int jj = idx >> 6, d = idx & 63;
        int pos = kpos[jj];
        r[jj * RS + d]    = qb[(pos << 6) + d];
        vv[(jj << 6) + d] = vb[(pos << 6) + d];
    }
    __syncthreads();
    {
        float s = 0.f, cs = 0.f;
        #pragma unroll 8
        for (int d = 0; d < 64; d++) {
            float x = r[tid * RS + d];
            float p = x * x; KAHAN(s, cs, p);
        }
        inorm[tid] = 1.f / fmaxf(sqrtf(s + cs), 1e-12f);
    }
    __syncthreads();

    int tx = tid & 15, ty = tid >> 4;
    float acc[8][8], cmp[8][8];
    #pragma unroll
    for (int i = 0; i < 8; i++)
        #pragma unroll
        for (int m = 0; m < 8; m++) { acc[i][m] = 0.f; cmp[i][m] = 0.f; }

    for (int db = 0; db < 16; db++) {
        float kvb[4][8];
        #pragma unroll
        for (int dd = 0; dd < 4; dd++)
            #pragma unroll
            for (int m = 0; m < 8; m++)
                kvb[dd][m] = r[(tx + 16 * m) * RS + db * 4 + dd];
        #pragma unroll
        for (int i = 0; i < 8; i++) {
            float qv[4];
            #pragma unroll
            for (int dd = 0; dd < 4; dd++) qv[dd] = r[(ty * 8 + i) * RS + db * 4 + dd];
            float pb[8];
            #pragma unroll
            for (int m = 0; m < 8; m++) {
                float p = qv[0] * kvb[0][m];
                p = fmaf(qv[1], kvb[1][m], p);
                p = fmaf(qv[2], kvb[2][m], p);
                p = fmaf(qv[3], kvb[3][m], p);
                pb[m] = p;
            }
            #pragma unroll
            for (int m = 0; m < 8; m++) KAHAN(acc[i][m], cmp[i][m], pb[m]);
        }
    }
    #pragma unroll
    for (int i = 0; i < 8; i++) {
        int row = ty * 8 + i; int rp = kpos[row];
        #pragma unroll
        for (int m = 0; m < 8; m++) {
            int col = tx + 16 * m;
            float dv = (acc[i][m] + cmp[i][m]) * inorm[col] * 0.125f;
            if (rp == kpos[col]) dv = -5e4f;
            dots[row * DS + col] = dv;
        }
    }
    __syncthreads();

    if (tid < 64) {
        float mx = -1e30f;
        #pragma unroll 8
        for (int j2 = 0; j2 < 128; j2++) mx = fmaxf(mx, dots[tid * DS + j2]);
        float s = 0.f;
        #pragma unroll 8
        for (int j2 = 0; j2 < 128; j2++) s += expf(dots[tid * DS + j2] - mx);
        float lg = mx + logf(s);
        logit[tid] = lg;
        lgg[((size_t)bh * NH + qh[tid]) * T_ + kpos[tid]] = lg;
    }
    __syncthreads();
    for (int it = 0; it < 64; it++) {
        int idx = it * 128 + tid; int i = idx >> 7, j2 = idx & 127;
        dots[i * DS + j2] = expf(dots[i * DS + j2] - logit[i]);
    }
    __syncthreads();

    float a2[8][4], c2[8][4];
    #pragma unroll
    for (int i = 0; i < 8; i++)
        #pragma unroll
        for (int m = 0; m < 4; m++) { a2[i][m] = 0.f; c2[i][m] = 0.f; }
    for (int jb = 0; jb < 32; jb++) {
        float vwb[4][4];
        #pragma unroll
        for (int dd = 0; dd < 4; dd++)
            #pragma unroll
            for (int m = 0; m < 4; m++)
                vwb[dd][m] = vv[(((jb * 4 + dd)) << 6) + tx + 16 * m];
        #pragma unroll
        for (int i = 0; i < 8; i++) {
            float pv[4];
            #pragma unroll
            for (int dd = 0; dd < 4; dd++) pv[dd] = dots[(ty * 8 + i) * DS + jb * 4 + dd];
            float pb[4];
            #pragma unroll
            for (int m = 0; m < 4; m++) {
                float p = pv[0] * vwb[0][m];
                p = fmaf(pv[1], vwb[1][m], p);
                p = fmaf(pv[2], vwb[2][m], p);
                p = fmaf(pv[3], vwb[3][m], p);
                pb[m] = p;
            }
            #pragma unroll
            for (int m = 0; m < 4; m++) KAHAN(a2[i][m], c2[i][m], pb[m]);
        }
    }
    #pragma unroll
    for (int i = 0; i < 8; i++) {
        int row = ty * 8 + i;
        size_t base = (((size_t)bh * NH + qh[row]) * T_ + kpos[row]) << 6;
        #pragma unroll
        for (int m = 0; m < 4; m++) og[base + tx + 16 * m] = a2[i][m] + c2[i][m];
    }
}

// ------------------------- combine hash rounds ------------------------------
__global__ __launch_bounds__(64) void combine_kernel(
    const float* __restrict__ og, const float* __restrict__ lgg, float* __restrict__ at)
{
    __shared__ float w[8];
    int bh = blockIdx.x >> 11, pos = blockIdx.x & 2047;
    int tid = threadIdx.x;
    if (tid == 0) {
        float v[8]; float mx = -1e30f;
        #pragma unroll
        for (int h = 0; h < 8; h++) {
            v[h] = lgg[((size_t)bh * NH + h) * T_ + pos];
            mx = fmaxf(mx, v[h]);
        }
        float s = 0.f;
        #pragma unroll
        for (int h = 0; h < 8; h++) { v[h] = expf(v[h] - mx); s += v[h]; }
        float is = 1.f / s;
        #pragma unroll
        for (int h = 0; h < 8; h++) w[h] = v[h] * is;
    }
    __syncthreads();
    float acc = 0.f, cc = 0.f;
    #pragma unroll
    for (int h = 0; h < 8; h++) {
        float p = w[h] * og[(((size_t)bh * NH + h) * T_ + pos) * 64 + tid];
        KAHAN(acc, cc, p);
    }
    int b = bh >> 3, hd = bh & 7;
    at[((size_t)(b * T_ + pos)) * DIM + hd * 64 + tid] = acc + cc;
}

// ------------------------- frontend helpers ---------------------------------
__global__ void wt_kernel(const float* __restrict__ w, float* __restrict__ wT)
{
    int idx = blockIdx.x * 256 + threadIdx.x;     // KC*DIM
    int c = idx / DIM, o2 = idx - c * DIM;
    wT[idx] = (c < 687) ? w[(size_t)o2 * 687 + c] : 0.f;
}

__global__ void im2col_kernel(const float* __restrict__ spec, float* __restrict__ im)
{
    int idx = blockIdx.x * 256 + threadIdx.x;     // BT*KC
    int row = idx / KC, c = idx - row * KC;
    int b = row >> 11, t = row & 2047;
    float val = 0.f;
    if (c < 687) {
        int i = c / 3, k = c - i * 3;
        int tt = t + k - 1;
        if (tt >= 0 && tt < T_) val = spec[((size_t)b * T_ + tt) * 229 + i];
    }
    im[idx] = val;
}

__global__ void pe_kernel(float* __restrict__ x1, float* __restrict__ x2,
                          const float* __restrict__ per, const float* __restrict__ pec)
{
    int idx = blockIdx.x * 256 + threadIdx.x;     // BT*DIM
    int c = idx & 511;
    int t = (idx >> 9) & 2047;
    float p = (c < 256) ? per[(t >> 6) * 256 + c] : pec[(t & 63) * 256 + (c - 256)];
    float v = x1[idx] + p;
    x1[idx] = v; x2[idx] = v;
}

__global__ void avg_kernel(const float* __restrict__ a, const float* __restrict__ b,
                           float* __restrict__ y)
{
    int idx = blockIdx.x * 256 + threadIdx.x;
    y[idx] = 0.5f * (a[idx] + b[idx]);
}

// ------------------------- driver -------------------------------------------
extern "C" void kernel_launch(void* const* d_in, const int* in_sizes, int n_in,
                              void* d_out, int out_size)
{
    const float* spec   = (const float*)d_in[0];
    const float* conv_w = (const float*)d_in[1];
    const float* conv_b = (const float*)d_in[2];
    const float* pe_row = (const float*)d_in[3];
    const float* pe_col = (const float*)d_in[4];
    const float* lnA_g  = (const float*)d_in[5];
    const float* lnA_b  = (const float*)d_in[6];
    const float* wqk    = (const float*)d_in[7];
    const float* wv     = (const float*)d_in[8];
    const float* wo     = (const float*)d_in[9];
    const float* bo     = (const float*)d_in[10];
    const float* lnF_g  = (const float*)d_in[11];
    const float* lnF_b  = (const float*)d_in[12];
    const float* w1     = (const float*)d_in[13];
    const float* b1     = (const float*)d_in[14];
    const float* w2     = (const float*)d_in[15];
    const float* b2     = (const float*)d_in[16];
    const float* lin_w  = (const float*)d_in[17];
    const float* lin_b  = (const float*)d_in[18];
    const float* rot    = (const float*)d_in[19];
    float* out = (float*)d_out;

    float *x1, *x2, *tmp, *qk, *v, *at, *ff, *im, *wT, *o, *lg;
    int *bk, *st;
    cudaGetSymbolAddress((void**)&x1, g_x1);
    cudaGetSymbolAddress((void**)&x2, g_x2);
    cudaGetSymbolAddress((void**)&tmp, g_tmp);
    cudaGetSymbolAddress((void**)&qk, g_qk);
    cudaGetSymbolAddress((void**)&v,  g_v);
    cudaGetSymbolAddress((void**)&at, g_at);
    cudaGetSymbolAddress((void**)&ff, g_ffb);
    cudaGetSymbolAddress((void**)&im, g_im);
    cudaGetSymbolAddress((void**)&wT, g_wT);
    cudaGetSymbolAddress((void**)&o,  g_o);
    cudaGetSymbolAddress((void**)&lg, g_lg);
    cudaGetSymbolAddress((void**)&bk, g_bk);
    cudaGetSymbolAddress((void**)&st, g_st);

    size_t asmem = (size_t)(128 * RS + 128 * 64 + 64 * DS + 128 + 64 + 128 + 64) * 4;
    cudaFuncSetAttribute(attn_kernel, cudaFuncAttributeMaxDynamicSharedMemorySize, (int)asmem);

    // frontend: conv1d (im2col GEMM) + relu + axial positional embedding
    wt_kernel<<<(KC * DIM) / 256, 256>>>(conv_w, wT);
    im2col_kernel<<<(BT * KC) / 256, 256>>>(spec, im);
    sgemm<<<dim3(DIM / 64, BT / 128), 256>>>(im, wT, conv_b, nullptr, x1,
                                             BT, DIM, KC, 1, 0, nullptr, nullptr, 0);
    pe_kernel<<<(BT * DIM) / 256, 256>>>(x1, x2, pe_row, pe_col);

    for (int i = 0; i < 8; i++) {
        ln_kernel<<<BT, 256>>>(x2, lnA_g + i * DIM, lnA_b + i * DIM, tmp);
        // fused QK + V projection (heads layout), 512 CTAs
        sgemm<<<dim3(16, 32), 256>>>(tmp, wqk + (size_t)i * DIM * DIM, nullptr, nullptr,
                                     qk, BT, DIM, DIM, 0, 1,
                                     wv + (size_t)i * DIM * DIM, v, DIM);
        hash_kernel<<<BH * (T_ / TCH), 128>>>(qk, rot + (size_t)i * 64 * 128, bk);
        sort_kernel<<<BH, 256>>>(bk, st);
        attn_kernel<<<BH * NCH, 128, asmem>>>(qk, v, st, o, lg);
        combine_kernel<<<BH * T_, 64>>>(o, lg, at);
        sgemm<<<dim3(8, 32), 256>>>(at, wo + (size_t)i * DIM * DIM, bo + i * DIM,
                                    x1, x1, BT, DIM, DIM, 0, 0, nullptr, nullptr, 0);
        ln_kernel<<<BT, 256>>>(x1, lnF_g + i * DIM, lnF_b + i * DIM, tmp);
        sgemm<<<dim3(FF / 64, 32), 256>>>(tmp, w1 + (size_t)i * DIM * FF, b1 + i * FF,
                                          nullptr, ff, BT, FF, DIM, 2, 0, nullptr, nullptr, 0);
        sgemm<<<dim3(8, 32), 256>>>(ff, w2 + (size_t)i * DIM * FF, b2 + i * DIM,
                                    x2, x2, BT, DIM, FF, 0, 0, nullptr, nullptr, 0);
    }

    avg_kernel<<<(BT * DIM) / 256, 256>>>(x1, x2, tmp);
    sgemm<<<dim3(2, 32), 256>>>(tmp, lin_w, lin_b, nullptr, out, BT, 88, DIM, 0, 0,
                                nullptr, nullptr, 0);
}

// round 10
// speedup vs baseline: 1.5768x; 1.0266x over previous
#include <cuda_runtime.h>
#include <cuda_bf16.h>
#include <math.h>
#include <stdint.h>

#define B_   2
#define T_   2048
#define BT   4096
#define DIM  512
#define H_   8
#define DH   64
#define NH   8
#define NB   32
#define NCH  256
#define BH   16
#define NHT  16384
#define KC   704
#define FF   2048

#define KAHAN(s, c, p) { float y_ = (p) - (c); float t_ = (s) + y_; (c) = (t_ - (s)) - y_; (s) = t_; }

// ------------------------- scratch (static device) -------------------------
__device__ float g_x1[BT*DIM];
__device__ float g_x2[BT*DIM];
__device__ float g_tmp[BT*DIM];
__device__ float g_qk[BT*DIM];
__device__ float g_v [BT*DIM];
__device__ float g_at[BT*DIM];
__device__ float g_ffb[BT*FF];
__device__ float g_im[BT*KC];
__device__ float g_wT[KC*DIM];
__device__ int   g_bk[BH*NHT];
__device__ int   g_st[BH*NHT];
__device__ float g_o [BH*NHT*DH];
__device__ float g_lg[BH*NHT];
// bf16 split buffers
__device__ __nv_bfloat16 g_a0[BT*FF];
__device__ __nv_bfloat16 g_a1[BT*FF];
__device__ __nv_bfloat16 g_a2[BT*FF];
__device__ __nv_bfloat16 g_bt0[2*1024*1024];
__device__ __nv_bfloat16 g_bt1[2*1024*1024];
__device__ __nv_bfloat16 g_bt2[2*1024*1024];

// ------------------------- warp-mma helpers ---------------------------------
__device__ __forceinline__ uint32_t smem_u32(const void* p) {
    uint32_t a;
    asm("{ .reg .u64 t; cvta.to.shared.u64 t, %1; cvt.u32.u64 %0, t; }" : "=r"(a) : "l"(p));
    return a;
}
__device__ __forceinline__ void ldsm_x4(uint32_t* r, uint32_t addr) {
    asm volatile("ldmatrix.sync.aligned.m8n8.x4.shared.b16 {%0,%1,%2,%3}, [%4];"
        : "=r"(r[0]), "=r"(r[1]), "=r"(r[2]), "=r"(r[3]) : "r"(addr));
}
__device__ __forceinline__ void ldsm_x2(uint32_t* r, uint32_t addr) {
    asm volatile("ldmatrix.sync.aligned.m8n8.x2.shared.b16 {%0,%1}, [%2];"
        : "=r"(r[0]), "=r"(r[1]) : "r"(addr));
}
__device__ __forceinline__ void mma_bf16(float* d, const uint32_t* a, const uint32_t* b) {
    asm volatile("mma.sync.aligned.m16n8k16.row.col.f32.bf16.bf16.f32 "
        "{%0,%1,%2,%3}, {%4,%5,%6,%7}, {%8,%9}, {%0,%1,%2,%3};"
        : "+f"(d[0]), "+f"(d[1]), "+f"(d[2]), "+f"(d[3])
        : "r"(a[0]), "r"(a[1]), "r"(a[2]), "r"(a[3]), "r"(b[0]), "r"(b[1]));
}

// ------------------------- fp32 -> bf16x3 conversions -----------------------
__global__ void cvt3a_kernel(const float* __restrict__ src, int n,
                             __nv_bfloat16* __restrict__ d0, __nv_bfloat16* __restrict__ d1,
                             __nv_bfloat16* __restrict__ d2)
{
    int i = blockIdx.x * 256 + threadIdx.x;
    if (i >= n) return;
    float v = src[i];
    __nv_bfloat16 b0 = __float2bfloat16(v);
    float r = v - __bfloat162float(b0);
    __nv_bfloat16 b1 = __float2bfloat16(r);
    float r2 = r - __bfloat162float(b1);
    __nv_bfloat16 b2 = __float2bfloat16(r2);
    d0[i] = b0; d1[i] = b1; d2[i] = b2;
}

// W [K, N] fp32 -> Bt splits [rowoff+N, K] bf16 (transposed)
__global__ void cvt3b_kernel(const float* __restrict__ W, int Kd, int Nd, int rowoff,
                             __nv_bfloat16* __restrict__ d0, __nv_bfloat16* __restrict__ d1,
                             __nv_bfloat16* __restrict__ d2)
{
    int i = blockIdx.x * 256 + threadIdx.x;
    if (i >= Kd * Nd) return;
    int nrow = i / Kd, k = i - nrow * Kd;
    float v = W[(size_t)k * Nd + nrow];
    __nv_bfloat16 b0 = __float2bfloat16(v);
    float r = v - __bfloat162float(b0);
    __nv_bfloat16 b1 = __float2bfloat16(r);
    float r2 = r - __bfloat162float(b1);
    __nv_bfloat16 b2 = __float2bfloat16(r2);
    size_t o = (size_t)(rowoff + nrow) * Kd + k;
    d0[o] = b0; d1[o] = b1; d2[o] = b2;
}

// ------------------------- tensor-core bf16x3 GEMM (mma.sync) ---------------
// BM=128, BN=64, BK=16, 256 threads (8 warps, each 32x32).
// 6 significant cross-products of the 3-way bf16 splits, fp32 mma accum,
// Kahan-merged into a master accumulator every 2 K-chunks (K=32).
#define ASTRIDE 24
__global__ __launch_bounds__(256) void tgemm(
    const __nv_bfloat16* __restrict__ a0, const __nv_bfloat16* __restrict__ a1,
    const __nv_bfloat16* __restrict__ a2,
    const __nv_bfloat16* __restrict__ bt0, const __nv_bfloat16* __restrict__ bt1,
    const __nv_bfloat16* __restrict__ bt2,
    const float* __restrict__ bias, const float* __restrict__ resid,
    float* __restrict__ C, float* __restrict__ C2,
    int K, int Nout, int act, int heads, int Nsplit)
{
    __shared__ __align__(16) __nv_bfloat16 Asm[3 * 128 * ASTRIDE];
    __shared__ __align__(16) __nv_bfloat16 Bsm[3 * 64 * ASTRIDE];

    const int tid = threadIdx.x;
    const int L = tid & 31, w = tid >> 5;
    const int mrow0 = (w & 3) * 32, ncol0 = (w >> 2) * 32;
    const int m0 = blockIdx.y * 128;
    const int n0 = blockIdx.x * 64;

    const uint32_t Abase = smem_u32(Asm);
    const uint32_t Bbase = smem_u32(Bsm);
    // ldmatrix per-lane offsets
    const int arow = (L & 7) + ((L >> 3) & 1) * 8;   // tile row for A x4
    const int acol = (L >> 4) * 8;                   // tile col for A x4
    const int brow = L & 7, bcol = ((L >> 3) & 1) * 8;

    float acc[32], macc[32], mcmp[32];
    #pragma unroll
    for (int i = 0; i < 32; i++) { acc[i] = 0.f; macc[i] = 0.f; mcmp[i] = 0.f; }

    const int nch = K >> 4;
    for (int c = 0; c < nch; c++) {
        const int k0 = c << 4;
        // stage A (3 splits, 128x16) and B (3 splits, 64x16)
        #pragma unroll
        for (int it = 0; it < 3; it++) {
            int idx = tid + it * 256;            // 0..767
            int sp = idx >> 8, rem = idx & 255;
            int row = rem >> 1, seg = rem & 1;
            const __nv_bfloat16* ap = (sp == 0) ? a0 : ((sp == 1) ? a1 : a2);
            uint4 v = *(const uint4*)(ap + (size_t)(m0 + row) * K + k0 + seg * 8);
            *(uint4*)(Asm + sp * (128 * ASTRIDE) + row * ASTRIDE + seg * 8) = v;
        }
        {
            int idx = tid;                        // 0..255 of 384
            int sp = idx >> 7, rem = idx & 127;
            int row = rem >> 1, seg = rem & 1;
            const __nv_bfloat16* bp = (sp == 0) ? bt0 : ((sp == 1) ? bt1 : bt2);
            uint4 v = *(const uint4*)(bp + (size_t)(n0 + row) * K + k0 + seg * 8);
            *(uint4*)(Bsm + sp * (64 * ASTRIDE) + row * ASTRIDE + seg * 8) = v;
        }
        if (tid < 128) {
            int idx = tid + 256;
            int sp = idx >> 7, rem = idx & 127;
            int row = rem >> 1, seg = rem & 1;
            const __nv_bfloat16* bp = (sp == 0) ? bt0 : ((sp == 1) ? bt1 : bt2);
            uint4 v = *(const uint4*)(bp + (size_t)(n0 + row) * K + k0 + seg * 8);
            *(uint4*)(Bsm + sp * (64 * ASTRIDE) + row * ASTRIDE + seg * 8) = v;
        }
        __syncthreads();

        // A fragments for all 3 splits (2 m-tiles each)
        uint32_t afr[3][2][4];
        #pragma unroll
        for (int sp = 0; sp < 3; sp++)
            #pragma unroll
            for (int mt = 0; mt < 2; mt++)
                ldsm_x4(afr[sp][mt],
                        Abase + ((sp * (128 * ASTRIDE) + (mrow0 + mt * 16 + arow) * ASTRIDE + acol) << 1));

        // cross-products grouped by B split
        #pragma unroll
        for (int bj = 0; bj < 3; bj++) {
            uint32_t bfr[4][2];
            #pragma unroll
            for (int nt = 0; nt < 4; nt++)
                ldsm_x2(bfr[nt],
                        Bbase + ((bj * (64 * ASTRIDE) + (ncol0 + nt * 8 + brow) * ASTRIDE + bcol) << 1));
            #pragma unroll
            for (int ai = 0; ai < 3; ai++) {
                if (ai + bj > 2) break;           // keep the 6 significant terms
                #pragma unroll
                for (int mt = 0; mt < 2; mt++)
                    #pragma unroll
                    for (int nt = 0; nt < 4; nt++)
                        mma_bf16(&acc[(mt * 4 + nt) * 4], afr[ai][mt], bfr[nt]);
            }
        }
        __syncthreads();

        if (c & 1) {
            #pragma unroll
            for (int i = 0; i < 32; i++) {
                KAHAN(macc[i], mcmp[i], acc[i]);
                acc[i] = 0.f;
            }
        }
    }

    // ------------- epilogue -------------
    int n0c = n0;
    float* Co = C;
    if (Nsplit && n0c >= Nsplit) { Co = C2; n0c -= Nsplit; }
    #pragma unroll
    for (int mt = 0; mt < 2; mt++)
        #pragma unroll
        for (int nt = 0; nt < 4; nt++)
            #pragma unroll
            for (int r = 0; r < 4; r++) {
                int i = (mt * 4 + nt) * 4 + r;
                float v = macc[i] + mcmp[i];
                int row = m0 + mrow0 + mt * 16 + (L >> 2) + ((r >> 1) * 8);
                int col = n0c + ncol0 + nt * 8 + ((L & 3) * 2) + (r & 1);
                if (bias) v += bias[col];
                if (act == 2) v = 0.5f * v * (1.f + erff(v * 0.70710678118654752f));
                if (resid) v += resid[(size_t)row * Nout + col];
                if (heads) {
                    int b = row >> 11, t = row & 2047;
                    int h = col >> 6, d = col & 63;
                    Co[((((size_t)b * H_ + h) * T_ + t) << 6) + d] = v;
                } else {
                    Co[(size_t)row * Nout + col] = v;
                }
            }
}

// ------------------------- scalar SGEMM (conv + final head) -----------------
__global__ __launch_bounds__(256) void sgemm(
    const float* __restrict__ A, const float* __restrict__ Bm,
    const float* __restrict__ bias, float* __restrict__ C,
    int M, int N, int K, int act)
{
    __shared__ float As[16][132];
    __shared__ float Bs[16][64];
    const int tid = threadIdx.x;
    const int tx = tid & 15, ty = tid >> 4;
    const int m0 = blockIdx.y * 128;
    int n0 = blockIdx.x * 64;

    float acc[8][4], cmp[8][4];
    #pragma unroll
    for (int i = 0; i < 8; i++)
        #pragma unroll
        for (int j = 0; j < 4; j++) { acc[i][j] = 0.f; cmp[i][j] = 0.f; }

    const int arow0 = tid >> 2, ac4 = (tid & 3) * 4;
    const int brow = tid >> 4, bc4 = (tid & 15) * 4;
    const int bcol = n0 + bc4;

    for (int k0 = 0; k0 < K; k0 += 16) {
        #pragma unroll
        for (int s = 0; s < 2; s++) {
            int row = arow0 + s * 64;
            float4 a = *(const float4*)(A + (size_t)(m0 + row) * K + k0 + ac4);
            As[ac4 + 0][row] = a.x; As[ac4 + 1][row] = a.y;
            As[ac4 + 2][row] = a.z; As[ac4 + 3][row] = a.w;
        }
        float4 bv;
        if (bcol < N) bv = *(const float4*)(Bm + (size_t)(k0 + brow) * N + bcol);
        else          bv = make_float4(0.f, 0.f, 0.f, 0.f);
        *(float4*)(&Bs[brow][bc4]) = bv;
        __syncthreads();
        float pb[8][4];
        #pragma unroll
        for (int kk = 0; kk < 16; kk++) {
            float4 a0 = *(const float4*)(&As[kk][ty * 8]);
            float4 a1 = *(const float4*)(&As[kk][ty * 8 + 4]);
            float4 bb = *(const float4*)(&Bs[kk][tx * 4]);
            float av[8] = {a0.x, a0.y, a0.z, a0.w, a1.x, a1.y, a1.z, a1.w};
            float bw[4] = {bb.x, bb.y, bb.z, bb.w};
            if (kk == 0) {
                #pragma unroll
                for (int i = 0; i < 8; i++)
                    #pragma unroll
                    for (int j = 0; j < 4; j++) pb[i][j] = av[i] * bw[j];
            } else {
                #pragma unroll
                for (int i = 0; i < 8; i++)
                    #pragma unroll
                    for (int j = 0; j < 4; j++) pb[i][j] = fmaf(av[i], bw[j], pb[i][j]);
            }
        }
        #pragma unroll
        for (int i = 0; i < 8; i++)
            #pragma unroll
            for (int j = 0; j < 4; j++) KAHAN(acc[i][j], cmp[i][j], pb[i][j]);
        __syncthreads();
    }

    #pragma unroll
    for (int i = 0; i < 8; i++) {
        int row = m0 + ty * 8 + i;
        #pragma unroll
        for (int j = 0; j < 4; j++) {
            int col = n0 + tx * 4 + j;
            if (col >= N) continue;
            float v = acc[i][j] + cmp[i][j];
            if (bias) v += bias[col];
            if (act == 1) v = fmaxf(v, 0.f);
            C[(size_t)row * N + col] = v;
        }
    }
}

// ------------------------- LayerNorm ----------------------------------------
__global__ __launch_bounds__(256) void ln_kernel(
    const float* __restrict__ x, const float* __restrict__ g,
    const float* __restrict__ bb, float* __restrict__ y)
{
    __shared__ float sh[8];
    int row = blockIdx.x, tid = threadIdx.x;
    const float* xr = x + (size_t)row * DIM;
    float v0 = xr[tid], v1 = xr[tid + 256];
    float s = v0 + v1;
    #pragma unroll
    for (int o = 16; o; o >>= 1) s += __shfl_down_sync(0xffffffffu, s, o);
    if ((tid & 31) == 0) sh[tid >> 5] = s;
    __syncthreads();
    if (tid < 32) {
        float t = (tid < 8) ? sh[tid] : 0.f;
        #pragma unroll
        for (int o = 4; o; o >>= 1) t += __shfl_down_sync(0xffffffffu, t, o);
        if (tid == 0) sh[0] = t;
    }
    __syncthreads();
    float mean = sh[0] * (1.f / DIM);
    __syncthreads();
    float d0 = v0 - mean, d1 = v1 - mean;
    float s2 = d0 * d0 + d1 * d1;
    #pragma unroll
    for (int o = 16; o; o >>= 1) s2 += __shfl_down_sync(0xffffffffu, s2, o);
    if ((tid & 31) == 0) sh[tid >> 5] = s2;
    __syncthreads();
    if (tid < 32) {
        float t = (tid < 8) ? sh[tid] : 0.f;
        #pragma unroll
        for (int o = 4; o; o >>= 1) t += __shfl_down_sync(0xffffffffu, t, o);
        if (tid == 0) sh[0] = t;
    }
    __syncthreads();
    float inv = 1.f / sqrtf(sh[0] * (1.f / DIM) + 1e-5f);
    float* yr = y + (size_t)row * DIM;
    yr[tid]       = d0 * inv * g[tid]       + bb[tid];
    yr[tid + 256] = d1 * inv * g[tid + 256] + bb[tid + 256];
}

// ------------------------- LSH hashing --------------------------------------
#define TCH 16
__global__ __launch_bounds__(128) void hash_kernel(
    const float* __restrict__ qk, const float* __restrict__ rot, int* __restrict__ bkt)
{
    __shared__ float q[4][DH];
    int blk = blockIdx.x;
    int bh = blk / (T_ / TCH);
    int t0 = (blk % (T_ / TCH)) * TCH;
    int tid = threadIdx.x;
    int h = tid >> 4, j = tid & 15;
    float rv[64];
    #pragma unroll
    for (int f = 0; f < 64; f++) rv[f] = rot[f * 128 + h * 16 + j];

    for (int tg = 0; tg < TCH; tg += 4) {
        __syncthreads();
        for (int idx = tid; idx < 4 * DH; idx += 128) {
            int r = idx >> 6, d = idx & 63;
            q[r][d] = qk[((size_t)bh * T_ + t0 + tg + r) * DH + d];
        }
        __syncthreads();
        float a0 = 0.f, a1 = 0.f, a2 = 0.f, a3 = 0.f;
        float c0 = 0.f, c1 = 0.f, c2 = 0.f, c3 = 0.f;
        #pragma unroll
        for (int f = 0; f < 64; f++) {
            float r = rv[f];
            float p0 = q[0][f] * r; KAHAN(a0, c0, p0);
            float p1 = q[1][f] * r; KAHAN(a1, c1, p1);
            float p2 = q[2][f] * r; KAHAN(a2, c2, p2);
            float p3 = q[3][f] * r; KAHAN(a3, c3, p3);
        }
        float vals[4] = {a0 + c0, a1 + c1, a2 + c2, a3 + c3};
        #pragma unroll
        for (int r = 0; r < 4; r++) {
            float v = vals[r]; int idx = j;
            float nv = -v;
            if (nv > v) { v = nv; idx = j + 16; }
            #pragma unroll
            for (int o = 8; o; o >>= 1) {
                float ov = __shfl_down_sync(0xffffffffu, v, o, 16);
                int   oi = __shfl_down_sync(0xffffffffu, idx, o, 16);
                if (ov > v || (ov == v && oi < idx)) { v = ov; idx = oi; }
            }
            if (j == 0) bkt[(size_t)bh * NHT + h * T_ + t0 + tg + r] = idx + h * NB;
        }
    }
}

// ------------------------- stable counting sort ------------------------------
__global__ __launch_bounds__(256) void sort_kernel(
    const int* __restrict__ bkt, int* __restrict__ st)
{
    __shared__ int hist[256];
    __shared__ int off[256];
    int bh = blockIdx.x, tid = threadIdx.x;
    const int* bb = bkt + (size_t)bh * NHT;
    hist[tid] = 0;
    __syncthreads();
    for (int i = tid; i < NHT; i += 256) atomicAdd(&hist[bb[i]], 1);
    __syncthreads();
    if (tid == 0) {
        int s = 0;
        for (int i = 0; i < 256; i++) { off[i] = s; s += hist[i]; }
    }
    __syncthreads();
    int beta = tid, h = tid >> 5;
    int o = off[beta];
    int* out2 = st + (size_t)bh * NHT;
    int base = h * T_;
    for (int k = 0; k < T_; k++)
        if (bb[base + k] == beta) out2[o++] = base + k;
}

// ------------------------- chunked LSH attention ----------------------------
#define RS 68
#define DS 129
__global__ __launch_bounds__(128) void attn_kernel(
    const float* __restrict__ qk, const float* __restrict__ vg,
    const int* __restrict__ st, float* __restrict__ og, float* __restrict__ lgg)
{
    extern __shared__ float sm[];
    float* r     = sm;
    float* vv    = r + 128 * RS;
    float* dots  = vv + 128 * 64;
    float* inorm = dots + 64 * DS;
    float* logit = inorm + 128;
    int*   kpos  = (int*)(logit + 64);
    int*   qh    = kpos + 128;

    int tid = threadIdx.x;
    int bh = blockIdx.x >> 8, c = blockIdx.x & 255;
    int cp = (c + NCH - 1) & 255;

    {
        int lc = (tid < 64) ? c : cp;
        int tk = st[(size_t)bh * NHT + lc * 64 + (tid & 63)];
        kpos[tid] = tk & (T_ - 1);
        if (tid < 64) qh[tid] = tk >> 11;
    }
    __syncthreads();

    const float* qb = qk + ((size_t)bh << 17);
    const float* vb = vg + ((size_t)bh << 17);
    for (int it = 0; it < 64; it++) {
        int idx = it * 128 + tid;
        int jj = idx >> 6, d = idx & 63;
        int pos = kpos[jj];
        r[jj * RS + d]    = qb[(pos << 6) + d];
        vv[(jj << 6) + d] = vb[(pos << 6) + d];
    }
    __syncthreads();
    {
        float s = 0.f, cs = 0.f;
        #pragma unroll 8
        for (int d = 0; d < 64; d++) {
            float x = r[tid * RS + d];
            float p = x * x; KAHAN(s, cs, p);
        }
        inorm[tid] = 1.f / fmaxf(sqrtf(s + cs), 1e-12f);
    }
    __syncthreads();

    int tx = tid & 15, ty = tid >> 4;
    float acc[8][8], cmp[8][8];
    #pragma unroll
    for (int i = 0; i < 8; i++)
        #pragma unroll
        for (int m = 0; m < 8; m++) { acc[i][m] = 0.f; cmp[i][m] = 0.f; }

    for (int db = 0; db < 16; db++) {
        float kvb[4][8];
        #pragma unroll
        for (int dd = 0; dd < 4; dd++)
            #pragma unroll
            for (int m = 0; m < 8; m++)
                kvb[dd][m] = r[(tx + 16 * m) * RS + db * 4 + dd];
        #pragma unroll
        for (int i = 0; i < 8; i++) {
            float qv[4];
            #pragma unroll
            for (int dd = 0; dd < 4; dd++) qv[dd] = r[(ty * 8 + i) * RS + db * 4 + dd];
            float pb[8];
            #pragma unroll
            for (int m = 0; m < 8; m++) {
                float p = qv[0] * kvb[0][m];
                p = fmaf(qv[1], kvb[1][m], p);
                p = fmaf(qv[2], kvb[2][m], p);
                p = fmaf(qv[3], kvb[3][m], p);
                pb[m] = p;
            }
            #pragma unroll
            for (int m = 0; m < 8; m++) KAHAN(acc[i][m], cmp[i][m], pb[m]);
        }
    }
    #pragma unroll
    for (int i = 0; i < 8; i++) {
        int row = ty * 8 + i; int rp = kpos[row];
        #pragma unroll
        for (int m = 0; m < 8; m++) {
            int col = tx + 16 * m;
            float dv = (acc[i][m] + cmp[i][m]) * inorm[col] * 0.125f;
            if (rp == kpos[col]) dv = -5e4f;
            dots[row * DS + col] = dv;
        }
    }
    __syncthreads();

    if (tid < 64) {
        float mx = -1e30f;
        #pragma unroll 8
        for (int j2 = 0; j2 < 128; j2++) mx = fmaxf(mx, dots[tid * DS + j2]);
        float s = 0.f;
        #pragma unroll 8
        for (int j2 = 0; j2 < 128; j2++) s += expf(dots[tid * DS + j2] - mx);
        float lg = mx + logf(s);
        logit[tid] = lg;
        lgg[((size_t)bh * NH + qh[tid]) * T_ + kpos[tid]] = lg;
    }
    __syncthreads();
    for (int it = 0; it < 64; it++) {
        int idx = it * 128 + tid; int i = idx >> 7, j2 = idx & 127;
        dots[i * DS + j2] = expf(dots[i * DS + j2] - logit[i]);
    }
    __syncthreads();

    float a2[8][4], c2[8][4];
    #pragma unroll
    for (int i = 0; i < 8; i++)
        #pragma unroll
        for (int m = 0; m < 4; m++) { a2[i][m] = 0.f; c2[i][m] = 0.f; }
    for (int jb = 0; jb < 32; jb++) {
        float vwb[4][4];
        #pragma unroll
        for (int dd = 0; dd < 4; dd++)
            #pragma unroll
            for (int m = 0; m < 4; m++)
                vwb[dd][m] = vv[(((jb * 4 + dd)) << 6) + tx + 16 * m];
        #pragma unroll
        for (int i = 0; i < 8; i++) {
            float pv[4];
            #pragma unroll
            for (int dd = 0; dd < 4; dd++) pv[dd] = dots[(ty * 8 + i) * DS + jb * 4 + dd];
            float pb[4];
            #pragma unroll
            for (int m = 0; m < 4; m++) {
                float p = pv[0] * vwb[0][m];
                p = fmaf(pv[1], vwb[1][m], p);
                p = fmaf(pv[2], vwb[2][m], p);
                p = fmaf(pv[3], vwb[3][m], p);
                pb[m] = p;
            }
            #pragma unroll
            for (int m = 0; m < 4; m++) KAHAN(a2[i][m], c2[i][m], pb[m]);
        }
    }
    #pragma unroll
    for (int i = 0; i < 8; i++) {
        int row = ty * 8 + i;
        size_t base = (((size_t)bh * NH + qh[row]) * T_ + kpos[row]) << 6;
        #pragma unroll
        for (int m = 0; m < 4; m++) og[base + tx + 16 * m] = a2[i][m] + c2[i][m];
    }
}

// ------------------------- combine hash rounds ------------------------------
__global__ __launch_bounds__(64) void combine_kernel(
    const float* __restrict__ og, const float* __restrict__ lgg, float* __restrict__ at)
{
    __shared__ float w[8];
    int bh = blockIdx.x >> 11, pos = blockIdx.x & 2047;
    int tid = threadIdx.x;
    if (tid == 0) {
        float v[8]; float mx = -1e30f;
        #pragma unroll
        for (int h = 0; h < 8; h++) {
            v[h] = lgg[((size_t)bh * NH + h) * T_ + pos];
            mx = fmaxf(mx, v[h]);
        }
        float s = 0.f;
        #pragma unroll
        for (int h = 0; h < 8; h++) { v[h] = expf(v[h] - mx); s += v[h]; }
        float is = 1.f / s;
        #pragma unroll
        for (int h = 0; h < 8; h++) w[h] = v[h] * is;
    }
    __syncthreads();
    float acc = 0.f, cc = 0.f;
    #pragma unroll
    for (int h = 0; h < 8; h++) {
        float p = w[h] * og[(((size_t)bh * NH + h) * T_ + pos) * 64 + tid];
        KAHAN(acc, cc, p);
    }
    int b = bh >> 3, hd = bh & 7;
    at[((size_t)(b * T_ + pos)) * DIM + hd * 64 + tid] = acc + cc;
}

// ------------------------- frontend helpers ---------------------------------
__global__ void wt_kernel(const float* __restrict__ w, float* __restrict__ wT)
{
    int idx = blockIdx.x * 256 + threadIdx.x;
    int c = idx / DIM, o2 = idx - c * DIM;
    wT[idx] = (c < 687) ? w[(size_t)o2 * 687 + c] : 0.f;
}

__global__ void im2col_kernel(const float* __restrict__ spec, float* __restrict__ im)
{
    int idx = blockIdx.x * 256 + threadIdx.x;
    int row = idx / KC, c = idx - row * KC;
    int b = row >> 11, t = row & 2047;
    float val = 0.f;
    if (c < 687) {
        int i = c / 3, k = c - i * 3;
        int tt = t + k - 1;
        if (tt >= 0 && tt < T_) val = spec[((size_t)b * T_ + tt) * 229 + i];
    }
    im[idx] = val;
}

__global__ void pe_kernel(float* __restrict__ x1, float* __restrict__ x2,
                          const float* __restrict__ per, const float* __restrict__ pec)
{
    int idx = blockIdx.x * 256 + threadIdx.x;
    int c = idx & 511;
    int t = (idx >> 9) & 2047;
    float p = (c < 256) ? per[(t >> 6) * 256 + c] : pec[(t & 63) * 256 + (c - 256)];
    float v = x1[idx] + p;
    x1[idx] = v; x2[idx] = v;
}

__global__ void avg_kernel(const float* __restrict__ a, const float* __restrict__ b,
                           float* __restrict__ y)
{
    int idx = blockIdx.x * 256 + threadIdx.x;
    y[idx] = 0.5f * (a[idx] + b[idx]);
}

// ------------------------- driver -------------------------------------------
extern "C" void kernel_launch(void* const* d_in, const int* in_sizes, int n_in,
                              void* d_out, int out_size)
{
    const float* spec   = (const float*)d_in[0];
    const float* conv_w = (const float*)d_in[1];
    const float* conv_b = (const float*)d_in[2];
    const float* pe_row = (const float*)d_in[3];
    const float* pe_col = (const float*)d_in[4];
    const float* lnA_g  = (const float*)d_in[5];
    const float* lnA_b  = (const float*)d_in[6];
    const float* wqk    = (const float*)d_in[7];
    const float* wv     = (const float*)d_in[8];
    const float* wo     = (const float*)d_in[9];
    const float* bo     = (const float*)d_in[10];
    const float* lnF_g  = (const float*)d_in[11];
    const float* lnF_b  = (const float*)d_in[12];
    const float* w1     = (const float*)d_in[13];
    const float* b1     = (const float*)d_in[14];
    const float* w2     = (const float*)d_in[15];
    const float* b2     = (const float*)d_in[16];
    const float* lin_w  = (const float*)d_in[17];
    const float* lin_b  = (const float*)d_in[18];
    const float* rot    = (const float*)d_in[19];
    float* out = (float*)d_out;

    float *x1, *x2, *tmp, *qk, *v, *at, *ff, *im, *wT, *o, *lg;
    int *bk, *st;
    __nv_bfloat16 *a0, *a1, *a2, *bt0, *bt1, *bt2;
    cudaGetSymbolAddress((void**)&x1, g_x1);
    cudaGetSymbolAddress((void**)&x2, g_x2);
    cudaGetSymbolAddress((void**)&tmp, g_tmp);
    cudaGetSymbolAddress((void**)&qk, g_qk);
    cudaGetSymbolAddress((void**)&v,  g_v);
    cudaGetSymbolAddress((void**)&at, g_at);
    cudaGetSymbolAddress((void**)&ff, g_ffb);
    cudaGetSymbolAddress((void**)&im, g_im);
    cudaGetSymbolAddress((void**)&wT, g_wT);
    cudaGetSymbolAddress((void**)&o,  g_o);
    cudaGetSymbolAddress((void**)&lg, g_lg);
    cudaGetSymbolAddress((void**)&bk, g_bk);
    cudaGetSymbolAddress((void**)&st, g_st);
    cudaGetSymbolAddress((void**)&a0, g_a0);
    cudaGetSymbolAddress((void**)&a1, g_a1);
    cudaGetSymbolAddress((void**)&a2, g_a2);
    cudaGetSymbolAddress((void**)&bt0, g_bt0);
    cudaGetSymbolAddress((void**)&bt1, g_bt1);
    cudaGetSymbolAddress((void**)&bt2, g_bt2);

    size_t asmem = (size_t)(128 * RS + 128 * 64 + 64 * DS + 128 + 64 + 128 + 64) * 4;
    cudaFuncSetAttribute(attn_kernel, cudaFuncAttributeMaxDynamicSharedMemorySize, (int)asmem);

    // frontend
    wt_kernel<<<(KC * DIM) / 256, 256>>>(conv_w, wT);
    im2col_kernel<<<(BT * KC) / 256, 256>>>(spec, im);
    sgemm<<<dim3(DIM / 64, BT / 128), 256>>>(im, wT, conv_b, x1, BT, DIM, KC, 1);
    pe_kernel<<<(BT * DIM) / 256, 256>>>(x1, x2, pe_row, pe_col);

    const int nA = BT * DIM;
    const int nF = BT * FF;
    for (int i = 0; i < 8; i++) {
        ln_kernel<<<BT, 256>>>(x2, lnA_g + i * DIM, lnA_b + i * DIM, tmp);
        // QKV (fused dual output, heads layout)
        cvt3a_kernel<<<(nA + 255) / 256, 256>>>(tmp, nA, a0, a1, a2);
        cvt3b_kernel<<<(DIM * DIM + 255) / 256, 256>>>(wqk + (size_t)i * DIM * DIM, DIM, DIM, 0, bt0, bt1, bt2);
        cvt3b_kernel<<<(DIM * DIM + 255) / 256, 256>>>(wv + (size_t)i * DIM * DIM, DIM, DIM, DIM, bt0, bt1, bt2);
        tgemm<<<dim3(16, 32), 256>>>(a0, a1, a2, bt0, bt1, bt2,
                                     nullptr, nullptr, qk, v, DIM, DIM, 0, 1, DIM);
        hash_kernel<<<BH * (T_ / TCH), 128>>>(qk, rot + (size_t)i * 64 * 128, bk);
        sort_kernel<<<BH, 256>>>(bk, st);
        attn_kernel<<<BH * NCH, 128, asmem>>>(qk, v, st, o, lg);
        combine_kernel<<<BH * T_, 64>>>(o, lg, at);
        // O projection + residual into x1
        cvt3a_kernel<<<(nA + 255) / 256, 256>>>(at, nA, a0, a1, a2);
        cvt3b_kernel<<<(DIM * DIM + 255) / 256, 256>>>(wo + (size_t)i * DIM * DIM, DIM, DIM, 0, bt0, bt1, bt2);
        tgemm<<<dim3(8, 32), 256>>>(a0, a1, a2, bt0, bt1, bt2,
                                    bo + i * DIM, x1, x1, nullptr, DIM, DIM, 0, 0, 0);
        ln_kernel<<<BT, 256>>>(x1, lnF_g + i * DIM, lnF_b + i * DIM, tmp);
        // FFN1 (gelu)
        cvt3a_kernel<<<(nA + 255) / 256, 256>>>(tmp, nA, a0, a1, a2);
        cvt3b_kernel<<<(DIM * FF + 255) / 256, 256>>>(w1 + (size_t)i * DIM * FF, DIM, FF, 0, bt0, bt1, bt2);
        tgemm<<<dim3(32, 32), 256>>>(a0, a1, a2, bt0, bt1, bt2,
                                     b1 + i * FF, nullptr, ff, nullptr, DIM, FF, 2, 0, 0);
        // FFN2 (+ residual into x2)
        cvt3a_kernel<<<(nF + 255) / 256, 256>>>(ff, nF, a0, a1, a2);
        cvt3b_kernel<<<(FF * DIM + 255) / 256, 256>>>(w2 + (size_t)i * FF * DIM, FF, DIM, 0, bt0, bt1, bt2);
        tgemm<<<dim3(8, 32), 256>>>(a0, a1, a2, bt0, bt1, bt2,
                                    b2 + i * DIM, x2, x2, nullptr, FF, DIM, 0, 0, 0);
    }

    avg_kernel<<<(BT * DIM) / 256, 256>>>(x1, x2, tmp);
    sgemm<<<dim3(2, 32), 256>>>(tmp, lin_w, lin_b, out, BT, 88, DIM, 0);
}

// round 12
// speedup vs baseline: 1.7003x; 1.0783x over previous
#include <cuda_runtime.h>
#include <cuda_bf16.h>
#include <math.h>
#include <stdint.h>

#define B_   2
#define T_   2048
#define BT   4096
#define DIM  512
#define H_   8
#define DH   64
#define NH   8
#define NB   32
#define NCH  256
#define BH   16
#define NHT  16384
#define KC   704
#define FF   2048

#define KAHAN(s, c, p) { float y_ = (p) - (c); float t_ = (s) + y_; (c) = (t_ - (s)) - y_; (s) = t_; }

// ------------------------- scratch (static device) -------------------------
__device__ float g_x1[BT*DIM];
__device__ float g_x2[BT*DIM];
__device__ float g_tmp[BT*DIM];
__device__ float g_qk[BT*DIM];
__device__ float g_v [BT*DIM];
__device__ float g_at[BT*DIM];
__device__ float g_im[BT*KC];
__device__ float g_wT[KC*DIM];
__device__ int   g_bk[BH*NHT];
__device__ int   g_st[BH*NHT];
__device__ float g_o [BH*NHT*DH];
__device__ float g_lg[BH*NHT];
// bf16 split buffers (activations: a* for DIM-wide inputs, f* for FFN hidden)
__device__ __nv_bfloat16 g_a0[BT*DIM];
__device__ __nv_bfloat16 g_a1[BT*DIM];
__device__ __nv_bfloat16 g_a2[BT*DIM];
__device__ __nv_bfloat16 g_f0[BT*FF];
__device__ __nv_bfloat16 g_f1[BT*FF];
__device__ __nv_bfloat16 g_f2[BT*FF];
__device__ __nv_bfloat16 g_bt0[2*1024*1024];
__device__ __nv_bfloat16 g_bt1[2*1024*1024];
__device__ __nv_bfloat16 g_bt2[2*1024*1024];

// ------------------------- warp-mma helpers ---------------------------------
__device__ __forceinline__ uint32_t smem_u32(const void* p) {
    uint32_t a;
    asm("{ .reg .u64 t; cvta.to.shared.u64 t, %1; cvt.u32.u64 %0, t; }" : "=r"(a) : "l"(p));
    return a;
}
__device__ __forceinline__ void ldsm_x4(uint32_t* r, uint32_t addr) {
    asm volatile("ldmatrix.sync.aligned.m8n8.x4.shared.b16 {%0,%1,%2,%3}, [%4];"
        : "=r"(r[0]), "=r"(r[1]), "=r"(r[2]), "=r"(r[3]) : "r"(addr));
}
__device__ __forceinline__ void ldsm_x2(uint32_t* r, uint32_t addr) {
    asm volatile("ldmatrix.sync.aligned.m8n8.x2.shared.b16 {%0,%1}, [%2];"
        : "=r"(r[0]), "=r"(r[1]) : "r"(addr));
}
__device__ __forceinline__ void mma_bf16(float* d, const uint32_t* a, const uint32_t* b) {
    asm volatile("mma.sync.aligned.m16n8k16.row.col.f32.bf16.bf16.f32 "
        "{%0,%1,%2,%3}, {%4,%5,%6,%7}, {%8,%9}, {%0,%1,%2,%3};"
        : "+f"(d[0]), "+f"(d[1]), "+f"(d[2]), "+f"(d[3])
        : "r"(a[0]), "r"(a[1]), "r"(a[2]), "r"(a[3]), "r"(b[0]), "r"(b[1]));
}
__device__ __forceinline__ void cp16(uint32_t dst, const void* src) {
    size_t g = (size_t)__cvta_generic_to_global(src);
    asm volatile("cp.async.cg.shared.global [%0], [%1], 16;" :: "r"(dst), "l"(g));
}

// ------------------------- fp32 -> bf16x3 conversions -----------------------
__device__ __forceinline__ void split3(float v, __nv_bfloat16& b0, __nv_bfloat16& b1,
                                       __nv_bfloat16& b2) {
    b0 = __float2bfloat16(v);
    float r = v - __bfloat162float(b0);
    b1 = __float2bfloat16(r);
    float r2 = r - __bfloat162float(b1);
    b2 = __float2bfloat16(r2);
}
__global__ void cvt3a_kernel(const float* __restrict__ src, int n,
                             __nv_bfloat16* __restrict__ d0, __nv_bfloat16* __restrict__ d1,
                             __nv_bfloat16* __restrict__ d2)
{
    int i = blockIdx.x * 256 + threadIdx.x;
    if (i >= n) return;
    __nv_bfloat16 b0, b1, b2;
    split3(src[i], b0, b1, b2);
    d0[i] = b0; d1[i] = b1; d2[i] = b2;
}
// W [K, N] fp32 -> Bt splits [rowoff+N, K] bf16 (transposed)
__global__ void cvt3b_kernel(const float* __restrict__ W, int Kd, int Nd, int rowoff,
                             __nv_bfloat16* __restrict__ d0, __nv_bfloat16* __restrict__ d1,
                             __nv_bfloat16* __restrict__ d2)
{
    int i = blockIdx.x * 256 + threadIdx.x;
    if (i >= Kd * Nd) return;
    int nrow = i / Kd, k = i - nrow * Kd;
    __nv_bfloat16 b0, b1, b2;
    split3(W[(size_t)k * Nd + nrow], b0, b1, b2);
    size_t o = (size_t)(rowoff + nrow) * Kd + k;
    d0[o] = b0; d1[o] = b1; d2[o] = b2;
}

// ------------------------- tensor-core bf16x3 GEMM (mma.sync, cp.async) -----
// BM=128, BN=64, BK=16, 256 threads (8 warps, each 32x32). Double-buffered
// cp.async staging. 6 significant cross-products, fp32 mma accum, Kahan merge
// every 2 K-chunks. s0!=null: epilogue writes bf16x3 splits (to DISJOINT bufs).
#define ASTRIDE 24
#define ABYTES (3 * 128 * ASTRIDE * 2)
#define BBYTES (3 * 64 * ASTRIDE * 2)
#define TG_SMEM (2 * (ABYTES + BBYTES))
__global__ __launch_bounds__(256) void tgemm(
    const __nv_bfloat16* __restrict__ a0, const __nv_bfloat16* __restrict__ a1,
    const __nv_bfloat16* __restrict__ a2,
    const __nv_bfloat16* __restrict__ bt0, const __nv_bfloat16* __restrict__ bt1,
    const __nv_bfloat16* __restrict__ bt2,
    const float* __restrict__ bias, const float* __restrict__ resid,
    float* __restrict__ C, float* __restrict__ C2,
    __nv_bfloat16* __restrict__ s0, __nv_bfloat16* __restrict__ s1,
    __nv_bfloat16* __restrict__ s2,
    int K, int Nout, int act, int heads, int Nsplit)
{
    extern __shared__ char smem[];
    const int tid = threadIdx.x;
    const int L = tid & 31, w = tid >> 5;
    const int mrow0 = (w & 3) * 32, ncol0 = (w >> 2) * 32;
    const int m0 = blockIdx.y * 128;
    const int n0 = blockIdx.x * 64;

    const uint32_t base = smem_u32(smem);
    const int arow = (L & 7) + ((L >> 3) & 1) * 8;
    const int acol = (L >> 4) * 8;
    const int brow = L & 7, bcol = ((L >> 3) & 1) * 8;

    const __nv_bfloat16* asp[3] = {a0, a1, a2};
    const __nv_bfloat16* bsp[3] = {bt0, bt1, bt2};

#define ISSUE_CHUNK(c, buf) do { \
    const int k0_ = (c) << 4; \
    _Pragma("unroll") \
    for (int it = 0; it < 3; it++) { \
        int idx = tid + it * 256; \
        int sp = idx >> 8, rem = idx & 255; \
        int row = rem >> 1, seg = rem & 1; \
        uint32_t dst = base + (buf) * ABYTES + \
            ((sp * (128 * ASTRIDE) + row * ASTRIDE + seg * 8) << 1); \
        cp16(dst, asp[sp] + (size_t)(m0 + row) * K + k0_ + seg * 8); \
    } \
    { \
        int idx = tid; \
        int sp = idx >> 7, rem = idx & 127, row = rem >> 1, seg = rem & 1; \
        uint32_t dst = base + 2 * ABYTES + (buf) * BBYTES + \
            ((sp * (64 * ASTRIDE) + row * ASTRIDE + seg * 8) << 1); \
        cp16(dst, bsp[sp] + (size_t)(n0 + row) * K + k0_ + seg * 8); \
    } \
    if (tid < 128) { \
        int idx = tid + 256; \
        int sp = idx >> 7, rem = idx & 127, row = rem >> 1, seg = rem & 1; \
        uint32_t dst = base + 2 * ABYTES + (buf) * BBYTES + \
            ((sp * (64 * ASTRIDE) + row * ASTRIDE + seg * 8) << 1); \
        cp16(dst, bsp[sp] + (size_t)(n0 + row) * K + k0_ + seg * 8); \
    } \
    asm volatile("cp.async.commit_group;" ::: "memory"); \
} while (0)

    float acc[32], macc[32], mcmp[32];
    #pragma unroll
    for (int i = 0; i < 32; i++) { acc[i] = 0.f; macc[i] = 0.f; mcmp[i] = 0.f; }

    const int nch = K >> 4;
    ISSUE_CHUNK(0, 0);

    for (int c = 0; c < nch; c++) {
        const int buf = c & 1;
        if (c + 1 < nch) {
            ISSUE_CHUNK(c + 1, buf ^ 1);
            asm volatile("cp.async.wait_group 1;" ::: "memory");
        } else {
            asm volatile("cp.async.wait_group 0;" ::: "memory");
        }
        __syncthreads();

        const uint32_t Ab = base + buf * ABYTES;
        const uint32_t Bb = base + 2 * ABYTES + buf * BBYTES;

        uint32_t afr[3][2][4];
        #pragma unroll
        for (int sp = 0; sp < 3; sp++)
            #pragma unroll
            for (int mt = 0; mt < 2; mt++)
                ldsm_x4(afr[sp][mt],
                        Ab + ((sp * (128 * ASTRIDE) + (mrow0 + mt * 16 + arow) * ASTRIDE + acol) << 1));

        #pragma unroll
        for (int bj = 0; bj < 3; bj++) {
            uint32_t bfr[4][2];
            #pragma unroll
            for (int nt = 0; nt < 4; nt++)
                ldsm_x2(bfr[nt],
                        Bb + ((bj * (64 * ASTRIDE) + (ncol0 + nt * 8 + brow) * ASTRIDE + bcol) << 1));
            #pragma unroll
            for (int ai = 0; ai < 3; ai++) {
                if (ai + bj > 2) break;
                #pragma unroll
                for (int mt = 0; mt < 2; mt++)
                    #pragma unroll
                    for (int nt = 0; nt < 4; nt++)
                        mma_bf16(&acc[(mt * 4 + nt) * 4], afr[ai][mt], bfr[nt]);
            }
        }
        __syncthreads();

        if (c & 1) {
            #pragma unroll
            for (int i = 0; i < 32; i++) {
                KAHAN(macc[i], mcmp[i], acc[i]);
                acc[i] = 0.f;
            }
        }
    }

    // ------------- epilogue -------------
    int n0c = n0;
    float* Co = C;
    if (Nsplit && n0c >= Nsplit) { Co = C2; n0c -= Nsplit; }
    #pragma unroll
    for (int mt = 0; mt < 2; mt++)
        #pragma unroll
        for (int nt = 0; nt < 4; nt++)
            #pragma unroll
            for (int r = 0; r < 4; r++) {
                int i = (mt * 4 + nt) * 4 + r;
                float v = macc[i] + mcmp[i];
                int row = m0 + mrow0 + mt * 16 + (L >> 2) + ((r >> 1) * 8);
                int col = n0c + ncol0 + nt * 8 + ((L & 3) * 2) + (r & 1);
                if (bias) v += bias[col];
                if (act == 2) v = 0.5f * v * (1.f + erff(v * 0.70710678118654752f));
                if (resid) v += resid[(size_t)row * Nout + col];
                if (s0) {
                    __nv_bfloat16 b0, b1, b2;
                    split3(v, b0, b1, b2);
                    size_t o = (size_t)row * Nout + col;
                    s0[o] = b0; s1[o] = b1; s2[o] = b2;
                } else if (heads) {
                    int b = row >> 11, t = row & 2047;
                    int h = col >> 6, d = col & 63;
                    Co[((((size_t)b * H_ + h) * T_ + t) << 6) + d] = v;
                } else {
                    Co[(size_t)row * Nout + col] = v;
                }
            }
}

// ------------------------- scalar SGEMM (conv + final head) -----------------
__global__ __launch_bounds__(256) void sgemm(
    const float* __restrict__ A, const float* __restrict__ Bm,
    const float* __restrict__ bias, float* __restrict__ C,
    int M, int N, int K, int act)
{
    __shared__ float As[16][132];
    __shared__ float Bs[16][64];
    const int tid = threadIdx.x;
    const int tx = tid & 15, ty = tid >> 4;
    const int m0 = blockIdx.y * 128;
    int n0 = blockIdx.x * 64;

    float acc[8][4], cmp[8][4];
    #pragma unroll
    for (int i = 0; i < 8; i++)
        #pragma unroll
        for (int j = 0; j < 4; j++) { acc[i][j] = 0.f; cmp[i][j] = 0.f; }

    const int arow0 = tid >> 2, ac4 = (tid & 3) * 4;
    const int brow = tid >> 4, bc4 = (tid & 15) * 4;
    const int bcol = n0 + bc4;

    for (int k0 = 0; k0 < K; k0 += 16) {
        #pragma unroll
        for (int s = 0; s < 2; s++) {
            int row = arow0 + s * 64;
            float4 a = *(const float4*)(A + (size_t)(m0 + row) * K + k0 + ac4);
            As[ac4 + 0][row] = a.x; As[ac4 + 1][row] = a.y;
            As[ac4 + 2][row] = a.z; As[ac4 + 3][row] = a.w;
        }
        float4 bv;
        if (bcol < N) bv = *(const float4*)(Bm + (size_t)(k0 + brow) * N + bcol);
        else          bv = make_float4(0.f, 0.f, 0.f, 0.f);
        *(float4*)(&Bs[brow][bc4]) = bv;
        __syncthreads();
        float pb[8][4];
        #pragma unroll
        for (int kk = 0; kk < 16; kk++) {
            float4 a0 = *(const float4*)(&As[kk][ty * 8]);
            float4 a1 = *(const float4*)(&As[kk][ty * 8 + 4]);
            float4 bb = *(const float4*)(&Bs[kk][tx * 4]);
            float av[8] = {a0.x, a0.y, a0.z, a0.w, a1.x, a1.y, a1.z, a1.w};
            float bw[4] = {bb.x, bb.y, bb.z, bb.w};
            if (kk == 0) {
                #pragma unroll
                for (int i = 0; i < 8; i++)
                    #pragma unroll
                    for (int j = 0; j < 4; j++) pb[i][j] = av[i] * bw[j];
            } else {
                #pragma unroll
                for (int i = 0; i < 8; i++)
                    #pragma unroll
                    for (int j = 0; j < 4; j++) pb[i][j] = fmaf(av[i], bw[j], pb[i][j]);
            }
        }
        #pragma unroll
        for (int i = 0; i < 8; i++)
            #pragma unroll
            for (int j = 0; j < 4; j++) KAHAN(acc[i][j], cmp[i][j], pb[i][j]);
        __syncthreads();
    }

    #pragma unroll
    for (int i = 0; i < 8; i++) {
        int row = m0 + ty * 8 + i;
        #pragma unroll
        for (int j = 0; j < 4; j++) {
            int col = n0 + tx * 4 + j;
            if (col >= N) continue;
            float v = acc[i][j] + cmp[i][j];
            if (bias) v += bias[col];
            if (act == 1) v = fmaxf(v, 0.f);
            C[(size_t)row * N + col] = v;
        }
    }
}

// ------------------------- LayerNorm ----------------------------------------
__global__ __launch_bounds__(256) void ln_kernel(
    const float* __restrict__ x, const float* __restrict__ g,
    const float* __restrict__ bb, float* __restrict__ y)
{
    __shared__ float sh[8];
    int row = blockIdx.x, tid = threadIdx.x;
    const float* xr = x + (size_t)row * DIM;
    float v0 = xr[tid], v1 = xr[tid + 256];
    float s = v0 + v1;
    #pragma unroll
    for (int o = 16; o; o >>= 1) s += __shfl_down_sync(0xffffffffu, s, o);
    if ((tid & 31) == 0) sh[tid >> 5] = s;
    __syncthreads();
    if (tid < 32) {
        float t = (tid < 8) ? sh[tid] : 0.f;
        #pragma unroll
        for (int o = 4; o; o >>= 1) t += __shfl_down_sync(0xffffffffu, t, o);
        if (tid == 0) sh[0] = t;
    }
    __syncthreads();
    float mean = sh[0] * (1.f / DIM);
    __syncthreads();
    float d0 = v0 - mean, d1 = v1 - mean;
    float s2 = d0 * d0 + d1 * d1;
    #pragma unroll
    for (int o = 16; o; o >>= 1) s2 += __shfl_down_sync(0xffffffffu, s2, o);
    if ((tid & 31) == 0) sh[tid >> 5] = s2;
    __syncthreads();
    if (tid < 32) {
        float t = (tid < 8) ? sh[tid] : 0.f;
        #pragma unroll
        for (int o = 4; o; o >>= 1) t += __shfl_down_sync(0xffffffffu, t, o);
        if (tid == 0) sh[0] = t;
    }
    __syncthreads();
    float inv = 1.f / sqrtf(sh[0] * (1.f / DIM) + 1e-5f);
    float* yr = y + (size_t)row * DIM;
    yr[tid]       = d0 * inv * g[tid]       + bb[tid];
    yr[tid + 256] = d1 * inv * g[tid + 256] + bb[tid + 256];
}

// ------------------------- LSH hashing --------------------------------------
#define TCH 16
__global__ __launch_bounds__(128) void hash_kernel(
    const float* __restrict__ qk, const float* __restrict__ rot, int* __restrict__ bkt)
{
    __shared__ float q[4][DH];
    int blk = blockIdx.x;
    int bh = blk / (T_ / TCH);
    int t0 = (blk % (T_ / TCH)) * TCH;
    int tid = threadIdx.x;
    int h = tid >> 4, j = tid & 15;
    float rv[64];
    #pragma unroll
    for (int f = 0; f < 64; f++) rv[f] = rot[f * 128 + h * 16 + j];

    for (int tg = 0; tg < TCH; tg += 4) {
        __syncthreads();
        for (int idx = tid; idx < 4 * DH; idx += 128) {
            int r = idx >> 6, d = idx & 63;
            q[r][d] = qk[((size_t)bh * T_ + t0 + tg + r) * DH + d];
        }
        __syncthreads();
        float a0 = 0.f, a1 = 0.f, a2 = 0.f, a3 = 0.f;
        float c0 = 0.f, c1 = 0.f, c2 = 0.f, c3 = 0.f;
        #pragma unroll
        for (int f = 0; f < 64; f++) {
            float r = rv[f];
            float p0 = q[0][f] * r; KAHAN(a0, c0, p0);
            float p1 = q[1][f] * r; KAHAN(a1, c1, p1);
            float p2 = q[2][f] * r; KAHAN(a2, c2, p2);
            float p3 = q[3][f] * r; KAHAN(a3, c3, p3);
        }
        float vals[4] = {a0 + c0, a1 + c1, a2 + c2, a3 + c3};
        #pragma unroll
        for (int r = 0; r < 4; r++) {
            float v = vals[r]; int idx = j;
            float nv = -v;
            if (nv > v) { v = nv; idx = j + 16; }
            #pragma unroll
            for (int o = 8; o; o >>= 1) {
                float ov = __shfl_down_sync(0xffffffffu, v, o, 16);
                int   oi = __shfl_down_sync(0xffffffffu, idx, o, 16);
                if (ov > v || (ov == v && oi < idx)) { v = ov; idx = oi; }
            }
            if (j == 0) bkt[(size_t)bh * NHT + h * T_ + t0 + tg + r] = idx + h * NB;
        }
    }
}

// ------------------------- stable counting sort ------------------------------
__global__ __launch_bounds__(256) void sort_kernel(
    const int* __restrict__ bkt, int* __restrict__ st)
{
    __shared__ int hist[256];
    __shared__ int off[256];
    int bh = blockIdx.x, tid = threadIdx.x;
    const int* bb = bkt + (size_t)bh * NHT;
    hist[tid] = 0;
    __syncthreads();
    for (int i = tid; i < NHT; i += 256) atomicAdd(&hist[bb[i]], 1);
    __syncthreads();
    if (tid == 0) {
        int s = 0;
        for (int i = 0; i < 256; i++) { off[i] = s; s += hist[i]; }
    }
    __syncthreads();
    int beta = tid, h = tid >> 5;
    int o = off[beta];
    int* out2 = st + (size_t)bh * NHT;
    int base = h * T_;
    for (int k = 0; k < T_; k++)
        if (bb[base + k] == beta) out2[o++] = base + k;
}

// ------------------------- chunked LSH attention ----------------------------
#define RS 68
#define DS 129
__global__ __launch_bounds__(128) void attn_kernel(
    const float* __restrict__ qk, const float* __restrict__ vg,
    const int* __restrict__ st, float* __restrict__ og, float* __restrict__ lgg)
{
    extern __shared__ float sm[];
    float* r     = sm;
    float* vv    = r + 128 * RS;
    float* dots  = vv + 128 * 64;
    float* inorm = dots + 64 * DS;
    float* logit = inorm + 128;
    int*   kpos  = (int*)(logit + 64);
    int*   qh    = kpos + 128;

    int tid = threadIdx.x;
    int bh = blockIdx.x >> 8, c = blockIdx.x & 255;
    int cp = (c + NCH - 1) & 255;

    {
        int lc = (tid < 64) ? c : cp;
        int tk = st[(size_t)bh * NHT + lc * 64 + (tid & 63)];
        kpos[tid] = tk & (T_ - 1);
        if (tid < 64) qh[tid] = tk >> 11;
    }
    __syncthreads();

    const float* qb = qk + ((size_t)bh << 17);
    const float* vb = vg + ((size_t)bh << 17);
    for (int it = 0; it < 64; it++) {
        int idx = it * 128 + tid;
        int jj = idx >> 6, d = idx & 63;
        int pos = kpos[jj];
        r[jj * RS + d]    = qb[(pos << 6) + d];
        vv[(jj << 6) + d] = vb[(pos << 6) + d];
    }
    __syncthreads();
    {
        float s = 0.f, cs = 0.f;
        #pragma unroll 8
        for (int d = 0; d < 64; d++) {
            float x = r[tid * RS + d];
            float p = x * x; KAHAN(s, cs, p);
        }
        inorm[tid] = 1.f / fmaxf(sqrtf(s + cs), 1e-12f);
    }
    __syncthreads();

    int tx = tid & 15, ty = tid >> 4;
    float acc[8][8], cmp[8][8];
    #pragma unroll
    for (int i = 0; i < 8; i++)
        #pragma unroll
        for (int m = 0; m < 8; m++) { acc[i][m] = 0.f; cmp[i][m] = 0.f; }

    for (int db = 0; db < 16; db++) {
        float kvb[4][8];
        #pragma unroll
        for (int dd = 0; dd < 4; dd++)
            #pragma unroll
            for (int m = 0; m < 8; m++)
                kvb[dd][m] = r[(tx + 16 * m) * RS + db * 4 + dd];
        #pragma unroll
        for (int i = 0; i < 8; i++) {
            float qv[4];
            #pragma unroll
            for (int dd = 0; dd < 4; dd++) qv[dd] = r[(ty * 8 + i) * RS + db * 4 + dd];
            float pb[8];
            #pragma unroll
            for (int m = 0; m < 8; m++) {
                float p = qv[0] * kvb[0][m];
                p = fmaf(qv[1], kvb[1][m], p);
                p = fmaf(qv[2], kvb[2][m], p);
                p = fmaf(qv[3], kvb[3][m], p);
                pb[m] = p;
            }
            #pragma unroll
            for (int m = 0; m < 8; m++) KAHAN(acc[i][m], cmp[i][m], pb[m]);
        }
    }
    #pragma unroll
    for (int i = 0; i < 8; i++) {
        int row = ty * 8 + i; int rp = kpos[row];
        #pragma unroll
        for (int m = 0; m < 8; m++) {
            int col = tx + 16 * m;
            float dv = (acc[i][m] + cmp[i][m]) * inorm[col] * 0.125f;
            if (rp == kpos[col]) dv = -5e4f;
            dots[row * DS + col] = dv;
        }
    }
    __syncthreads();

    if (tid < 64) {
        float mx = -1e30f;
        #pragma unroll 8
        for (int j2 = 0; j2 < 128; j2++) mx = fmaxf(mx, dots[tid * DS + j2]);
        float s = 0.f;
        #pragma unroll 8
        for (int j2 = 0; j2 < 128; j2++) s += expf(dots[tid * DS + j2] - mx);
        float lg = mx + logf(s);
        logit[tid] = lg;
        lgg[((size_t)bh * NH + qh[tid]) * T_ + kpos[tid]] = lg;
    }
    __syncthreads();
    for (int it = 0; it < 64; it++) {
        int idx = it * 128 + tid; int i = idx >> 7, j2 = idx & 127;
        dots[i * DS + j2] = expf(dots[i * DS + j2] - logit[i]);
    }
    __syncthreads();

    float a2[8][4], c2[8][4];
    #pragma unroll
    for (int i = 0; i < 8; i++)
        #pragma unroll
        for (int m = 0; m < 4; m++) { a2[i][m] = 0.f; c2[i][m] = 0.f; }
    for (int jb = 0; jb < 32; jb++) {
        float vwb[4][4];
        #pragma unroll
        for (int dd = 0; dd < 4; dd++)
            #pragma unroll
            for (int m = 0; m < 4; m++)
                vwb[dd][m] = vv[(((jb * 4 + dd)) << 6) + tx + 16 * m];
        #pragma unroll
        for (int i = 0; i < 8; i++) {
            float pv[4];
            #pragma unroll
            for (int dd = 0; dd < 4; dd++) pv[dd] = dots[(ty * 8 + i) * DS + jb * 4 + dd];
            float pb[4];
            #pragma unroll
            for (int m = 0; m < 4; m++) {
                float p = pv[0] * vwb[0][m];
                p = fmaf(pv[1], vwb[1][m], p);
                p = fmaf(pv[2], vwb[2][m], p);
                p = fmaf(pv[3], vwb[3][m], p);
                pb[m] = p;
            }
            #pragma unroll
            for (int m = 0; m < 4; m++) KAHAN(a2[i][m], c2[i][m], pb[m]);
        }
    }
    #pragma unroll
    for (int i = 0; i < 8; i++) {
        int row = ty * 8 + i;
        size_t base = (((size_t)bh * NH + qh[row]) * T_ + kpos[row]) << 6;
        #pragma unroll
        for (int m = 0; m < 4; m++) og[base + tx + 16 * m] = a2[i][m] + c2[i][m];
    }
}

// ------------------------- combine hash rounds ------------------------------
__global__ __launch_bounds__(64) void combine_kernel(
    const float* __restrict__ og, const float* __restrict__ lgg, float* __restrict__ at)
{
    __shared__ float w[8];
    int bh = blockIdx.x >> 11, pos = blockIdx.x & 2047;
    int tid = threadIdx.x;
    if (tid == 0) {
        float v[8]; float mx = -1e30f;
        #pragma unroll
        for (int h = 0; h < 8; h++) {
            v[h] = lgg[((size_t)bh * NH + h) * T_ + pos];
            mx = fmaxf(mx, v[h]);
        }
        float s = 0.f;
        #pragma unroll
        for (int h = 0; h < 8; h++) { v[h] = expf(v[h] - mx); s += v[h]; }
        float is = 1.f / s;
        #pragma unroll
        for (int h = 0; h < 8; h++) w[h] = v[h] * is;
    }
    __syncthreads();
    float acc = 0.f, cc = 0.f;
    #pragma unroll
    for (int h = 0; h < 8; h++) {
        float p = w[h] * og[(((size_t)bh * NH + h) * T_ + pos) * 64 + tid];
        KAHAN(acc, cc, p);
    }
    int b = bh >> 3, hd = bh & 7;
    at[((size_t)(b * T_ + pos)) * DIM + hd * 64 + tid] = acc + cc;
}

// ------------------------- frontend helpers ---------------------------------
__global__ void wt_kernel(const float* __restrict__ w, float* __restrict__ wT)
{
    int idx = blockIdx.x * 256 + threadIdx.x;
    int c = idx / DIM, o2 = idx - c * DIM;
    wT[idx] = (c < 687) ? w[(size_t)o2 * 687 + c] : 0.f;
}

__global__ void im2col_kernel(const float* __restrict__ spec, float* __restrict__ im)
{
    int idx = blockIdx.x * 256 + threadIdx.x;
    int row = idx / KC, c = idx - row * KC;
    int b = row >> 11, t = row & 2047;
    float val = 0.f;
    if (c < 687) {
        int i = c / 3, k = c - i * 3;
        int tt = t + k - 1;
        if (tt >= 0 && tt < T_) val = spec[((size_t)b * T_ + tt) * 229 + i];
    }
    im[idx] = val;
}

__global__ void pe_kernel(float* __restrict__ x1, float* __restrict__ x2,
                          const float* __restrict__ per, const float* __restrict__ pec)
{
    int idx = blockIdx.x * 256 + threadIdx.x;
    int c = idx & 511;
    int t = (idx >> 9) & 2047;
    float p = (c < 256) ? per[(t >> 6) * 256 + c] : pec[(t & 63) * 256 + (c - 256)];
    float v = x1[idx] + p;
    x1[idx] = v; x2[idx] = v;
}

__global__ void avg_kernel(const float* __restrict__ a, const float* __restrict__ b,
                           float* __restrict__ y)
{
    int idx = blockIdx.x * 256 + threadIdx.x;
    y[idx] = 0.5f * (a[idx] + b[idx]);
}

// ------------------------- driver -------------------------------------------
extern "C" void kernel_launch(void* const* d_in, const int* in_sizes, int n_in,
                              void* d_out, int out_size)
{
    const float* spec   = (const float*)d_in[0];
    const float* conv_w = (const float*)d_in[1];
    const float* conv_b = (const float*)d_in[2];
    const float* pe_row = (const float*)d_in[3];
    const float* pe_col = (const float*)d_in[4];
    const float* lnA_g  = (const float*)d_in[5];
    const float* lnA_b  = (const float*)d_in[6];
    const float* wqk    = (const float*)d_in[7];
    const float* wv     = (const float*)d_in[8];
    const float* wo     = (const float*)d_in[9];
    const float* bo     = (const float*)d_in[10];
    const float* lnF_g  = (const float*)d_in[11];
    const float* lnF_b  = (const float*)d_in[12];
    const float* w1     = (const float*)d_in[13];
    const float* b1     = (const float*)d_in[14];
    const float* w2     = (const float*)d_in[15];
    const float* b2     = (const float*)d_in[16];
    const float* lin_w  = (const float*)d_in[17];
    const float* lin_b  = (const float*)d_in[18];
    const float* rot    = (const float*)d_in[19];
    float* out = (float*)d_out;

    float *x1, *x2, *tmp, *qk, *v, *at, *im, *wT, *o, *lg;
    int *bk, *st;
    __nv_bfloat16 *a0, *a1, *a2, *f0, *f1, *f2, *bt0, *bt1, *bt2;
    cudaGetSymbolAddress((void**)&x1, g_x1);
    cudaGetSymbolAddress((void**)&x2, g_x2);
    cudaGetSymbolAddress((void**)&tmp, g_tmp);
    cudaGetSymbolAddress((void**)&qk, g_qk);
    cudaGetSymbolAddress((void**)&v,  g_v);
    cudaGetSymbolAddress((void**)&at, g_at);
    cudaGetSymbolAddress((void**)&im, g_im);
    cudaGetSymbolAddress((void**)&wT, g_wT);
    cudaGetSymbolAddress((void**)&o,  g_o);
    cudaGetSymbolAddress((void**)&lg, g_lg);
    cudaGetSymbolAddress((void**)&bk, g_bk);
    cudaGetSymbolAddress((void**)&st, g_st);
    cudaGetSymbolAddress((void**)&a0, g_a0);
    cudaGetSymbolAddress((void**)&a1, g_a1);
    cudaGetSymbolAddress((void**)&a2, g_a2);
    cudaGetSymbolAddress((void**)&f0, g_f0);
    cudaGetSymbolAddress((void**)&f1, g_f1);
    cudaGetSymbolAddress((void**)&f2, g_f2);
    cudaGetSymbolAddress((void**)&bt0, g_bt0);
    cudaGetSymbolAddress((void**)&bt1, g_bt1);
    cudaGetSymbolAddress((void**)&bt2, g_bt2);

    size_t asmem = (size_t)(128 * RS + 128 * 64 + 64 * DS + 128 + 64 + 128 + 64) * 4;
    cudaFuncSetAttribute(attn_kernel, cudaFuncAttributeMaxDynamicSharedMemorySize, (int)asmem);
    cudaFuncSetAttribute(tgemm, cudaFuncAttributeMaxDynamicSharedMemorySize, TG_SMEM);

    // frontend
    wt_kernel<<<(KC * DIM) / 256, 256>>>(conv_w, wT);
    im2col_kernel<<<(BT * KC) / 256, 256>>>(spec, im);
    sgemm<<<dim3(DIM / 64, BT / 128), 256>>>(im, wT, conv_b, x1, BT, DIM, KC, 1);
    pe_kernel<<<(BT * DIM) / 256, 256>>>(x1, x2, pe_row, pe_col);

    const int nA = BT * DIM;
    for (int i = 0; i < 8; i++) {
        ln_kernel<<<BT, 256>>>(x2, lnA_g + i * DIM, lnA_b + i * DIM, tmp);
        // QKV (fused dual output, heads layout)
        cvt3a_kernel<<<(nA + 255) / 256, 256>>>(tmp, nA, a0, a1, a2);
        cvt3b_kernel<<<(DIM * DIM + 255) / 256, 256>>>(wqk + (size_t)i * DIM * DIM, DIM, DIM, 0, bt0, bt1, bt2);
        cvt3b_kernel<<<(DIM * DIM + 255) / 256, 256>>>(wv + (size_t)i * DIM * DIM, DIM, DIM, DIM, bt0, bt1, bt2);
        tgemm<<<dim3(16, 32), 256, TG_SMEM>>>(a0, a1, a2, bt0, bt1, bt2,
                                              nullptr, nullptr, qk, v,
                                              nullptr, nullptr, nullptr, DIM, DIM, 0, 1, DIM);
        hash_kernel<<<BH * (T_ / TCH), 128>>>(qk, rot + (size_t)i * 64 * 128, bk);
        sort_kernel<<<BH, 256>>>(bk, st);
        attn_kernel<<<BH * NCH, 128, asmem>>>(qk, v, st, o, lg);
        combine_kernel<<<BH * T_, 64>>>(o, lg, at);
        // O projection + residual into x1
        cvt3a_kernel<<<(nA + 255) / 256, 256>>>(at, nA, a0, a1, a2);
        cvt3b_kernel<<<(DIM * DIM + 255) / 256, 256>>>(wo + (size_t)i * DIM * DIM, DIM, DIM, 0, bt0, bt1, bt2);
        tgemm<<<dim3(8, 32), 256, TG_SMEM>>>(a0, a1, a2, bt0, bt1, bt2,
                                             bo + i * DIM, x1, x1, nullptr,
                                             nullptr, nullptr, nullptr, DIM, DIM, 0, 0, 0);
        ln_kernel<<<BT, 256>>>(x1, lnF_g + i * DIM, lnF_b + i * DIM, tmp);
        // FFN1 (gelu) -> bf16x3 splits into DISJOINT f0/f1/f2
        cvt3a_kernel<<<(nA + 255) / 256, 256>>>(tmp, nA, a0, a1, a2);
        cvt3b_kernel<<<(DIM * FF + 255) / 256, 256>>>(w1 + (size_t)i * DIM * FF, DIM, FF, 0, bt0, bt1, bt2);
        tgemm<<<dim3(32, 32), 256, TG_SMEM>>>(a0, a1, a2, bt0, bt1, bt2,
                                              b1 + i * FF, nullptr, nullptr, nullptr,
                                              f0, f1, f2, DIM, FF, 2, 0, 0);
        // FFN2 (+ residual into x2): A splits in f0/f1/f2
        cvt3b_kernel<<<(FF * DIM + 255) / 256, 256>>>(w2 + (size_t)i * FF * DIM, FF, DIM, 0, bt0, bt1, bt2);
        tgemm<<<dim3(8, 32), 256, TG_SMEM>>>(f0, f1, f2, bt0, bt1, bt2,
                                             b2 + i * DIM, x2, x2, nullptr,
                                             nullptr, nullptr, nullptr, FF, DIM, 0, 0, 0);
    }

    avg_kernel<<<(BT * DIM) / 256, 256>>>(x1, x2, tmp);
    sgemm<<<dim3(2, 32), 256>>>(tmp, lin_w, lin_b, out, BT, 88, DIM, 0);
}

// round 13
// speedup vs baseline: 1.9022x; 1.1187x over previous
#include <cuda_runtime.h>
#include <cuda_bf16.h>
#include <math.h>
#include <stdint.h>

#define B_   2
#define T_   2048
#define BT   4096
#define DIM  512
#define H_   8
#define DH   64
#define NH   8
#define NB   32
#define NCH  256
#define BH   16
#define NHT  16384
#define KC   704
#define FF   2048

#define KAHAN(s, c, p) { float y_ = (p) - (c); float t_ = (s) + y_; (c) = (t_ - (s)) - y_; (s) = t_; }

// ------------------------- scratch (static device) -------------------------
__device__ float g_x1[BT*DIM];
__device__ float g_x2[BT*DIM];
__device__ float g_tmp[BT*DIM];
__device__ float g_qk[BT*DIM];
__device__ float g_v [BT*DIM];
__device__ float g_at[BT*DIM];
__device__ float g_im[BT*KC];
__device__ float g_wT[KC*DIM];
__device__ int   g_bk[BH*NHT];
__device__ int   g_st[BH*NHT];
__device__ float g_o [BH*NHT*DH];
__device__ float g_lg[BH*NHT];
// bf16 split buffers (activations: a* DIM-wide, f* FFN hidden)
__device__ __nv_bfloat16 g_a0[BT*DIM];
__device__ __nv_bfloat16 g_a1[BT*DIM];
__device__ __nv_bfloat16 g_a2[BT*DIM];
__device__ __nv_bfloat16 g_f0[BT*FF];
__device__ __nv_bfloat16 g_f1[BT*FF];
__device__ __nv_bfloat16 g_f2[BT*FF];
__device__ __nv_bfloat16 g_bt0[2*1024*1024];
__device__ __nv_bfloat16 g_bt1[2*1024*1024];
__device__ __nv_bfloat16 g_bt2[2*1024*1024];

// ------------------------- warp-mma helpers ---------------------------------
__device__ __forceinline__ uint32_t smem_u32(const void* p) {
    uint32_t a;
    asm("{ .reg .u64 t; cvta.to.shared.u64 t, %1; cvt.u32.u64 %0, t; }" : "=r"(a) : "l"(p));
    return a;
}
__device__ __forceinline__ void ldsm_x4(uint32_t* r, uint32_t addr) {
    asm volatile("ldmatrix.sync.aligned.m8n8.x4.shared.b16 {%0,%1,%2,%3}, [%4];"
        : "=r"(r[0]), "=r"(r[1]), "=r"(r[2]), "=r"(r[3]) : "r"(addr));
}
__device__ __forceinline__ void ldsm_x2(uint32_t* r, uint32_t addr) {
    asm volatile("ldmatrix.sync.aligned.m8n8.x2.shared.b16 {%0,%1}, [%2];"
        : "=r"(r[0]), "=r"(r[1]) : "r"(addr));
}
__device__ __forceinline__ void mma_bf16(float* d, const uint32_t* a, const uint32_t* b) {
    asm volatile("mma.sync.aligned.m16n8k16.row.col.f32.bf16.bf16.f32 "
        "{%0,%1,%2,%3}, {%4,%5,%6,%7}, {%8,%9}, {%0,%1,%2,%3};"
        : "+f"(d[0]), "+f"(d[1]), "+f"(d[2]), "+f"(d[3])
        : "r"(a[0]), "r"(a[1]), "r"(a[2]), "r"(a[3]), "r"(b[0]), "r"(b[1]));
}
__device__ __forceinline__ void cp16(uint32_t dst, const void* src) {
    size_t g = (size_t)__cvta_generic_to_global(src);
    asm volatile("cp.async.cg.shared.global [%0], [%1], 16;" :: "r"(dst), "l"(g));
}

// ------------------------- fp32 -> bf16x3 conversions -----------------------
__device__ __forceinline__ void split3(float v, __nv_bfloat16& b0, __nv_bfloat16& b1,
                                       __nv_bfloat16& b2) {
    b0 = __float2bfloat16(v);
    float r = v - __bfloat162float(b0);
    b1 = __float2bfloat16(r);
    float r2 = r - __bfloat162float(b1);
    b2 = __float2bfloat16(r2);
}
__global__ void cvt3a_kernel(const float* __restrict__ src, int n,
                             __nv_bfloat16* __restrict__ d0, __nv_bfloat16* __restrict__ d1,
                             __nv_bfloat16* __restrict__ d2)
{
    int i = blockIdx.x * 256 + threadIdx.x;
    if (i >= n) return;
    __nv_bfloat16 b0, b1, b2;
    split3(src[i], b0, b1, b2);
    d0[i] = b0; d1[i] = b1; d2[i] = b2;
}
// W [K, N] fp32 -> Bt splits [rowoff+N, K] bf16 (transposed)
__global__ void cvt3b_kernel(const float* __restrict__ W, int Kd, int Nd, int rowoff,
                             __nv_bfloat16* __restrict__ d0, __nv_bfloat16* __restrict__ d1,
                             __nv_bfloat16* __restrict__ d2)
{
    int i = blockIdx.x * 256 + threadIdx.x;
    if (i >= Kd * Nd) return;
    int nrow = i / Kd, k = i - nrow * Kd;
    __nv_bfloat16 b0, b1, b2;
    split3(W[(size_t)k * Nd + nrow], b0, b1, b2);
    size_t o = (size_t)(rowoff + nrow) * Kd + k;
    d0[o] = b0; d1[o] = b1; d2[o] = b2;
}

// ------------------------- tensor-core bf16x3 GEMM --------------------------
// BM=128, BN=64, BK=32 per stage, 3-stage cp.async pipeline, ONE sync/chunk.
// 256 threads (8 warps, each 32x32). 6 significant cross-products, fp32 mma
// accum, Kahan merge once per 32-k chunk (bit-identical order to prior round).
#define ASTRIDE 40
#define ABYTES (3 * 128 * ASTRIDE * 2)
#define BBYTES (3 * 64 * ASTRIDE * 2)
#define STAGEB (ABYTES + BBYTES)
#define TG_SMEM (3 * STAGEB)
__global__ __launch_bounds__(256) void tgemm(
    const __nv_bfloat16* __restrict__ a0, const __nv_bfloat16* __restrict__ a1,
    const __nv_bfloat16* __restrict__ a2,
    const __nv_bfloat16* __restrict__ bt0, const __nv_bfloat16* __restrict__ bt1,
    const __nv_bfloat16* __restrict__ bt2,
    const float* __restrict__ bias, const float* __restrict__ resid,
    float* __restrict__ C, float* __restrict__ C2,
    __nv_bfloat16* __restrict__ s0, __nv_bfloat16* __restrict__ s1,
    __nv_bfloat16* __restrict__ s2,
    int K, int Nout, int act, int heads, int Nsplit)
{
    extern __shared__ char smem[];
    const int tid = threadIdx.x;
    const int L = tid & 31, w = tid >> 5;
    const int mrow0 = (w & 3) * 32, ncol0 = (w >> 2) * 32;
    const int m0 = blockIdx.y * 128;
    const int n0 = blockIdx.x * 64;

    const uint32_t base = smem_u32(smem);
    const int arow = (L & 7) + ((L >> 3) & 1) * 8;
    const int acol = (L >> 4) * 8;
    const int brow = L & 7, bcol = ((L >> 3) & 1) * 8;

    const __nv_bfloat16* asp[3] = {a0, a1, a2};
    const __nv_bfloat16* bsp[3] = {bt0, bt1, bt2};

    // A: 1536 cp16 (3sp x 128row x 4seg), B: 768 cp16 (3sp x 64row x 4seg)
#define ISSUE_CHUNK(c, buf) do { \
    const int k0_ = (c) << 5; \
    const uint32_t sA_ = base + (buf) * STAGEB; \
    const uint32_t sB_ = sA_ + ABYTES; \
    _Pragma("unroll") \
    for (int it = 0; it < 6; it++) { \
        int idx = tid + it * 256; \
        int sp = idx >> 9, rem = idx & 511; \
        int row = rem >> 2, seg = rem & 3; \
        uint32_t dst = sA_ + ((sp * (128 * ASTRIDE) + row * ASTRIDE + seg * 8) << 1); \
        cp16(dst, asp[sp] + (size_t)(m0 + row) * K + k0_ + seg * 8); \
    } \
    _Pragma("unroll") \
    for (int it = 0; it < 3; it++) { \
        int idx = tid + it * 256; \
        int sp = idx >> 8, rem = idx & 255; \
        int row = rem >> 2, seg = rem & 3; \
        uint32_t dst = sB_ + ((sp * (64 * ASTRIDE) + row * ASTRIDE + seg * 8) << 1); \
        cp16(dst, bsp[sp] + (size_t)(n0 + row) * K + k0_ + seg * 8); \
    } \
    asm volatile("cp.async.commit_group;" ::: "memory"); \
} while (0)

    float acc[32], macc[32], mcmp[32];
    #pragma unroll
    for (int i = 0; i < 32; i++) { acc[i] = 0.f; macc[i] = 0.f; mcmp[i] = 0.f; }

    const int nch = K >> 5;
    ISSUE_CHUNK(0, 0);
    if (nch > 1) ISSUE_CHUNK(1, 1);

    for (int c = 0; c < nch; c++) {
        const int buf = c % 3;
        if (c + 1 < nch) asm volatile("cp.async.wait_group 1;" ::: "memory");
        else             asm volatile("cp.async.wait_group 0;" ::: "memory");
        __syncthreads();

        const uint32_t Ab = base + buf * STAGEB;
        const uint32_t Bb = Ab + ABYTES;

        #pragma unroll
        for (int ks = 0; ks < 2; ks++) {
            const int kof = ks * 16;
            uint32_t afr[3][2][4];
            #pragma unroll
            for (int sp = 0; sp < 3; sp++)
                #pragma unroll
                for (int mt = 0; mt < 2; mt++)
                    ldsm_x4(afr[sp][mt],
                            Ab + ((sp * (128 * ASTRIDE) + (mrow0 + mt * 16 + arow) * ASTRIDE
                                   + kof + acol) << 1));
            #pragma unroll
            for (int bj = 0; bj < 3; bj++) {
                uint32_t bfr[4][2];
                #pragma unroll
                for (int nt = 0; nt < 4; nt++)
                    ldsm_x2(bfr[nt],
                            Bb + ((bj * (64 * ASTRIDE) + (ncol0 + nt * 8 + brow) * ASTRIDE
                                   + kof + bcol) << 1));
                #pragma unroll
                for (int ai = 0; ai < 3; ai++) {
                    if (ai + bj > 2) break;
                    #pragma unroll
                    for (int mt = 0; mt < 2; mt++)
                        #pragma unroll
                        for (int nt = 0; nt < 4; nt++)
                            mma_bf16(&acc[(mt * 4 + nt) * 4], afr[ai][mt], bfr[nt]);
                }
            }
        }

        #pragma unroll
        for (int i = 0; i < 32; i++) {
            KAHAN(macc[i], mcmp[i], acc[i]);
            acc[i] = 0.f;
        }

        if (c + 2 < nch) ISSUE_CHUNK(c + 2, (c + 2) % 3);
    }

    // ------------- epilogue -------------
    int n0c = n0;
    float* Co = C;
    if (Nsplit && n0c >= Nsplit) { Co = C2; n0c -= Nsplit; }
    #pragma unroll
    for (int mt = 0; mt < 2; mt++)
        #pragma unroll
        for (int nt = 0; nt < 4; nt++)
            #pragma unroll
            for (int r = 0; r < 4; r++) {
                int i = (mt * 4 + nt) * 4 + r;
                float v = macc[i] + mcmp[i];
                int row = m0 + mrow0 + mt * 16 + (L >> 2) + ((r >> 1) * 8);
                int col = n0c + ncol0 + nt * 8 + ((L & 3) * 2) + (r & 1);
                if (bias) v += bias[col];
                if (act == 2) v = 0.5f * v * (1.f + erff(v * 0.70710678118654752f));
                if (resid) v += resid[(size_t)row * Nout + col];
                if (s0) {
                    __nv_bfloat16 b0, b1, b2;
                    split3(v, b0, b1, b2);
                    size_t o = (size_t)row * Nout + col;
                    s0[o] = b0; s1[o] = b1; s2[o] = b2;
                } else if (heads) {
                    int b = row >> 11, t = row & 2047;
                    int h = col >> 6, d = col & 63;
                    Co[((((size_t)b * H_ + h) * T_ + t) << 6) + d] = v;
                } else {
                    Co[(size_t)row * Nout + col] = v;
                }
            }
}

// ------------------------- scalar SGEMM (conv + final head) -----------------
__global__ __launch_bounds__(256) void sgemm(
    const float* __restrict__ A, const float* __restrict__ Bm,
    const float* __restrict__ bias, float* __restrict__ C,
    int M, int N, int K, int act)
{
    __shared__ float As[16][132];
    __shared__ float Bs[16][64];
    const int tid = threadIdx.x;
    const int tx = tid & 15, ty = tid >> 4;
    const int m0 = blockIdx.y * 128;
    int n0 = blockIdx.x * 64;

    float acc[8][4], cmp[8][4];
    #pragma unroll
    for (int i = 0; i < 8; i++)
        #pragma unroll
        for (int j = 0; j < 4; j++) { acc[i][j] = 0.f; cmp[i][j] = 0.f; }

    const int arow0 = tid >> 2, ac4 = (tid & 3) * 4;
    const int brow = tid >> 4, bc4 = (tid & 15) * 4;
    const int bcol = n0 + bc4;

    for (int k0 = 0; k0 < K; k0 += 16) {
        #pragma unroll
        for (int s = 0; s < 2; s++) {
            int row = arow0 + s * 64;
            float4 a = *(const float4*)(A + (size_t)(m0 + row) * K + k0 + ac4);
            As[ac4 + 0][row] = a.x; As[ac4 + 1][row] = a.y;
            As[ac4 + 2][row] = a.z; As[ac4 + 3][row] = a.w;
        }
        float4 bv;
        if (bcol < N) bv = *(const float4*)(Bm + (size_t)(k0 + brow) * N + bcol);
        else          bv = make_float4(0.f, 0.f, 0.f, 0.f);
        *(float4*)(&Bs[brow][bc4]) = bv;
        __syncthreads();
        float pb[8][4];
        #pragma unroll
        for (int kk = 0; kk < 16; kk++) {
            float4 a0 = *(const float4*)(&As[kk][ty * 8]);
            float4 a1 = *(const float4*)(&As[kk][ty * 8 + 4]);
            float4 bb = *(const float4*)(&Bs[kk][tx * 4]);
            float av[8] = {a0.x, a0.y, a0.z, a0.w, a1.x, a1.y, a1.z, a1.w};
            float bw[4] = {bb.x, bb.y, bb.z, bb.w};
            if (kk == 0) {
                #pragma unroll
                for (int i = 0; i < 8; i++)
                    #pragma unroll
                    for (int j = 0; j < 4; j++) pb[i][j] = av[i] * bw[j];
            } else {
                #pragma unroll
                for (int i = 0; i < 8; i++)
                    #pragma unroll
                    for (int j = 0; j < 4; j++) pb[i][j] = fmaf(av[i], bw[j], pb[i][j]);
            }
        }
        #pragma unroll
        for (int i = 0; i < 8; i++)
            #pragma unroll
            for (int j = 0; j < 4; j++) KAHAN(acc[i][j], cmp[i][j], pb[i][j]);
        __syncthreads();
    }

    #pragma unroll
    for (int i = 0; i < 8; i++) {
        int row = m0 + ty * 8 + i;
        #pragma unroll
        for (int j = 0; j < 4; j++) {
            int col = n0 + tx * 4 + j;
            if (col >= N) continue;
            float v = acc[i][j] + cmp[i][j];
            if (bias) v += bias[col];
            if (act == 1) v = fmaxf(v, 0.f);
            C[(size_t)row * N + col] = v;
        }
    }
}

// ------------------------- LayerNorm ----------------------------------------
__global__ __launch_bounds__(256) void ln_kernel(
    const float* __restrict__ x, const float* __restrict__ g,
    const float* __restrict__ bb, float* __restrict__ y)
{
    __shared__ float sh[8];
    int row = blockIdx.x, tid = threadIdx.x;
    const float* xr = x + (size_t)row * DIM;
    float v0 = xr[tid], v1 = xr[tid + 256];
    float s = v0 + v1;
    #pragma unroll
    for (int o = 16; o; o >>= 1) s += __shfl_down_sync(0xffffffffu, s, o);
    if ((tid & 31) == 0) sh[tid >> 5] = s;
    __syncthreads();
    if (tid < 32) {
        float t = (tid < 8) ? sh[tid] : 0.f;
        #pragma unroll
        for (int o = 4; o; o >>= 1) t += __shfl_down_sync(0xffffffffu, t, o);
        if (tid == 0) sh[0] = t;
    }
    __syncthreads();
    float mean = sh[0] * (1.f / DIM);
    __syncthreads();
    float d0 = v0 - mean, d1 = v1 - mean;
    float s2 = d0 * d0 + d1 * d1;
    #pragma unroll
    for (int o = 16; o; o >>= 1) s2 += __shfl_down_sync(0xffffffffu, s2, o);
    if ((tid & 31) == 0) sh[tid >> 5] = s2;
    __syncthreads();
    if (tid < 32) {
        float t = (tid < 8) ? sh[tid] : 0.f;
        #pragma unroll
        for (int o = 4; o; o >>= 1) t += __shfl_down_sync(0xffffffffu, t, o);
        if (tid == 0) sh[0] = t;
    }
    __syncthreads();
    float inv = 1.f / sqrtf(sh[0] * (1.f / DIM) + 1e-5f);
    float* yr = y + (size_t)row * DIM;
    yr[tid]       = d0 * inv * g[tid]       + bb[tid];
    yr[tid + 256] = d1 * inv * g[tid + 256] + bb[tid + 256];
}

// ------------------------- LSH hashing --------------------------------------
#define TCH 16
__global__ __launch_bounds__(128) void hash_kernel(
    const float* __restrict__ qk, const float* __restrict__ rot, int* __restrict__ bkt)
{
    __shared__ float q[4][DH];
    int blk = blockIdx.x;
    int bh = blk / (T_ / TCH);
    int t0 = (blk % (T_ / TCH)) * TCH;
    int tid = threadIdx.x;
    int h = tid >> 4, j = tid & 15;
    float rv[64];
    #pragma unroll
    for (int f = 0; f < 64; f++) rv[f] = rot[f * 128 + h * 16 + j];

    for (int tg = 0; tg < TCH; tg += 4) {
        __syncthreads();
        for (int idx = tid; idx < 4 * DH; idx += 128) {
            int r = idx >> 6, d = idx & 63;
            q[r][d] = qk[((size_t)bh * T_ + t0 + tg + r) * DH + d];
        }
        __syncthreads();
        float a0 = 0.f, a1 = 0.f, a2 = 0.f, a3 = 0.f;
        float c0 = 0.f, c1 = 0.f, c2 = 0.f, c3 = 0.f;
        #pragma unroll
        for (int f = 0; f < 64; f++) {
            float r = rv[f];
            float p0 = q[0][f] * r; KAHAN(a0, c0, p0);
            float p1 = q[1][f] * r; KAHAN(a1, c1, p1);
            float p2 = q[2][f] * r; KAHAN(a2, c2, p2);
            float p3 = q[3][f] * r; KAHAN(a3, c3, p3);
        }
        float vals[4] = {a0 + c0, a1 + c1, a2 + c2, a3 + c3};
        #pragma unroll
        for (int r = 0; r < 4; r++) {
            float v = vals[r]; int idx = j;
            float nv = -v;
            if (nv > v) { v = nv; idx = j + 16; }
            #pragma unroll
            for (int o = 8; o; o >>= 1) {
                float ov = __shfl_down_sync(0xffffffffu, v, o, 16);
                int   oi = __shfl_down_sync(0xffffffffu, idx, o, 16);
                if (ov > v || (ov == v && oi < idx)) { v = ov; idx = oi; }
            }
            if (j == 0) bkt[(size_t)bh * NHT + h * T_ + t0 + tg + r] = idx + h * NB;
        }
    }
}

// ------------------------- stable counting sort ------------------------------
__global__ __launch_bounds__(256) void sort_kernel(
    const int* __restrict__ bkt, int* __restrict__ st)
{
    __shared__ int hist[256];
    __shared__ int off[256];
    int bh = blockIdx.x, tid = threadIdx.x;
    const int* bb = bkt + (size_t)bh * NHT;
    hist[tid] = 0;
    __syncthreads();
    for (int i = tid; i < NHT; i += 256) atomicAdd(&hist[bb[i]], 1);
    __syncthreads();
    if (tid == 0) {
        int s = 0;
        for (int i = 0; i < 256; i++) { off[i] = s; s += hist[i]; }
    }
    __syncthreads();
    int beta = tid, h = tid >> 5;
    int o = off[beta];
    int* out2 = st + (size_t)bh * NHT;
    int base = h * T_;
    for (int k = 0; k < T_; k++)
        if (bb[base + k] == beta) out2[o++] = base + k;
}

// ------------------------- chunked LSH attention ----------------------------
#define RS 68
#define DS 129
__global__ __launch_bounds__(128) void attn_kernel(
    const float* __restrict__ qk, const float* __restrict__ vg,
    const int* __restrict__ st, float* __restrict__ og, float* __restrict__ lgg)
{
    extern __shared__ float sm[];
    float* r     = sm;
    float* vv    = r + 128 * RS;
    float* dots  = vv + 128 * 64;
    float* inorm = dots + 64 * DS;
    float* logit = inorm + 128;
    int*   kpos  = (int*)(logit + 64);
    int*   qh    = kpos + 128;

    int tid = threadIdx.x;
    int bh = blockIdx.x >> 8, c = blockIdx.x & 255;
    int cp = (c + NCH - 1) & 255;

    {
        int lc = (tid < 64) ? c : cp;
        int tk = st[(size_t)bh * NHT + lc * 64 + (tid & 63)];
        kpos[tid] = tk & (T_ - 1);
        if (tid < 64) qh[tid] = tk >> 11;
    }
    __syncthreads();

    const float* qb = qk + ((size_t)bh << 17);
    const float* vb = vg + ((size_t)bh << 17);
    for (int it = 0; it < 64; it++) {
        int idx = it * 128 + tid;
        int jj = idx >> 6, d = idx & 63;
        int pos = kpos[jj];
        r[jj * RS + d]    = qb[(pos << 6) + d];
        vv[(jj << 6) + d] = vb[(pos << 6) + d];
    }
    __syncthreads();
    {
        float s = 0.f, cs = 0.f;
        #pragma unroll 8
        for (int d = 0; d < 64; d++) {
            float x = r[tid * RS + d];
            float p = x * x; KAHAN(s, cs, p);
        }
        inorm[tid] = 1.f / fmaxf(sqrtf(s + cs), 1e-12f);
    }
    __syncthreads();

    int tx = tid & 15, ty = tid >> 4;
    float acc[8][8], cmp[8][8];
    #pragma unroll
    for (int i = 0; i < 8; i++)
        #pragma unroll
        for (int m = 0; m < 8; m++) { acc[i][m] = 0.f; cmp[i][m] = 0.f; }

    for (int db = 0; db < 16; db++) {
        float kvb[4][8];
        #pragma unroll
        for (int dd = 0; dd < 4; dd++)
            #pragma unroll
            for (int m = 0; m < 8; m++)
                kvb[dd][m] = r[(tx + 16 * m) * RS + db * 4 + dd];
        #pragma unroll
        for (int i = 0; i < 8; i++) {
            float qv[4];
            #pragma unroll
            for (int dd = 0; dd < 4; dd++) qv[dd] = r[(ty * 8 + i) * RS + db * 4 + dd];
            float pb[8];
            #pragma unroll
            for (int m = 0; m < 8; m++) {
                float p = qv[0] * kvb[0][m];
                p = fmaf(qv[1], kvb[1][m], p);
                p = fmaf(qv[2], kvb[2][m], p);
                p = fmaf(qv[3], kvb[3][m], p);
                pb[m] = p;
            }
            #pragma unroll
            for (int m = 0; m < 8; m++) KAHAN(acc[i][m], cmp[i][m], pb[m]);
        }
    }
    #pragma unroll
    for (int i = 0; i < 8; i++) {
        int row = ty * 8 + i; int rp = kpos[row];
        #pragma unroll
        for (int m = 0; m < 8; m++) {
            int col = tx + 16 * m;
            float dv = (acc[i][m] + cmp[i][m]) * inorm[col] * 0.125f;
            if (rp == kpos[col]) dv = -5e4f;
            dots[row * DS + col] = dv;
        }
    }
    __syncthreads();

    if (tid < 64) {
        float mx = -1e30f;
        #pragma unroll 8
        for (int j2 = 0; j2 < 128; j2++) mx = fmaxf(mx, dots[tid * DS + j2]);
        float s = 0.f;
        #pragma unroll 8
        for (int j2 = 0; j2 < 128; j2++) s += expf(dots[tid * DS + j2] - mx);
        float lg = mx + logf(s);
        logit[tid] = lg;
        lgg[((size_t)bh * NH + qh[tid]) * T_ + kpos[tid]] = lg;
    }
    __syncthreads();
    for (int it = 0; it < 64; it++) {
        int idx = it * 128 + tid; int i = idx >> 7, j2 = idx & 127;
        dots[i * DS + j2] = expf(dots[i * DS + j2] - logit[i]);
    }
    __syncthreads();

    float a2[8][4], c2[8][4];
    #pragma unroll
    for (int i = 0; i < 8; i++)
        #pragma unroll
        for (int m = 0; m < 4; m++) { a2[i][m] = 0.f; c2[i][m] = 0.f; }
    for (int jb = 0; jb < 32; jb++) {
        float vwb[4][4];
        #pragma unroll
        for (int dd = 0; dd < 4; dd++)
            #pragma unroll
            for (int m = 0; m < 4; m++)
                vwb[dd][m] = vv[(((jb * 4 + dd)) << 6) + tx + 16 * m];
        #pragma unroll
        for (int i = 0; i < 8; i++) {
            float pv[4];
            #pragma unroll
            for (int dd = 0; dd < 4; dd++) pv[dd] = dots[(ty * 8 + i) * DS + jb * 4 + dd];
            float pb[4];
            #pragma unroll
            for (int m = 0; m < 4; m++) {
                float p = pv[0] * vwb[0][m];
                p = fmaf(pv[1], vwb[1][m], p);
                p = fmaf(pv[2], vwb[2][m], p);
                p = fmaf(pv[3], vwb[3][m], p);
                pb[m] = p;
            }
            #pragma unroll
            for (int m = 0; m < 4; m++) KAHAN(a2[i][m], c2[i][m], pb[m]);
        }
    }
    #pragma unroll
    for (int i = 0; i < 8; i++) {
        int row = ty * 8 + i;
        size_t base = (((size_t)bh * NH + qh[row]) * T_ + kpos[row]) << 6;
        #pragma unroll
        for (int m = 0; m < 4; m++) og[base + tx + 16 * m] = a2[i][m] + c2[i][m];
    }
}

// ------------------------- combine hash rounds ------------------------------
__global__ __launch_bounds__(64) void combine_kernel(
    const float* __restrict__ og, const float* __restrict__ lgg, float* __restrict__ at)
{
    __shared__ float w[8];
    int bh = blockIdx.x >> 11, pos = blockIdx.x & 2047;
    int tid = threadIdx.x;
    if (tid == 0) {
        float v[8]; float mx = -1e30f;
        #pragma unroll
        for (int h = 0; h < 8; h++) {
            v[h] = lgg[((size_t)bh * NH + h) * T_ + pos];
            mx = fmaxf(mx, v[h]);
        }
        float s = 0.f;
        #pragma unroll
        for (int h = 0; h < 8; h++) { v[h] = expf(v[h] - mx); s += v[h]; }
        float is = 1.f / s;
        #pragma unroll
        for (int h = 0; h < 8; h++) w[h] = v[h] * is;
    }
    __syncthreads();
    float acc = 0.f, cc = 0.f;
    #pragma unroll
    for (int h = 0; h < 8; h++) {
        float p = w[h] * og[(((size_t)bh * NH + h) * T_ + pos) * 64 + tid];
        KAHAN(acc, cc, p);
    }
    int b = bh >> 3, hd = bh & 7;
    at[((size_t)(b * T_ + pos)) * DIM + hd * 64 + tid] = acc + cc;
}

// ------------------------- frontend helpers ---------------------------------
__global__ void wt_kernel(const float* __restrict__ w, float* __restrict__ wT)
{
    int idx = blockIdx.x * 256 + threadIdx.x;
    int c = idx / DIM, o2 = idx - c * DIM;
    wT[idx] = (c < 687) ? w[(size_t)o2 * 687 + c] : 0.f;
}

__global__ void im2col_kernel(const float* __restrict__ spec, float* __restrict__ im)
{
    int idx = blockIdx.x * 256 + threadIdx.x;
    int row = idx / KC, c = idx - row * KC;
    int b = row >> 11, t = row & 2047;
    float val = 0.f;
    if (c < 687) {
        int i = c / 3, k = c - i * 3;
        int tt = t + k - 1;
        if (tt >= 0 && tt < T_) val = spec[((size_t)b * T_ + tt) * 229 + i];
    }
    im[idx] = val;
}

__global__ void pe_kernel(float* __restrict__ x1, float* __restrict__ x2,
                          const float* __restrict__ per, const float* __restrict__ pec)
{
    int idx = blockIdx.x * 256 + threadIdx.x;
    int c = idx & 511;
    int t = (idx >> 9) & 2047;
    float p = (c < 256) ? per[(t >> 6) * 256 + c] : pec[(t & 63) * 256 + (c - 256)];
    float v = x1[idx] + p;
    x1[idx] = v; x2[idx] = v;
}

__global__ void avg_kernel(const float* __restrict__ a, const float* __restrict__ b,
                           float* __restrict__ y)
{
    int idx = blockIdx.x * 256 + threadIdx.x;
    y[idx] = 0.5f * (a[idx] + b[idx]);
}

// ------------------------- driver -------------------------------------------
extern "C" void kernel_launch(void* const* d_in, const int* in_sizes, int n_in,
                              void* d_out, int out_size)
{
    const float* spec   = (const float*)d_in[0];
    const float* conv_w = (const float*)d_in[1];
    const float* conv_b = (const float*)d_in[2];
    const float* pe_row = (const float*)d_in[3];
    const float* pe_col = (const float*)d_in[4];
    const float* lnA_g  = (const float*)d_in[5];
    const float* lnA_b  = (const float*)d_in[6];
    const float* wqk    = (const float*)d_in[7];
    const float* wv     = (const float*)d_in[8];
    const float* wo     = (const float*)d_in[9];
    const float* bo     = (const float*)d_in[10];
    const float* lnF_g  = (const float*)d_in[11];
    const float* lnF_b  = (const float*)d_in[12];
    const float* w1     = (const float*)d_in[13];
    const float* b1     = (const float*)d_in[14];
    const float* w2     = (const float*)d_in[15];
    const float* b2     = (const float*)d_in[16];
    const float* lin_w  = (const float*)d_in[17];
    const float* lin_b  = (const float*)d_in[18];
    const float* rot    = (const float*)d_in[19];
    float* out = (float*)d_out;

    float *x1, *x2, *tmp, *qk, *v, *at, *im, *wT, *o, *lg;
    int *bk, *st;
    __nv_bfloat16 *a0, *a1, *a2, *f0, *f1, *f2, *bt0, *bt1, *bt2;
    cudaGetSymbolAddress((void**)&x1, g_x1);
    cudaGetSymbolAddress((void**)&x2, g_x2);
    cudaGetSymbolAddress((void**)&tmp, g_tmp);
    cudaGetSymbolAddress((void**)&qk, g_qk);
    cudaGetSymbolAddress((void**)&v,  g_v);
    cudaGetSymbolAddress((void**)&at, g_at);
    cudaGetSymbolAddress((void**)&im, g_im);
    cudaGetSymbolAddress((void**)&wT, g_wT);
    cudaGetSymbolAddress((void**)&o,  g_o);
    cudaGetSymbolAddress((void**)&lg, g_lg);
    cudaGetSymbolAddress((void**)&bk, g_bk);
    cudaGetSymbolAddress((void**)&st, g_st);
    cudaGetSymbolAddress((void**)&a0, g_a0);
    cudaGetSymbolAddress((void**)&a1, g_a1);
    cudaGetSymbolAddress((void**)&a2, g_a2);
    cudaGetSymbolAddress((void**)&f0, g_f0);
    cudaGetSymbolAddress((void**)&f1, g_f1);
    cudaGetSymbolAddress((void**)&f2, g_f2);
    cudaGetSymbolAddress((void**)&bt0, g_bt0);
    cudaGetSymbolAddress((void**)&bt1, g_bt1);
    cudaGetSymbolAddress((void**)&bt2, g_bt2);

    size_t asmem = (size_t)(128 * RS + 128 * 64 + 64 * DS + 128 + 64 + 128 + 64) * 4;
    cudaFuncSetAttribute(attn_kernel, cudaFuncAttributeMaxDynamicSharedMemorySize, (int)asmem);
    cudaFuncSetAttribute(tgemm, cudaFuncAttributeMaxDynamicSharedMemorySize, TG_SMEM);

    // frontend
    wt_kernel<<<(KC * DIM) / 256, 256>>>(conv_w, wT);
    im2col_kernel<<<(BT * KC) / 256, 256>>>(spec, im);
    sgemm<<<dim3(DIM / 64, BT / 128), 256>>>(im, wT, conv_b, x1, BT, DIM, KC, 1);
    pe_kernel<<<(BT * DIM) / 256, 256>>>(x1, x2, pe_row, pe_col);

    const int nA = BT * DIM;
    for (int i = 0; i < 8; i++) {
        ln_kernel<<<BT, 256>>>(x2, lnA_g + i * DIM, lnA_b + i * DIM, tmp);
        // QKV (fused dual output, heads layout)
        cvt3a_kernel<<<(nA + 255) / 256, 256>>>(tmp, nA, a0, a1, a2);
        cvt3b_kernel<<<(DIM * DIM + 255) / 256, 256>>>(wqk + (size_t)i * DIM * DIM, DIM, DIM, 0, bt0, bt1, bt2);
        cvt3b_kernel<<<(DIM * DIM + 255) / 256, 256>>>(wv + (size_t)i * DIM * DIM, DIM, DIM, DIM, bt0, bt1, bt2);
        tgemm<<<dim3(16, 32), 256, TG_SMEM>>>(a0, a1, a2, bt0, bt1, bt2,
                                              nullptr, nullptr, qk, v,
                                              nullptr, nullptr, nullptr, DIM, DIM, 0, 1, DIM);
        hash_kernel<<<BH * (T_ / TCH), 128>>>(qk, rot + (size_t)i * 64 * 128, bk);
        sort_kernel<<<BH, 256>>>(bk, st);
        attn_kernel<<<BH * NCH, 128, asmem>>>(qk, v, st, o, lg);
        combine_kernel<<<BH * T_, 64>>>(o, lg, at);
        // O projection + residual into x1
        cvt3a_kernel<<<(nA + 255) / 256, 256>>>(at, nA, a0, a1, a2);
        cvt3b_kernel<<<(DIM * DIM + 255) / 256, 256>>>(wo + (size_t)i * DIM * DIM, DIM, DIM, 0, bt0, bt1, bt2);
        tgemm<<<dim3(8, 32), 256, TG_SMEM>>>(a0, a1, a2, bt0, bt1, bt2,
                                             bo + i * DIM, x1, x1, nullptr,
                                             nullptr, nullptr, nullptr, DIM, DIM, 0, 0, 0);
        ln_kernel<<<BT, 256>>>(x1, lnF_g + i * DIM, lnF_b + i * DIM, tmp);
        // FFN1 (gelu) -> bf16x3 splits into DISJOINT f0/f1/f2
        cvt3a_kernel<<<(nA + 255) / 256, 256>>>(tmp, nA, a0, a1, a2);
        cvt3b_kernel<<<(DIM * FF + 255) / 256, 256>>>(w1 + (size_t)i * DIM * FF, DIM, FF, 0, bt0, bt1, bt2);
        tgemm<<<dim3(32, 32), 256, TG_SMEM>>>(a0, a1, a2, bt0, bt1, bt2,
                                              b1 + i * FF, nullptr, nullptr, nullptr,
                                              f0, f1, f2, DIM, FF, 2, 0, 0);
        // FFN2 (+ residual into x2): A splits in f0/f1/f2
        cvt3b_kernel<<<(FF * DIM + 255) / 256, 256>>>(w2 + (size_t)i * FF * DIM, FF, DIM, 0, bt0, bt1, bt2);
        tgemm<<<dim3(8, 32), 256, TG_SMEM>>>(f0, f1, f2, bt0, bt1, bt2,
                                             b2 + i * DIM, x2, x2, nullptr,
                                             nullptr, nullptr, nullptr, FF, DIM, 0, 0, 0);
    }

    avg_kernel<<<(BT * DIM) / 256, 256>>>(x1, x2, tmp);
    sgemm<<<dim3(2, 32), 256>>>(tmp, lin_w, lin_b, out, BT, 88, DIM, 0);
}

// round 14
// speedup vs baseline: 1.9554x; 1.0280x over previous
#include <cuda_runtime.h>
#include <cuda_bf16.h>
#include <math.h>
#include <stdint.h>

#define B_   2
#define T_   2048
#define BT   4096
#define DIM  512
#define H_   8
#define DH   64
#define NH   8
#define NB   32
#define NCH  256
#define BH   16
#define NHT  16384
#define KC   704
#define FF   2048

#define KAHAN(s, c, p) { float y_ = (p) - (c); float t_ = (s) + y_; (c) = (t_ - (s)) - y_; (s) = t_; }

// ------------------------- scratch (static device) -------------------------
__device__ float g_x1[BT*DIM];
__device__ float g_x2[BT*DIM];
__device__ float g_tmp[BT*DIM];
__device__ float g_qk[BT*DIM];
__device__ float g_v [BT*DIM];
__device__ float g_im[BT*KC];
__device__ float g_wT[KC*DIM];
__device__ int   g_bk[BH*NHT];
__device__ int   g_st[BH*NHT];
__device__ float g_o [BH*NHT*DH];
__device__ float g_lg[BH*NHT];
// bf16 split buffers (activations: a* DIM-wide, f* FFN hidden)
__device__ __nv_bfloat16 g_a0[BT*DIM];
__device__ __nv_bfloat16 g_a1[BT*DIM];
__device__ __nv_bfloat16 g_a2[BT*DIM];
__device__ __nv_bfloat16 g_f0[BT*FF];
__device__ __nv_bfloat16 g_f1[BT*FF];
__device__ __nv_bfloat16 g_f2[BT*FF];
__device__ __nv_bfloat16 g_bt0[2*1024*1024];
__device__ __nv_bfloat16 g_bt1[2*1024*1024];
__device__ __nv_bfloat16 g_bt2[2*1024*1024];

// ------------------------- warp-mma helpers ---------------------------------
__device__ __forceinline__ uint32_t smem_u32(const void* p) {
    uint32_t a;
    asm("{ .reg .u64 t; cvta.to.shared.u64 t, %1; cvt.u32.u64 %0, t; }" : "=r"(a) : "l"(p));
    return a;
}
__device__ __forceinline__ void ldsm_x4(uint32_t* r, uint32_t addr) {
    asm volatile("ldmatrix.sync.aligned.m8n8.x4.shared.b16 {%0,%1,%2,%3}, [%4];"
        : "=r"(r[0]), "=r"(r[1]), "=r"(r[2]), "=r"(r[3]) : "r"(addr));
}
__device__ __forceinline__ void ldsm_x2(uint32_t* r, uint32_t addr) {
    asm volatile("ldmatrix.sync.aligned.m8n8.x2.shared.b16 {%0,%1}, [%2];"
        : "=r"(r[0]), "=r"(r[1]) : "r"(addr));
}
__device__ __forceinline__ void mma_bf16(float* d, const uint32_t* a, const uint32_t* b) {
    asm volatile("mma.sync.aligned.m16n8k16.row.col.f32.bf16.bf16.f32 "
        "{%0,%1,%2,%3}, {%4,%5,%6,%7}, {%8,%9}, {%0,%1,%2,%3};"
        : "+f"(d[0]), "+f"(d[1]), "+f"(d[2]), "+f"(d[3])
        : "r"(a[0]), "r"(a[1]), "r"(a[2]), "r"(a[3]), "r"(b[0]), "r"(b[1]));
}
__device__ __forceinline__ void cp16(uint32_t dst, const void* src) {
    size_t g = (size_t)__cvta_generic_to_global(src);
    asm volatile("cp.async.cg.shared.global [%0], [%1], 16;" :: "r"(dst), "l"(g));
}

// ------------------------- fp32 -> bf16x3 splits -----------------------------
__device__ __forceinline__ void split3(float v, __nv_bfloat16& b0, __nv_bfloat16& b1,
                                       __nv_bfloat16& b2) {
    b0 = __float2bfloat16(v);
    float r = v - __bfloat162float(b0);
    b1 = __float2bfloat16(r);
    float r2 = r - __bfloat162float(b1);
    b2 = __float2bfloat16(r2);
}
// W [K, N] fp32 -> Bt splits [rowoff+N, K] bf16 (transposed)
__global__ void cvt3b_kernel(const float* __restrict__ W, int Kd, int Nd, int rowoff,
                             __nv_bfloat16* __restrict__ d0, __nv_bfloat16* __restrict__ d1,
                             __nv_bfloat16* __restrict__ d2)
{
    int i = blockIdx.x * 256 + threadIdx.x;
    if (i >= Kd * Nd) return;
    int nrow = i / Kd, k = i - nrow * Kd;
    __nv_bfloat16 b0, b1, b2;
    split3(W[(size_t)k * Nd + nrow], b0, b1, b2);
    size_t o = (size_t)(rowoff + nrow) * Kd + k;
    d0[o] = b0; d1[o] = b1; d2[o] = b2;
}

// ------------------------- tensor-core bf16x3 GEMM --------------------------
// BM=128, BN=64, BK=32 per stage, 3-stage cp.async pipeline, ONE sync/chunk.
#define ASTRIDE 40
#define ABYTES (3 * 128 * ASTRIDE * 2)
#define BBYTES (3 * 64 * ASTRIDE * 2)
#define STAGEB (ABYTES + BBYTES)
#define TG_SMEM (3 * STAGEB)
__global__ __launch_bounds__(256) void tgemm(
    const __nv_bfloat16* __restrict__ a0, const __nv_bfloat16* __restrict__ a1,
    const __nv_bfloat16* __restrict__ a2,
    const __nv_bfloat16* __restrict__ bt0, const __nv_bfloat16* __restrict__ bt1,
    const __nv_bfloat16* __restrict__ bt2,
    const float* __restrict__ bias, const float* __restrict__ resid,
    float* __restrict__ C, float* __restrict__ C2,
    __nv_bfloat16* __restrict__ s0, __nv_bfloat16* __restrict__ s1,
    __nv_bfloat16* __restrict__ s2,
    int K, int Nout, int act, int heads, int Nsplit)
{
    extern __shared__ char smem[];
    const int tid = threadIdx.x;
    const int L = tid & 31, w = tid >> 5;
    const int mrow0 = (w & 3) * 32, ncol0 = (w >> 2) * 32;
    const int m0 = blockIdx.y * 128;
    const int n0 = blockIdx.x * 64;

    const uint32_t base = smem_u32(smem);
    const int arow = (L & 7) + ((L >> 3) & 1) * 8;
    const int acol = (L >> 4) * 8;
    const int brow = L & 7, bcol = ((L >> 3) & 1) * 8;

    const __nv_bfloat16* asp[3] = {a0, a1, a2};
    const __nv_bfloat16* bsp[3] = {bt0, bt1, bt2};

#define ISSUE_CHUNK(c, buf) do { \
    const int k0_ = (c) << 5; \
    const uint32_t sA_ = base + (buf) * STAGEB; \
    const uint32_t sB_ = sA_ + ABYTES; \
    _Pragma("unroll") \
    for (int it = 0; it < 6; it++) { \
        int idx = tid + it * 256; \
        int sp = idx >> 9, rem = idx & 511; \
        int row = rem >> 2, seg = rem & 3; \
        uint32_t dst = sA_ + ((sp * (128 * ASTRIDE) + row * ASTRIDE + seg * 8) << 1); \
        cp16(dst, asp[sp] + (size_t)(m0 + row) * K + k0_ + seg * 8); \
    } \
    _Pragma("unroll") \
    for (int it = 0; it < 3; it++) { \
        int idx = tid + it * 256; \
        int sp = idx >> 8, rem = idx & 255; \
        int row = rem >> 2, seg = rem & 3; \
        uint32_t dst = sB_ + ((sp * (64 * ASTRIDE) + row * ASTRIDE + seg * 8) << 1); \
        cp16(dst, bsp[sp] + (size_t)(n0 + row) * K + k0_ + seg * 8); \
    } \
    asm volatile("cp.async.commit_group;" ::: "memory"); \
} while (0)

    float acc[32], macc[32], mcmp[32];
    #pragma unroll
    for (int i = 0; i < 32; i++) { acc[i] = 0.f; macc[i] = 0.f; mcmp[i] = 0.f; }

    const int nch = K >> 5;
    ISSUE_CHUNK(0, 0);
    if (nch > 1) ISSUE_CHUNK(1, 1);

    for (int c = 0; c < nch; c++) {
        const int buf = c % 3;
        if (c + 1 < nch) asm volatile("cp.async.wait_group 1;" ::: "memory");
        else             asm volatile("cp.async.wait_group 0;" ::: "memory");
        __syncthreads();

        const uint32_t Ab = base + buf * STAGEB;
        const uint32_t Bb = Ab + ABYTES;

        #pragma unroll
        for (int ks = 0; ks < 2; ks++) {
            const int kof = ks * 16;
            uint32_t afr[3][2][4];
            #pragma unroll
            for (int sp = 0; sp < 3; sp++)
                #pragma unroll
                for (int mt = 0; mt < 2; mt++)
                    ldsm_x4(afr[sp][mt],
                            Ab + ((sp * (128 * ASTRIDE) + (mrow0 + mt * 16 + arow) * ASTRIDE
                                   + kof + acol) << 1));
            #pragma unroll
            for (int bj = 0; bj < 3; bj++) {
                uint32_t bfr[4][2];
                #pragma unroll
                for (int nt = 0; nt < 4; nt++)
                    ldsm_x2(bfr[nt],
                            Bb + ((bj * (64 * ASTRIDE) + (ncol0 + nt * 8 + brow) * ASTRIDE
                                   + kof + bcol) << 1));
                #pragma unroll
                for (int ai = 0; ai < 3; ai++) {
                    if (ai + bj > 2) break;
                    #pragma unroll
                    for (int mt = 0; mt < 2; mt++)
                        #pragma unroll
                        for (int nt = 0; nt < 4; nt++)
                            mma_bf16(&acc[(mt * 4 + nt) * 4], afr[ai][mt], bfr[nt]);
                }
            }
        }

        #pragma unroll
        for (int i = 0; i < 32; i++) {
            KAHAN(macc[i], mcmp[i], acc[i]);
            acc[i] = 0.f;
        }

        if (c + 2 < nch) ISSUE_CHUNK(c + 2, (c + 2) % 3);
    }

    // ------------- epilogue -------------
    int n0c = n0;
    float* Co = C;
    if (Nsplit && n0c >= Nsplit) { Co = C2; n0c -= Nsplit; }
    #pragma unroll
    for (int mt = 0; mt < 2; mt++)
        #pragma unroll
        for (int nt = 0; nt < 4; nt++)
            #pragma unroll
            for (int r = 0; r < 4; r++) {
                int i = (mt * 4 + nt) * 4 + r;
                float v = macc[i] + mcmp[i];
                int row = m0 + mrow0 + mt * 16 + (L >> 2) + ((r >> 1) * 8);
                int col = n0c + ncol0 + nt * 8 + ((L & 3) * 2) + (r & 1);
                if (bias) v += bias[col];
                if (act == 2) v = 0.5f * v * (1.f + erff(v * 0.70710678118654752f));
                if (resid) v += resid[(size_t)row * Nout + col];
                if (s0) {
                    __nv_bfloat16 b0, b1, b2;
                    split3(v, b0, b1, b2);
                    size_t o = (size_t)row * Nout + col;
                    s0[o] = b0; s1[o] = b1; s2[o] = b2;
                } else if (heads) {
                    int b = row >> 11, t = row & 2047;
                    int h = col >> 6, d = col & 63;
                    Co[((((size_t)b * H_ + h) * T_ + t) << 6) + d] = v;
                } else {
                    Co[(size_t)row * Nout + col] = v;
                }
            }
}

// ------------------------- scalar SGEMM (conv + final head) -----------------
__global__ __launch_bounds__(256) void sgemm(
    const float* __restrict__ A, const float* __restrict__ Bm,
    const float* __restrict__ bias, float* __restrict__ C,
    int M, int N, int K, int act)
{
    __shared__ float As[16][132];
    __shared__ float Bs[16][64];
    const int tid = threadIdx.x;
    const int tx = tid & 15, ty = tid >> 4;
    const int m0 = blockIdx.y * 128;
    int n0 = blockIdx.x * 64;

    float acc[8][4], cmp[8][4];
    #pragma unroll
    for (int i = 0; i < 8; i++)
        #pragma unroll
        for (int j = 0; j < 4; j++) { acc[i][j] = 0.f; cmp[i][j] = 0.f; }

    const int arow0 = tid >> 2, ac4 = (tid & 3) * 4;
    const int brow = tid >> 4, bc4 = (tid & 15) * 4;
    const int bcol = n0 + bc4;

    for (int k0 = 0; k0 < K; k0 += 16) {
        #pragma unroll
        for (int s = 0; s < 2; s++) {
            int row = arow0 + s * 64;
            float4 a = *(const float4*)(A + (size_t)(m0 + row) * K + k0 + ac4);
            As[ac4 + 0][row] = a.x; As[ac4 + 1][row] = a.y;
            As[ac4 + 2][row] = a.z; As[ac4 + 3][row] = a.w;
        }
        float4 bv;
        if (bcol < N) bv = *(const float4*)(Bm + (size_t)(k0 + brow) * N + bcol);
        else          bv = make_float4(0.f, 0.f, 0.f, 0.f);
        *(float4*)(&Bs[brow][bc4]) = bv;
        __syncthreads();
        float pb[8][4];
        #pragma unroll
        for (int kk = 0; kk < 16; kk++) {
            float4 a0 = *(const float4*)(&As[kk][ty * 8]);
            float4 a1 = *(const float4*)(&As[kk][ty * 8 + 4]);
            float4 bb = *(const float4*)(&Bs[kk][tx * 4]);
            float av[8] = {a0.x, a0.y, a0.z, a0.w, a1.x, a1.y, a1.z, a1.w};
            float bw[4] = {bb.x, bb.y, bb.z, bb.w};
            if (kk == 0) {
                #pragma unroll
                for (int i = 0; i < 8; i++)
                    #pragma unroll
                    for (int j = 0; j < 4; j++) pb[i][j] = av[i] * bw[j];
            } else {
                #pragma unroll
                for (int i = 0; i < 8; i++)
                    #pragma unroll
                    for (int j = 0; j < 4; j++) pb[i][j] = fmaf(av[i], bw[j], pb[i][j]);
            }
        }
        #pragma unroll
        for (int i = 0; i < 8; i++)
            #pragma unroll
            for (int j = 0; j < 4; j++) KAHAN(acc[i][j], cmp[i][j], pb[i][j]);
        __syncthreads();
    }

    #pragma unroll
    for (int i = 0; i < 8; i++) {
        int row = m0 + ty * 8 + i;
        #pragma unroll
        for (int j = 0; j < 4; j++) {
            int col = n0 + tx * 4 + j;
            if (col >= N) continue;
            float v = acc[i][j] + cmp[i][j];
            if (bias) v += bias[col];
            if (act == 1) v = fmaxf(v, 0.f);
            C[(size_t)row * N + col] = v;
        }
    }
}

// ------------------------- LayerNorm (emits bf16x3 splits) -------------------
__global__ __launch_bounds__(256) void ln_kernel(
    const float* __restrict__ x, const float* __restrict__ g,
    const float* __restrict__ bb,
    __nv_bfloat16* __restrict__ d0, __nv_bfloat16* __restrict__ d1,
    __nv_bfloat16* __restrict__ d2)
{
    __shared__ float sh[8];
    int row = blockIdx.x, tid = threadIdx.x;
    const float* xr = x + (size_t)row * DIM;
    float v0 = xr[tid], v1 = xr[tid + 256];
    float s = v0 + v1;
    #pragma unroll
    for (int o = 16; o; o >>= 1) s += __shfl_down_sync(0xffffffffu, s, o);
    if ((tid & 31) == 0) sh[tid >> 5] = s;
    __syncthreads();
    if (tid < 32) {
        float t = (tid < 8) ? sh[tid] : 0.f;
        #pragma unroll
        for (int o = 4; o; o >>= 1) t += __shfl_down_sync(0xffffffffu, t, o);
        if (tid == 0) sh[0] = t;
    }
    __syncthreads();
    float mean = sh[0] * (1.f / DIM);
    __syncthreads();
    float dd0 = v0 - mean, dd1 = v1 - mean;
    float s2 = dd0 * dd0 + dd1 * dd1;
    #pragma unroll
    for (int o = 16; o; o >>= 1) s2 += __shfl_down_sync(0xffffffffu, s2, o);
    if ((tid & 31) == 0) sh[tid >> 5] = s2;
    __syncthreads();
    if (tid < 32) {
        float t = (tid < 8) ? sh[tid] : 0.f;
        #pragma unroll
        for (int o = 4; o; o >>= 1) t += __shfl_down_sync(0xffffffffu, t, o);
        if (tid == 0) sh[0] = t;
    }
    __syncthreads();
    float inv = 1.f / sqrtf(sh[0] * (1.f / DIM) + 1e-5f);
    float y0 = dd0 * inv * g[tid]       + bb[tid];
    float y1 = dd1 * inv * g[tid + 256] + bb[tid + 256];
    __nv_bfloat16 b0, b1, b2;
    size_t o0 = (size_t)row * DIM + tid;
    split3(y0, b0, b1, b2);
    d0[o0] = b0; d1[o0] = b1; d2[o0] = b2;
    split3(y1, b0, b1, b2);
    d0[o0 + 256] = b0; d1[o0 + 256] = b1; d2[o0 + 256] = b2;
}

// ------------------------- LSH hashing --------------------------------------
#define TCH 16
__global__ __launch_bounds__(128) void hash_kernel(
    const float* __restrict__ qk, const float* __restrict__ rot, int* __restrict__ bkt)
{
    __shared__ float q[4][DH];
    int blk = blockIdx.x;
    int bh = blk / (T_ / TCH);
    int t0 = (blk % (T_ / TCH)) * TCH;
    int tid = threadIdx.x;
    int h = tid >> 4, j = tid & 15;
    float rv[64];
    #pragma unroll
    for (int f = 0; f < 64; f++) rv[f] = rot[f * 128 + h * 16 + j];

    for (int tg = 0; tg < TCH; tg += 4) {
        __syncthreads();
        for (int idx = tid; idx < 4 * DH; idx += 128) {
            int r = idx >> 6, d = idx & 63;
            q[r][d] = qk[((size_t)bh * T_ + t0 + tg + r) * DH + d];
        }
        __syncthreads();
        float a0 = 0.f, a1 = 0.f, a2 = 0.f, a3 = 0.f;
        float c0 = 0.f, c1 = 0.f, c2 = 0.f, c3 = 0.f;
        #pragma unroll
        for (int f = 0; f < 64; f++) {
            float r = rv[f];
            float p0 = q[0][f] * r; KAHAN(a0, c0, p0);
            float p1 = q[1][f] * r; KAHAN(a1, c1, p1);
            float p2 = q[2][f] * r; KAHAN(a2, c2, p2);
            float p3 = q[3][f] * r; KAHAN(a3, c3, p3);
        }
        float vals[4] = {a0 + c0, a1 + c1, a2 + c2, a3 + c3};
        #pragma unroll
        for (int r = 0; r < 4; r++) {
            float v = vals[r]; int idx = j;
            float nv = -v;
            if (nv > v) { v = nv; idx = j + 16; }
            #pragma unroll
            for (int o = 8; o; o >>= 1) {
                float ov = __shfl_down_sync(0xffffffffu, v, o, 16);
                int   oi = __shfl_down_sync(0xffffffffu, idx, o, 16);
                if (ov > v || (ov == v && oi < idx)) { v = ov; idx = oi; }
            }
            if (j == 0) bkt[(size_t)bh * NHT + h * T_ + t0 + tg + r] = idx + h * NB;
        }
    }
}

// ------------------------- stable counting sort ------------------------------
__global__ __launch_bounds__(256) void sort_kernel(
    const int* __restrict__ bkt, int* __restrict__ st)
{
    __shared__ int hist[256];
    __shared__ int off[256];
    int bh = blockIdx.x, tid = threadIdx.x;
    const int* bb = bkt + (size_t)bh * NHT;
    hist[tid] = 0;
    __syncthreads();
    for (int i = tid; i < NHT; i += 256) atomicAdd(&hist[bb[i]], 1);
    __syncthreads();
    if (tid == 0) {
        int s = 0;
        for (int i = 0; i < 256; i++) { off[i] = s; s += hist[i]; }
    }
    __syncthreads();
    int beta = tid, h = tid >> 5;
    int o = off[beta];
    int* out2 = st + (size_t)bh * NHT;
    int base = h * T_;
    for (int k = 0; k < T_; k++)
        if (bb[base + k] == beta) out2[o++] = base + k;
}

// ------------------------- chunked LSH attention (plain fp32 accum) ---------
#define RS 68
#define DS 129
__global__ __launch_bounds__(128) void attn_kernel(
    const float* __restrict__ qk, const float* __restrict__ vg,
    const int* __restrict__ st, float* __restrict__ og, float* __restrict__ lgg)
{
    extern __shared__ float sm[];
    float* r     = sm;
    float* vv    = r + 128 * RS;
    float* dots  = vv + 128 * 64;
    float* inorm = dots + 64 * DS;
    float* logit = inorm + 128;
    int*   kpos  = (int*)(logit + 64);
    int*   qh    = kpos + 128;

    int tid = threadIdx.x;
    int bh = blockIdx.x >> 8, c = blockIdx.x & 255;
    int cp = (c + NCH - 1) & 255;

    {
        int lc = (tid < 64) ? c : cp;
        int tk = st[(size_t)bh * NHT + lc * 64 + (tid & 63)];
        kpos[tid] = tk & (T_ - 1);
        if (tid < 64) qh[tid] = tk >> 11;
    }
    __syncthreads();

    const float* qb = qk + ((size_t)bh << 17);
    const float* vb = vg + ((size_t)bh << 17);
    for (int it = 0; it < 64; it++) {
        int idx = it * 128 + tid;
        int jj = idx >> 6, d = idx & 63;
        int pos = kpos[jj];
        r[jj * RS + d]    = qb[(pos << 6) + d];
        vv[(jj << 6) + d] = vb[(pos << 6) + d];
    }
    __syncthreads();
    {
        float s = 0.f, cs = 0.f;
        #pragma unroll 8
        for (int d = 0; d < 64; d++) {
            float x = r[tid * RS + d];
            float p = x * x; KAHAN(s, cs, p);
        }
        inorm[tid] = 1.f / fmaxf(sqrtf(s + cs), 1e-12f);
    }
    __syncthreads();

    int tx = tid & 15, ty = tid >> 4;
    float acc[8][8];
    #pragma unroll
    for (int i = 0; i < 8; i++)
        #pragma unroll
        for (int m = 0; m < 8; m++) acc[i][m] = 0.f;

    for (int d = 0; d < 64; d++) {
        float kv[8];
        #pragma unroll
        for (int m = 0; m < 8; m++) kv[m] = r[(tx + 16 * m) * RS + d];
        #pragma unroll
        for (int i = 0; i < 8; i++) {
            float q = r[(ty * 8 + i) * RS + d];
            #pragma unroll
            for (int m = 0; m < 8; m++) acc[i][m] = fmaf(q, kv[m], acc[i][m]);
        }
    }
    #pragma unroll
    for (int i = 0; i < 8; i++) {
        int row = ty * 8 + i; int rp = kpos[row];
        #pragma unroll
        for (int m = 0; m < 8; m++) {
            int col = tx + 16 * m;
            float dv = acc[i][m] * inorm[col] * 0.125f;
            if (rp == kpos[col]) dv = -5e4f;
            dots[row * DS + col] = dv;
        }
    }
    __syncthreads();

    if (tid < 64) {
        float mx = -1e30f;
        #pragma unroll 8
        for (int j2 = 0; j2 < 128; j2++) mx = fmaxf(mx, dots[tid * DS + j2]);
        float s = 0.f;
        #pragma unroll 8
        for (int j2 = 0; j2 < 128; j2++) s += expf(dots[tid * DS + j2] - mx);
        float lg = mx + logf(s);
        logit[tid] = lg;
        lgg[((size_t)bh * NH + qh[tid]) * T_ + kpos[tid]] = lg;
    }
    __syncthreads();
    for (int it = 0; it < 64; it++) {
        int idx = it * 128 + tid; int i = idx >> 7, j2 = idx & 127;
        dots[i * DS + j2] = expf(dots[i * DS + j2] - logit[i]);
    }
    __syncthreads();

    float a2[8][4];
    #pragma unroll
    for (int i = 0; i < 8; i++)
        #pragma unroll
        for (int m = 0; m < 4; m++) a2[i][m] = 0.f;
    for (int j2 = 0; j2 < 128; j2++) {
        float vw[4];
        #pragma unroll
        for (int m = 0; m < 4; m++) vw[m] = vv[(j2 << 6) + tx + 16 * m];
        #pragma unroll
        for (int i = 0; i < 8; i++) {
            float p = dots[(ty * 8 + i) * DS + j2];
            #pragma unroll
            for (int m = 0; m < 4; m++) a2[i][m] = fmaf(p, vw[m], a2[i][m]);
        }
    }
    #pragma unroll
    for (int i = 0; i < 8; i++) {
        int row = ty * 8 + i;
        size_t base = (((size_t)bh * NH + qh[row]) * T_ + kpos[row]) << 6;
        #pragma unroll
        for (int m = 0; m < 4; m++) og[base + tx + 16 * m] = a2[i][m];
    }
}

// ------------------------- combine hash rounds (emits bf16x3 splits) --------
__global__ __launch_bounds__(64) void combine_kernel(
    const float* __restrict__ og, const float* __restrict__ lgg,
    __nv_bfloat16* __restrict__ d0, __nv_bfloat16* __restrict__ d1,
    __nv_bfloat16* __restrict__ d2)
{
    __shared__ float w[8];
    int bh = blockIdx.x >> 11, pos = blockIdx.x & 2047;
    int tid = threadIdx.x;
    if (tid == 0) {
        float v[8]; float mx = -1e30f;
        #pragma unroll
        for (int h = 0; h < 8; h++) {
            v[h] = lgg[((size_t)bh * NH + h) * T_ + pos];
            mx = fmaxf(mx, v[h]);
        }
        float s = 0.f;
        #pragma unroll
        for (int h = 0; h < 8; h++) { v[h] = expf(v[h] - mx); s += v[h]; }
        float is = 1.f / s;
        #pragma unroll
        for (int h = 0; h < 8; h++) w[h] = v[h] * is;
    }
    __syncthreads();
    float acc = 0.f, cc = 0.f;
    #pragma unroll
    for (int h = 0; h < 8; h++) {
        float p = w[h] * og[(((size_t)bh * NH + h) * T_ + pos) * 64 + tid];
        KAHAN(acc, cc, p);
    }
    int b = bh >> 3, hd = bh & 7;
    size_t o = ((size_t)(b * T_ + pos)) * DIM + hd * 64 + tid;
    __nv_bfloat16 b0, b1, b2;
    split3(acc + cc, b0, b1, b2);
    d0[o] = b0; d1[o] = b1; d2[o] = b2;
}

// ------------------------- frontend helpers ---------------------------------
__global__ void wt_kernel(const float* __restrict__ w, float* __restrict__ wT)
{
    int idx = blockIdx.x * 256 + threadIdx.x;
    int c = idx / DIM, o2 = idx - c * DIM;
    wT[idx] = (c < 687) ? w[(size_t)o2 * 687 + c] : 0.f;
}

__global__ void im2col_kernel(const float* __restrict__ spec, float* __restrict__ im)
{
    int idx = blockIdx.x * 256 + threadIdx.x;
    int row = idx / KC, c = idx - row * KC;
    int b = row >> 11, t = row & 2047;
    float val = 0.f;
    if (c < 687) {
        int i = c / 3, k = c - i * 3;
        int tt = t + k - 1;
        if (tt >= 0 && tt < T_) val = spec[((size_t)b * T_ + tt) * 229 + i];
    }
    im[idx] = val;
}

__global__ void pe_kernel(float* __restrict__ x1, float* __restrict__ x2,
                          const float* __restrict__ per, const float* __restrict__ pec)
{
    int idx = blockIdx.x * 256 + threadIdx.x;
    int c = idx & 511;
    int t = (idx >> 9) & 2047;
    float p = (c < 256) ? per[(t >> 6) * 256 + c] : pec[(t & 63) * 256 + (c - 256)];
    float v = x1[idx] + p;
    x1[idx] = v; x2[idx] = v;
}

__global__ void avg_kernel(const float* __restrict__ a, const float* __restrict__ b,
                           float* __restrict__ y)
{
    int idx = blockIdx.x * 256 + threadIdx.x;
    y[idx] = 0.5f * (a[idx] + b[idx]);
}

// ------------------------- driver -------------------------------------------
extern "C" void kernel_launch(void* const* d_in, const int* in_sizes, int n_in,
                              void* d_out, int out_size)
{
    const float* spec   = (const float*)d_in[0];
    const float* conv_w = (const float*)d_in[1];
    const float* conv_b = (const float*)d_in[2];
    const float* pe_row = (const float*)d_in[3];
    const float* pe_col = (const float*)d_in[4];
    const float* lnA_g  = (const float*)d_in[5];
    const float* lnA_b  = (const float*)d_in[6];
    const float* wqk    = (const float*)d_in[7];
    const float* wv     = (const float*)d_in[8];
    const float* wo     = (const float*)d_in[9];
    const float* bo     = (const float*)d_in[10];
    const float* lnF_g  = (const float*)d_in[11];
    const float* lnF_b  = (const float*)d_in[12];
    const float* w1     = (const float*)d_in[13];
    const float* b1     = (const float*)d_in[14];
    const float* w2     = (const float*)d_in[15];
    const float* b2     = (const float*)d_in[16];
    const float* lin_w  = (const float*)d_in[17];
    const float* lin_b  = (const float*)d_in[18];
    const float* rot    = (const float*)d_in[19];
    float* out = (float*)d_out;

    float *x1, *x2, *tmp, *qk, *v, *im, *wT, *o, *lg;
    int *bk, *st;
    __nv_bfloat16 *a0, *a1, *a2, *f0, *f1, *f2, *bt0, *bt1, *bt2;
    cudaGetSymbolAddress((void**)&x1, g_x1);
    cudaGetSymbolAddress((void**)&x2, g_x2);
    cudaGetSymbolAddress((void**)&tmp, g_tmp);
    cudaGetSymbolAddress((void**)&qk, g_qk);
    cudaGetSymbolAddress((void**)&v,  g_v);
    cudaGetSymbolAddress((void**)&im, g_im);
    cudaGetSymbolAddress((void**)&wT, g_wT);
    cudaGetSymbolAddress((void**)&o,  g_o);
    cudaGetSymbolAddress((void**)&lg, g_lg);
    cudaGetSymbolAddress((void**)&bk, g_bk);
    cudaGetSymbolAddress((void**)&st, g_st);
    cudaGetSymbolAddress((void**)&a0, g_a0);
    cudaGetSymbolAddress((void**)&a1, g_a1);
    cudaGetSymbolAddress((void**)&a2, g_a2);
    cudaGetSymbolAddress((void**)&f0, g_f0);
    cudaGetSymbolAddress((void**)&f1, g_f1);
    cudaGetSymbolAddress((void**)&f2, g_f2);
    cudaGetSymbolAddress((void**)&bt0, g_bt0);
    cudaGetSymbolAddress((void**)&bt1, g_bt1);
    cudaGetSymbolAddress((void**)&bt2, g_bt2);

    size_t asmem = (size_t)(128 * RS + 128 * 64 + 64 * DS + 128 + 64 + 128 + 64) * 4;
    cudaFuncSetAttribute(attn_kernel, cudaFuncAttributeMaxDynamicSharedMemorySize, (int)asmem);
    cudaFuncSetAttribute(tgemm, cudaFuncAttributeMaxDynamicSharedMemorySize, TG_SMEM);

    // frontend
    wt_kernel<<<(KC * DIM) / 256, 256>>>(conv_w, wT);
    im2col_kernel<<<(BT * KC) / 256, 256>>>(spec, im);
    sgemm<<<dim3(DIM / 64, BT / 128), 256>>>(im, wT, conv_b, x1, BT, DIM, KC, 1);
    pe_kernel<<<(BT * DIM) / 256, 256>>>(x1, x2, pe_row, pe_col);

    for (int i = 0; i < 8; i++) {
        // LN -> bf16x3 splits of attention input
        ln_kernel<<<BT, 256>>>(x2, lnA_g + i * DIM, lnA_b + i * DIM, a0, a1, a2);
        cvt3b_kernel<<<(DIM * DIM + 255) / 256, 256>>>(wqk + (size_t)i * DIM * DIM, DIM, DIM, 0, bt0, bt1, bt2);
        cvt3b_kernel<<<(DIM * DIM + 255) / 256, 256>>>(wv + (size_t)i * DIM * DIM, DIM, DIM, DIM, bt0, bt1, bt2);
        tgemm<<<dim3(16, 32), 256, TG_SMEM>>>(a0, a1, a2, bt0, bt1, bt2,
                                              nullptr, nullptr, qk, v,
                                              nullptr, nullptr, nullptr, DIM, DIM, 0, 1, DIM);
        hash_kernel<<<BH * (T_ / TCH), 128>>>(qk, rot + (size_t)i * 64 * 128, bk);
        sort_kernel<<<BH, 256>>>(bk, st);
        attn_kernel<<<BH * NCH, 128, asmem>>>(qk, v, st, o, lg);
        // combine -> bf16x3 splits of O-proj input
        combine_kernel<<<BH * T_, 64>>>(o, lg, a0, a1, a2);
        cvt3b_kernel<<<(DIM * DIM + 255) / 256, 256>>>(wo + (size_t)i * DIM * DIM, DIM, DIM, 0, bt0, bt1, bt2);
        tgemm<<<dim3(8, 32), 256, TG_SMEM>>>(a0, a1, a2, bt0, bt1, bt2,
                                             bo + i * DIM, x1, x1, nullptr,
                                             nullptr, nullptr, nullptr, DIM, DIM, 0, 0, 0);
        // LN -> bf16x3 splits of FFN input
        ln_kernel<<<BT, 256>>>(x1, lnF_g + i * DIM, lnF_b + i * DIM, a0, a1, a2);
        cvt3b_kernel<<<(DIM * FF + 255) / 256, 256>>>(w1 + (size_t)i * DIM * FF, DIM, FF, 0, bt0, bt1, bt2);
        tgemm<<<dim3(32, 32), 256, TG_SMEM>>>(a0, a1, a2, bt0, bt1, bt2,
                                              b1 + i * FF, nullptr, nullptr, nullptr,
                                              f0, f1, f2, DIM, FF, 2, 0, 0);
        cvt3b_kernel<<<(FF * DIM + 255) / 256, 256>>>(w2 + (size_t)i * FF * DIM, FF, DIM, 0, bt0, bt1, bt2);
        tgemm<<<dim3(8, 32), 256, TG_SMEM>>>(f0, f1, f2, bt0, bt1, bt2,
                                             b2 + i * DIM, x2, x2, nullptr,
                                             nullptr, nullptr, nullptr, FF, DIM, 0, 0, 0);
    }

    avg_kernel<<<(BT * DIM) / 256, 256>>>(x1, x2, tmp);
    sgemm<<<dim3(2, 32), 256>>>(tmp, lin_w, lin_b, out, BT, 88, DIM, 0);
}

// round 15
// speedup vs baseline: 2.1673x; 1.1084x over previous
#include <cuda_runtime.h>
#include <cuda_bf16.h>
#include <math.h>
#include <stdint.h>

#define B_   2
#define T_   2048
#define BT   4096
#define DIM  512
#define H_   8
#define DH   64
#define NH   8
#define NB   32
#define NCH  256
#define BH   16
#define NHT  16384
#define KC   704
#define FF   2048

#define KAHAN(s, c, p) { float y_ = (p) - (c); float t_ = (s) + y_; (c) = (t_ - (s)) - y_; (s) = t_; }

// ------------------------- scratch (static device) -------------------------
__device__ float g_x1[BT*DIM];
__device__ float g_x2[BT*DIM];
__device__ float g_tmp[BT*DIM];
__device__ float g_qk[BT*DIM];
__device__ float g_v [BT*DIM];
__device__ float g_im[BT*KC];
__device__ float g_wT[KC*DIM];
__device__ int   g_bk[BH*NHT];
__device__ int   g_st[BH*NHT];
__device__ float g_o [BH*NHT*DH];
__device__ float g_lg[BH*NHT];
// bf16 split buffers
__device__ __nv_bfloat16 g_a0[BT*DIM];
__device__ __nv_bfloat16 g_a1[BT*DIM];
__device__ __nv_bfloat16 g_a2[BT*DIM];
__device__ __nv_bfloat16 g_f0[BT*FF];
__device__ __nv_bfloat16 g_f1[BT*FF];
__device__ __nv_bfloat16 g_f2[BT*FF];
__device__ __nv_bfloat16 g_bt0[2*1024*1024];
__device__ __nv_bfloat16 g_bt1[2*1024*1024];
__device__ __nv_bfloat16 g_bt2[2*1024*1024];

// ------------------------- warp-mma helpers ---------------------------------
__device__ __forceinline__ uint32_t smem_u32(const void* p) {
    uint32_t a;
    asm("{ .reg .u64 t; cvta.to.shared.u64 t, %1; cvt.u32.u64 %0, t; }" : "=r"(a) : "l"(p));
    return a;
}
__device__ __forceinline__ void ldsm_x4(uint32_t* r, uint32_t addr) {
    asm volatile("ldmatrix.sync.aligned.m8n8.x4.shared.b16 {%0,%1,%2,%3}, [%4];"
        : "=r"(r[0]), "=r"(r[1]), "=r"(r[2]), "=r"(r[3]) : "r"(addr));
}
__device__ __forceinline__ void ldsm_x2(uint32_t* r, uint32_t addr) {
    asm volatile("ldmatrix.sync.aligned.m8n8.x2.shared.b16 {%0,%1}, [%2];"
        : "=r"(r[0]), "=r"(r[1]) : "r"(addr));
}
__device__ __forceinline__ void mma_bf16(float* d, const uint32_t* a, const uint32_t* b) {
    asm volatile("mma.sync.aligned.m16n8k16.row.col.f32.bf16.bf16.f32 "
        "{%0,%1,%2,%3}, {%4,%5,%6,%7}, {%8,%9}, {%0,%1,%2,%3};"
        : "+f"(d[0]), "+f"(d[1]), "+f"(d[2]), "+f"(d[3])
        : "r"(a[0]), "r"(a[1]), "r"(a[2]), "r"(a[3]), "r"(b[0]), "r"(b[1]));
}
__device__ __forceinline__ void cp16(uint32_t dst, const void* src) {
    size_t g = (size_t)__cvta_generic_to_global(src);
    asm volatile("cp.async.cg.shared.global [%0], [%1], 16;" :: "r"(dst), "l"(g));
}

// ------------------------- fp32 -> bf16x3 splits -----------------------------
__device__ __forceinline__ void split3(float v, __nv_bfloat16& b0, __nv_bfloat16& b1,
                                       __nv_bfloat16& b2) {
    b0 = __float2bfloat16(v);
    float r = v - __bfloat162float(b0);
    b1 = __float2bfloat16(r);
    float r2 = r - __bfloat162float(b1);
    b2 = __float2bfloat16(r2);
}
// W [K, N] fp32 -> Bt splits [rowoff+N, K] bf16 (transposed)
__global__ void cvt3b_kernel(const float* __restrict__ W, int Kd, int Nd, int rowoff,
                             __nv_bfloat16* __restrict__ d0, __nv_bfloat16* __restrict__ d1,
                             __nv_bfloat16* __restrict__ d2)
{
    int i = blockIdx.x * 256 + threadIdx.x;
    if (i >= Kd * Nd) return;
    int nrow = i / Kd, k = i - nrow * Kd;
    __nv_bfloat16 b0, b1, b2;
    split3(W[(size_t)k * Nd + nrow], b0, b1, b2);
    size_t o = (size_t)(rowoff + nrow) * Kd + k;
    d0[o] = b0; d1[o] = b1; d2[o] = b2;
}

// ------------------------- tensor-core bf16x3 GEMM --------------------------
// BM=128, BN=64, BK=32 per stage, 2-stage cp.async pipeline, 2 CTAs/SM.
// Chunk partials plain-summed into macc (no mcmp) to fit 128 regs.
#define ASTRIDE 40
#define ABYTES (3 * 128 * ASTRIDE * 2)
#define BBYTES (3 * 64 * ASTRIDE * 2)
#define STAGEB (ABYTES + BBYTES)
#define TG_SMEM (2 * STAGEB)
__global__ __launch_bounds__(256, 2) void tgemm(
    const __nv_bfloat16* __restrict__ a0, const __nv_bfloat16* __restrict__ a1,
    const __nv_bfloat16* __restrict__ a2,
    const __nv_bfloat16* __restrict__ bt0, const __nv_bfloat16* __restrict__ bt1,
    const __nv_bfloat16* __restrict__ bt2,
    const float* __restrict__ bias, const float* __restrict__ resid,
    float* __restrict__ C, float* __restrict__ C2,
    __nv_bfloat16* __restrict__ s0, __nv_bfloat16* __restrict__ s1,
    __nv_bfloat16* __restrict__ s2,
    int K, int Nout, int act, int heads, int Nsplit)
{
    extern __shared__ char smem[];
    const int tid = threadIdx.x;
    const int L = tid & 31, w = tid >> 5;
    const int mrow0 = (w & 3) * 32, ncol0 = (w >> 2) * 32;
    const int m0 = blockIdx.y * 128;
    const int n0 = blockIdx.x * 64;

    const uint32_t base = smem_u32(smem);
    const int arow = (L & 7) + ((L >> 3) & 1) * 8;
    const int acol = (L >> 4) * 8;
    const int brow = L & 7, bcol = ((L >> 3) & 1) * 8;

    const __nv_bfloat16* asp[3] = {a0, a1, a2};
    const __nv_bfloat16* bsp[3] = {bt0, bt1, bt2};

#define ISSUE_CHUNK(c, buf) do { \
    const int k0_ = (c) << 5; \
    const uint32_t sA_ = base + (buf) * STAGEB; \
    const uint32_t sB_ = sA_ + ABYTES; \
    _Pragma("unroll") \
    for (int it = 0; it < 6; it++) { \
        int idx = tid + it * 256; \
        int sp = idx >> 9, rem = idx & 511; \
        int row = rem >> 2, seg = rem & 3; \
        uint32_t dst = sA_ + ((sp * (128 * ASTRIDE) + row * ASTRIDE + seg * 8) << 1); \
        cp16(dst, asp[sp] + (size_t)(m0 + row) * K + k0_ + seg * 8); \
    } \
    _Pragma("unroll") \
    for (int it = 0; it < 3; it++) { \
        int idx = tid + it * 256; \
        int sp = idx >> 8, rem = idx & 255; \
        int row = rem >> 2, seg = rem & 3; \
        uint32_t dst = sB_ + ((sp * (64 * ASTRIDE) + row * ASTRIDE + seg * 8) << 1); \
        cp16(dst, bsp[sp] + (size_t)(n0 + row) * K + k0_ + seg * 8); \
    } \
    asm volatile("cp.async.commit_group;" ::: "memory"); \
} while (0)

    float acc[32], macc[32];
    #pragma unroll
    for (int i = 0; i < 32; i++) { acc[i] = 0.f; macc[i] = 0.f; }

    const int nch = K >> 5;
    ISSUE_CHUNK(0, 0);

    for (int c = 0; c < nch; c++) {
        const int buf = c & 1;
        if (c + 1 < nch) {
            ISSUE_CHUNK(c + 1, buf ^ 1);
            asm volatile("cp.async.wait_group 1;" ::: "memory");
        } else {
            asm volatile("cp.async.wait_group 0;" ::: "memory");
        }
        __syncthreads();

        const uint32_t Ab = base + buf * STAGEB;
        const uint32_t Bb = Ab + ABYTES;

        #pragma unroll
        for (int ks = 0; ks < 2; ks++) {
            const int kof = ks * 16;
            uint32_t afr[3][2][4];
            #pragma unroll
            for (int sp = 0; sp < 3; sp++)
                #pragma unroll
                for (int mt = 0; mt < 2; mt++)
                    ldsm_x4(afr[sp][mt],
                            Ab + ((sp * (128 * ASTRIDE) + (mrow0 + mt * 16 + arow) * ASTRIDE
                                   + kof + acol) << 1));
            #pragma unroll
            for (int bj = 0; bj < 3; bj++) {
                uint32_t bfr[4][2];
                #pragma unroll
                for (int nt = 0; nt < 4; nt++)
                    ldsm_x2(bfr[nt],
                            Bb + ((bj * (64 * ASTRIDE) + (ncol0 + nt * 8 + brow) * ASTRIDE
                                   + kof + bcol) << 1));
                #pragma unroll
                for (int ai = 0; ai < 3; ai++) {
                    if (ai + bj > 2) break;
                    #pragma unroll
                    for (int mt = 0; mt < 2; mt++)
                        #pragma unroll
                        for (int nt = 0; nt < 4; nt++)
                            mma_bf16(&acc[(mt * 4 + nt) * 4], afr[ai][mt], bfr[nt]);
                }
            }
        }
        __syncthreads();

        #pragma unroll
        for (int i = 0; i < 32; i++) {
            macc[i] += acc[i];
            acc[i] = 0.f;
        }
    }

    // ------------- epilogue -------------
    int n0c = n0;
    float* Co = C;
    if (Nsplit && n0c >= Nsplit) { Co = C2; n0c -= Nsplit; }
    #pragma unroll
    for (int mt = 0; mt < 2; mt++)
        #pragma unroll
        for (int nt = 0; nt < 4; nt++)
            #pragma unroll
            for (int r = 0; r < 4; r++) {
                int i = (mt * 4 + nt) * 4 + r;
                float v = macc[i];
                int row = m0 + mrow0 + mt * 16 + (L >> 2) + ((r >> 1) * 8);
                int col = n0c + ncol0 + nt * 8 + ((L & 3) * 2) + (r & 1);
                if (bias) v += bias[col];
                if (act == 2) v = 0.5f * v * (1.f + erff(v * 0.70710678118654752f));
                if (resid) v += resid[(size_t)row * Nout + col];
                if (s0) {
                    __nv_bfloat16 b0, b1, b2;
                    split3(v, b0, b1, b2);
                    size_t o = (size_t)row * Nout + col;
                    s0[o] = b0; s1[o] = b1; s2[o] = b2;
                } else if (heads) {
                    int b = row >> 11, t = row & 2047;
                    int h = col >> 6, d = col & 63;
                    Co[((((size_t)b * H_ + h) * T_ + t) << 6) + d] = v;
                } else {
                    Co[(size_t)row * Nout + col] = v;
                }
            }
}

// ------------------------- scalar SGEMM (conv + final head) -----------------
__global__ __launch_bounds__(256) void sgemm(
    const float* __restrict__ A, const float* __restrict__ Bm,
    const float* __restrict__ bias, float* __restrict__ C,
    int M, int N, int K, int act)
{
    __shared__ float As[16][132];
    __shared__ float Bs[16][64];
    const int tid = threadIdx.x;
    const int tx = tid & 15, ty = tid >> 4;
    const int m0 = blockIdx.y * 128;
    int n0 = blockIdx.x * 64;

    float acc[8][4], cmp[8][4];
    #pragma unroll
    for (int i = 0; i < 8; i++)
        #pragma unroll
        for (int j = 0; j < 4; j++) { acc[i][j] = 0.f; cmp[i][j] = 0.f; }

    const int arow0 = tid >> 2, ac4 = (tid & 3) * 4;
    const int brow = tid >> 4, bc4 = (tid & 15) * 4;
    const int bcol = n0 + bc4;

    for (int k0 = 0; k0 < K; k0 += 16) {
        #pragma unroll
        for (int s = 0; s < 2; s++) {
            int row = arow0 + s * 64;
            float4 a = *(const float4*)(A + (size_t)(m0 + row) * K + k0 + ac4);
            As[ac4 + 0][row] = a.x; As[ac4 + 1][row] = a.y;
            As[ac4 + 2][row] = a.z; As[ac4 + 3][row] = a.w;
        }
        float4 bv;
        if (bcol < N) bv = *(const float4*)(Bm + (size_t)(k0 + brow) * N + bcol);
        else          bv = make_float4(0.f, 0.f, 0.f, 0.f);
        *(float4*)(&Bs[brow][bc4]) = bv;
        __syncthreads();
        float pb[8][4];
        #pragma unroll
        for (int kk = 0; kk < 16; kk++) {
            float4 a0 = *(const float4*)(&As[kk][ty * 8]);
            float4 a1 = *(const float4*)(&As[kk][ty * 8 + 4]);
            float4 bb = *(const float4*)(&Bs[kk][tx * 4]);
            float av[8] = {a0.x, a0.y, a0.z, a0.w, a1.x, a1.y, a1.z, a1.w};
            float bw[4] = {bb.x, bb.y, bb.z, bb.w};
            if (kk == 0) {
                #pragma unroll
                for (int i = 0; i < 8; i++)
                    #pragma unroll
                    for (int j = 0; j < 4; j++) pb[i][j] = av[i] * bw[j];
            } else {
                #pragma unroll
                for (int i = 0; i < 8; i++)
                    #pragma unroll
                    for (int j = 0; j < 4; j++) pb[i][j] = fmaf(av[i], bw[j], pb[i][j]);
            }
        }
        #pragma unroll
        for (int i = 0; i < 8; i++)
            #pragma unroll
            for (int j = 0; j < 4; j++) KAHAN(acc[i][j], cmp[i][j], pb[i][j]);
        __syncthreads();
    }

    #pragma unroll
    for (int i = 0; i < 8; i++) {
        int row = m0 + ty * 8 + i;
        #pragma unroll
        for (int j = 0; j < 4; j++) {
            int col = n0 + tx * 4 + j;
            if (col >= N) continue;
            float v = acc[i][j] + cmp[i][j];
            if (bias) v += bias[col];
            if (act == 1) v = fmaxf(v, 0.f);
            C[(size_t)row * N + col] = v;
        }
    }
}

// ------------------------- LayerNorm (emits bf16x3 splits) -------------------
__global__ __launch_bounds__(256) void ln_kernel(
    const float* __restrict__ x, const float* __restrict__ g,
    const float* __restrict__ bb,
    __nv_bfloat16* __restrict__ d0, __nv_bfloat16* __restrict__ d1,
    __nv_bfloat16* __restrict__ d2)
{
    __shared__ float sh[8];
    int row = blockIdx.x, tid = threadIdx.x;
    const float* xr = x + (size_t)row * DIM;
    float v0 = xr[tid], v1 = xr[tid + 256];
    float s = v0 + v1;
    #pragma unroll
    for (int o = 16; o; o >>= 1) s += __shfl_down_sync(0xffffffffu, s, o);
    if ((tid & 31) == 0) sh[tid >> 5] = s;
    __syncthreads();
    if (tid < 32) {
        float t = (tid < 8) ? sh[tid] : 0.f;
        #pragma unroll
        for (int o = 4; o; o >>= 1) t += __shfl_down_sync(0xffffffffu, t, o);
        if (tid == 0) sh[0] = t;
    }
    __syncthreads();
    float mean = sh[0] * (1.f / DIM);
    __syncthreads();
    float dd0 = v0 - mean, dd1 = v1 - mean;
    float s2 = dd0 * dd0 + dd1 * dd1;
    #pragma unroll
    for (int o = 16; o; o >>= 1) s2 += __shfl_down_sync(0xffffffffu, s2, o);
    if ((tid & 31) == 0) sh[tid >> 5] = s2;
    __syncthreads();
    if (tid < 32) {
        float t = (tid < 8) ? sh[tid] : 0.f;
        #pragma unroll
        for (int o = 4; o; o >>= 1) t += __shfl_down_sync(0xffffffffu, t, o);
        if (tid == 0) sh[0] = t;
    }
    __syncthreads();
    float inv = 1.f / sqrtf(sh[0] * (1.f / DIM) + 1e-5f);
    float y0 = dd0 * inv * g[tid]       + bb[tid];
    float y1 = dd1 * inv * g[tid + 256] + bb[tid + 256];
    __nv_bfloat16 b0, b1, b2;
    size_t o0 = (size_t)row * DIM + tid;
    split3(y0, b0, b1, b2);
    d0[o0] = b0; d1[o0] = b1; d2[o0] = b2;
    split3(y1, b0, b1, b2);
    d0[o0 + 256] = b0; d1[o0 + 256] = b1; d2[o0 + 256] = b2;
}

// ------------------------- LSH hashing --------------------------------------
#define TCH 16
__global__ __launch_bounds__(128) void hash_kernel(
    const float* __restrict__ qk, const float* __restrict__ rot, int* __restrict__ bkt)
{
    __shared__ float q[4][DH];
    int blk = blockIdx.x;
    int bh = blk / (T_ / TCH);
    int t0 = (blk % (T_ / TCH)) * TCH;
    int tid = threadIdx.x;
    int h = tid >> 4, j = tid & 15;
    float rv[64];
    #pragma unroll
    for (int f = 0; f < 64; f++) rv[f] = rot[f * 128 + h * 16 + j];

    for (int tg = 0; tg < TCH; tg += 4) {
        __syncthreads();
        for (int idx = tid; idx < 4 * DH; idx += 128) {
            int r = idx >> 6, d = idx & 63;
            q[r][d] = qk[((size_t)bh * T_ + t0 + tg + r) * DH + d];
        }
        __syncthreads();
        float a0 = 0.f, a1 = 0.f, a2 = 0.f, a3 = 0.f;
        float c0 = 0.f, c1 = 0.f, c2 = 0.f, c3 = 0.f;
        #pragma unroll
        for (int f = 0; f < 64; f++) {
            float r = rv[f];
            float p0 = q[0][f] * r; KAHAN(a0, c0, p0);
            float p1 = q[1][f] * r; KAHAN(a1, c1, p1);
            float p2 = q[2][f] * r; KAHAN(a2, c2, p2);
            float p3 = q[3][f] * r; KAHAN(a3, c3, p3);
        }
        float vals[4] = {a0 + c0, a1 + c1, a2 + c2, a3 + c3};
        #pragma unroll
        for (int r = 0; r < 4; r++) {
            float v = vals[r]; int idx = j;
            float nv = -v;
            if (nv > v) { v = nv; idx = j + 16; }
            #pragma unroll
            for (int o = 8; o; o >>= 1) {
                float ov = __shfl_down_sync(0xffffffffu, v, o, 16);
                int   oi = __shfl_down_sync(0xffffffffu, idx, o, 16);
                if (ov > v || (ov == v && oi < idx)) { v = ov; idx = oi; }
            }
            if (j == 0) bkt[(size_t)bh * NHT + h * T_ + t0 + tg + r] = idx + h * NB;
        }
    }
}

// ------------------------- stable counting sort ------------------------------
__global__ __launch_bounds__(256) void sort_kernel(
    const int* __restrict__ bkt, int* __restrict__ st)
{
    __shared__ int hist[256];
    __shared__ int off[256];
    int bh = blockIdx.x, tid = threadIdx.x;
    const int* bb = bkt + (size_t)bh * NHT;
    hist[tid] = 0;
    __syncthreads();
    for (int i = tid; i < NHT; i += 256) atomicAdd(&hist[bb[i]], 1);
    __syncthreads();
    if (tid == 0) {
        int s = 0;
        for (int i = 0; i < 256; i++) { off[i] = s; s += hist[i]; }
    }
    __syncthreads();
    int beta = tid, h = tid >> 5;
    int o = off[beta];
    int* out2 = st + (size_t)bh * NHT;
    int base = h * T_;
    for (int k = 0; k < T_; k++)
        if (bb[base + k] == beta) out2[o++] = base + k;
}

// ------------------------- chunked LSH attention (plain fp32 accum) ---------
#define RS 68
#define DS 129
__global__ __launch_bounds__(128) void attn_kernel(
    const float* __restrict__ qk, const float* __restrict__ vg,
    const int* __restrict__ st, float* __restrict__ og, float* __restrict__ lgg)
{
    extern __shared__ float sm[];
    float* r     = sm;
    float* vv    = r + 128 * RS;
    float* dots  = vv + 128 * 64;
    float* inorm = dots + 64 * DS;
    float* logit = inorm + 128;
    int*   kpos  = (int*)(logit + 64);
    int*   qh    = kpos + 128;

    int tid = threadIdx.x;
    int bh = blockIdx.x >> 8, c = blockIdx.x & 255;
    int cp = (c + NCH - 1) & 255;

    {
        int lc = (tid < 64) ? c : cp;
        int tk = st[(size_t)bh * NHT + lc * 64 + (tid & 63)];
        kpos[tid] = tk & (T_ - 1);
        if (tid < 64) qh[tid] = tk >> 11;
    }
    __syncthreads();

    const float* qb = qk + ((size_t)bh << 17);
    const float* vb = vg + ((size_t)bh << 17);
    for (int it = 0; it < 64; it++) {
        int idx = it * 128 + tid;
        int jj = idx >> 6, d = idx & 63;
        int pos = kpos[jj];
        r[jj * RS + d]    = qb[(pos << 6) + d];
        vv[(jj << 6) + d] = vb[(pos << 6) + d];
    }
    __syncthreads();
    {
        float s = 0.f, cs = 0.f;
        #pragma unroll 8
        for (int d = 0; d < 64; d++) {
            float x = r[tid * RS + d];
            float p = x * x; KAHAN(s, cs, p);
        }
        inorm[tid] = 1.f / fmaxf(sqrtf(s + cs), 1e-12f);
    }
    __syncthreads();

    int tx = tid & 15, ty = tid >> 4;
    float acc[8][8];
    #pragma unroll
    for (int i = 0; i < 8; i++)
        #pragma unroll
        for (int m = 0; m < 8; m++) acc[i][m] = 0.f;

    for (int d = 0; d < 64; d++) {
        float kv[8];
        #pragma unroll
        for (int m = 0; m < 8; m++) kv[m] = r[(tx + 16 * m) * RS + d];
        #pragma unroll
        for (int i = 0; i < 8; i++) {
            float q = r[(ty * 8 + i) * RS + d];
            #pragma unroll
            for (int m = 0; m < 8; m++) acc[i][m] = fmaf(q, kv[m], acc[i][m]);
        }
    }
    #pragma unroll
    for (int i = 0; i < 8; i++) {
        int row = ty * 8 + i; int rp = kpos[row];
        #pragma unroll
        for (int m = 0; m < 8; m++) {
            int col = tx + 16 * m;
            float dv = acc[i][m] * inorm[col] * 0.125f;
            if (rp == kpos[col]) dv = -5e4f;
            dots[row * DS + col] = dv;
        }
    }
    __syncthreads();

    if (tid < 64) {
        float mx = -1e30f;
        #pragma unroll 8
        for (int j2 = 0; j2 < 128; j2++) mx = fmaxf(mx, dots[tid * DS + j2]);
        float s = 0.f;
        #pragma unroll 8
        for (int j2 = 0; j2 < 128; j2++) s += expf(dots[tid * DS + j2] - mx);
        float lg = mx + logf(s);
        logit[tid] = lg;
        lgg[((size_t)bh * NH + qh[tid]) * T_ + kpos[tid]] = lg;
    }
    __syncthreads();
    for (int it = 0; it < 64; it++) {
        int idx = it * 128 + tid; int i = idx >> 7, j2 = idx & 127;
        dots[i * DS + j2] = expf(dots[i * DS + j2] - logit[i]);
    }
    __syncthreads();

    float a2[8][4];
    #pragma unroll
    for (int i = 0; i < 8; i++)
        #pragma unroll
        for (int m = 0; m < 4; m++) a2[i][m] = 0.f;
    for (int j2 = 0; j2 < 128; j2++) {
        float vw[4];
        #pragma unroll
        for (int m = 0; m < 4; m++) vw[m] = vv[(j2 << 6) + tx + 16 * m];
        #pragma unroll
        for (int i = 0; i < 8; i++) {
            float p = dots[(ty * 8 + i) * DS + j2];
            #pragma unroll
            for (int m = 0; m < 4; m++) a2[i][m] = fmaf(p, vw[m], a2[i][m]);
        }
    }
    #pragma unroll
    for (int i = 0; i < 8; i++) {
        int row = ty * 8 + i;
        size_t base = (((size_t)bh * NH + qh[row]) * T_ + kpos[row]) << 6;
        #pragma unroll
        for (int m = 0; m < 4; m++) og[base + tx + 16 * m] = a2[i][m];
    }
}

// ------------------------- combine hash rounds (emits bf16x3 splits) --------
__global__ __launch_bounds__(64) void combine_kernel(
    const float* __restrict__ og, const float* __restrict__ lgg,
    __nv_bfloat16* __restrict__ d0, __nv_bfloat16* __restrict__ d1,
    __nv_bfloat16* __restrict__ d2)
{
    __shared__ float w[8];
    int bh = blockIdx.x >> 11, pos = blockIdx.x & 2047;
    int tid = threadIdx.x;
    if (tid == 0) {
        float v[8]; float mx = -1e30f;
        #pragma unroll
        for (int h = 0; h < 8; h++) {
            v[h] = lgg[((size_t)bh * NH + h) * T_ + pos];
            mx = fmaxf(mx, v[h]);
        }
        float s = 0.f;
        #pragma unroll
        for (int h = 0; h < 8; h++) { v[h] = expf(v[h] - mx); s += v[h]; }
        float is = 1.f / s;
        #pragma unroll
        for (int h = 0; h < 8; h++) w[h] = v[h] * is;
    }
    __syncthreads();
    float acc = 0.f, cc = 0.f;
    #pragma unroll
    for (int h = 0; h < 8; h++) {
        float p = w[h] * og[(((size_t)bh * NH + h) * T_ + pos) * 64 + tid];
        KAHAN(acc, cc, p);
    }
    int b = bh >> 3, hd = bh & 7;
    size_t o = ((size_t)(b * T_ + pos)) * DIM + hd * 64 + tid;
    __nv_bfloat16 b0, b1, b2;
    split3(acc + cc, b0, b1, b2);
    d0[o] = b0; d1[o] = b1; d2[o] = b2;
}

// ------------------------- frontend helpers ---------------------------------
__global__ void wt_kernel(const float* __restrict__ w, float* __restrict__ wT)
{
    int idx = blockIdx.x * 256 + threadIdx.x;
    int c = idx / DIM, o2 = idx - c * DIM;
    wT[idx] = (c < 687) ? w[(size_t)o2 * 687 + c] : 0.f;
}

__global__ void im2col_kernel(const float* __restrict__ spec, float* __restrict__ im)
{
    int idx = blockIdx.x * 256 + threadIdx.x;
    int row = idx / KC, c = idx - row * KC;
    int b = row >> 11, t = row & 2047;
    float val = 0.f;
    if (c < 687) {
        int i = c / 3, k = c - i * 3;
        int tt = t + k - 1;
        if (tt >= 0 && tt < T_) val = spec[((size_t)b * T_ + tt) * 229 + i];
    }
    im[idx] = val;
}

__global__ void pe_kernel(float* __restrict__ x1, float* __restrict__ x2,
                          const float* __restrict__ per, const float* __restrict__ pec)
{
    int idx = blockIdx.x * 256 + threadIdx.x;
    int c = idx & 511;
    int t = (idx >> 9) & 2047;
    float p = (c < 256) ? per[(t >> 6) * 256 + c] : pec[(t & 63) * 256 + (c - 256)];
    float v = x1[idx] + p;
    x1[idx] = v; x2[idx] = v;
}

__global__ void avg_kernel(const float* __restrict__ a, const float* __restrict__ b,
                           float* __restrict__ y)
{
    int idx = blockIdx.x * 256 + threadIdx.x;
    y[idx] = 0.5f * (a[idx] + b[idx]);
}

// ------------------------- driver -------------------------------------------
extern "C" void kernel_launch(void* const* d_in, const int* in_sizes, int n_in,
                              void* d_out, int out_size)
{
    const float* spec   = (const float*)d_in[0];
    const float* conv_w = (const float*)d_in[1];
    const float* conv_b = (const float*)d_in[2];
    const float* pe_row = (const float*)d_in[3];
    const float* pe_col = (const float*)d_in[4];
    const float* lnA_g  = (const float*)d_in[5];
    const float* lnA_b  = (const float*)d_in[6];
    const float* wqk    = (const float*)d_in[7];
    const float* wv     = (const float*)d_in[8];
    const float* wo     = (const float*)d_in[9];
    const float* bo     = (const float*)d_in[10];
    const float* lnF_g  = (const float*)d_in[11];
    const float* lnF_b  = (const float*)d_in[12];
    const float* w1     = (const float*)d_in[13];
    const float* b1     = (const float*)d_in[14];
    const float* w2     = (const float*)d_in[15];
    const float* b2     = (const float*)d_in[16];
    const float* lin_w  = (const float*)d_in[17];
    const float* lin_b  = (const float*)d_in[18];
    const float* rot    = (const float*)d_in[19];
    float* out = (float*)d_out;

    float *x1, *x2, *tmp, *qk, *v, *im, *wT, *o, *lg;
    int *bk, *st;
    __nv_bfloat16 *a0, *a1, *a2, *f0, *f1, *f2, *bt0, *bt1, *bt2;
    cudaGetSymbolAddress((void**)&x1, g_x1);
    cudaGetSymbolAddress((void**)&x2, g_x2);
    cudaGetSymbolAddress((void**)&tmp, g_tmp);
    cudaGetSymbolAddress((void**)&qk, g_qk);
    cudaGetSymbolAddress((void**)&v,  g_v);
    cudaGetSymbolAddress((void**)&im, g_im);
    cudaGetSymbolAddress((void**)&wT, g_wT);
    cudaGetSymbolAddress((void**)&o,  g_o);
    cudaGetSymbolAddress((void**)&lg, g_lg);
    cudaGetSymbolAddress((void**)&bk, g_bk);
    cudaGetSymbolAddress((void**)&st, g_st);
    cudaGetSymbolAddress((void**)&a0, g_a0);
    cudaGetSymbolAddress((void**)&a1, g_a1);
    cudaGetSymbolAddress((void**)&a2, g_a2);
    cudaGetSymbolAddress((void**)&f0, g_f0);
    cudaGetSymbolAddress((void**)&f1, g_f1);
    cudaGetSymbolAddress((void**)&f2, g_f2);
    cudaGetSymbolAddress((void**)&bt0, g_bt0);
    cudaGetSymbolAddress((void**)&bt1, g_bt1);
    cudaGetSymbolAddress((void**)&bt2, g_bt2);

    size_t asmem = (size_t)(128 * RS + 128 * 64 + 64 * DS + 128 + 64 + 128 + 64) * 4;
    cudaFuncSetAttribute(attn_kernel, cudaFuncAttributeMaxDynamicSharedMemorySize, (int)asmem);
    cudaFuncSetAttribute(tgemm, cudaFuncAttributeMaxDynamicSharedMemorySize, TG_SMEM);

    // frontend
    wt_kernel<<<(KC * DIM) / 256, 256>>>(conv_w, wT);
    im2col_kernel<<<(BT * KC) / 256, 256>>>(spec, im);
    sgemm<<<dim3(DIM / 64, BT / 128), 256>>>(im, wT, conv_b, x1, BT, DIM, KC, 1);
    pe_kernel<<<(BT * DIM) / 256, 256>>>(x1, x2, pe_row, pe_col);

    for (int i = 0; i < 8; i++) {
        ln_kernel<<<BT, 256>>>(x2, lnA_g + i * DIM, lnA_b + i * DIM, a0, a1, a2);
        cvt3b_kernel<<<(DIM * DIM + 255) / 256, 256>>>(wqk + (size_t)i * DIM * DIM, DIM, DIM, 0, bt0, bt1, bt2);
        cvt3b_kernel<<<(DIM * DIM + 255) / 256, 256>>>(wv + (size_t)i * DIM * DIM, DIM, DIM, DIM, bt0, bt1, bt2);
        tgemm<<<dim3(16, 32), 256, TG_SMEM>>>(a0, a1, a2, bt0, bt1, bt2,
                                              nullptr, nullptr, qk, v,
                                              nullptr, nullptr, nullptr, DIM, DIM, 0, 1, DIM);
        hash_kernel<<<BH * (T_ / TCH), 128>>>(qk, rot + (size_t)i * 64 * 128, bk);
        sort_kernel<<<BH, 256>>>(bk, st);
        attn_kernel<<<BH * NCH, 128, asmem>>>(qk, v, st, o, lg);
        combine_kernel<<<BH * T_, 64>>>(o, lg, a0, a1, a2);
        cvt3b_kernel<<<(DIM * DIM + 255) / 256, 256>>>(wo + (size_t)i * DIM * DIM, DIM, DIM, 0, bt0, bt1, bt2);
        tgemm<<<dim3(8, 32), 256, TG_SMEM>>>(a0, a1, a2, bt0, bt1, bt2,
                                             bo + i * DIM, x1, x1, nullptr,
                                             nullptr, nullptr, nullptr, DIM, DIM, 0, 0, 0);
        ln_kernel<<<BT, 256>>>(x1, lnF_g + i * DIM, lnF_b + i * DIM, a0, a1, a2);
        cvt3b_kernel<<<(DIM * FF + 255) / 256, 256>>>(w1 + (size_t)i * DIM * FF, DIM, FF, 0, bt0, bt1, bt2);
        tgemm<<<dim3(32, 32), 256, TG_SMEM>>>(a0, a1, a2, bt0, bt1, bt2,
                                              b1 + i * FF, nullptr, nullptr, nullptr,
                                              f0, f1, f2, DIM, FF, 2, 0, 0);
        cvt3b_kernel<<<(FF * DIM + 255) / 256, 256>>>(w2 + (size_t)i * FF * DIM, FF, DIM, 0, bt0, bt1, bt2);
        tgemm<<<dim3(8, 32), 256, TG_SMEM>>>(f0, f1, f2, bt0, bt1, bt2,
                                             b2 + i * DIM, x2, x2, nullptr,
                                             nullptr, nullptr, nullptr, FF, DIM, 0, 0, 0);
    }

    avg_kernel<<<(BT * DIM) / 256, 256>>>(x1, x2, tmp);
    sgemm<<<dim3(2, 32), 256>>>(tmp, lin_w, lin_b, out, BT, 88, DIM, 0);
}

// round 16
// speedup vs baseline: 2.1938x; 1.0122x over previous
#include <cuda_runtime.h>
#include <cuda_bf16.h>
#include <math.h>
#include <stdint.h>

#define B_   2
#define T_   2048
#define BT   4096
#define DIM  512
#define H_   8
#define DH   64
#define NH   8
#define NB   32
#define NCH  256
#define BH   16
#define NHT  16384
#define KC   704
#define FF   2048

#define KAHAN(s, c, p) { float y_ = (p) - (c); float t_ = (s) + y_; (c) = (t_ - (s)) - y_; (s) = t_; }

// ------------------------- scratch (static device) -------------------------
__device__ float g_x1[BT*DIM];
__device__ float g_x2[BT*DIM];
__device__ float g_tmp[BT*DIM];
__device__ float g_qk[BT*DIM];
__device__ float g_v [BT*DIM];
__device__ float g_im[BT*KC];
__device__ int   g_bk[BH*NHT];
__device__ int   g_st[BH*NHT];
__device__ float g_o [BH*NHT*DH];
__device__ float g_lg[BH*NHT];
// bf16 split buffers
__device__ __nv_bfloat16 g_a0[BT*DIM];
__device__ __nv_bfloat16 g_a1[BT*DIM];
__device__ __nv_bfloat16 g_a2[BT*DIM];
__device__ __nv_bfloat16 g_f0[BT*FF];
__device__ __nv_bfloat16 g_f1[BT*FF];
__device__ __nv_bfloat16 g_f2[BT*FF];
__device__ __nv_bfloat16 g_bt0[2*1024*1024];
__device__ __nv_bfloat16 g_bt1[2*1024*1024];
__device__ __nv_bfloat16 g_bt2[2*1024*1024];

// ------------------------- warp-mma helpers ---------------------------------
__device__ __forceinline__ uint32_t smem_u32(const void* p) {
    uint32_t a;
    asm("{ .reg .u64 t; cvta.to.shared.u64 t, %1; cvt.u32.u64 %0, t; }" : "=r"(a) : "l"(p));
    return a;
}
__device__ __forceinline__ void ldsm_x4(uint32_t* r, uint32_t addr) {
    asm volatile("ldmatrix.sync.aligned.m8n8.x4.shared.b16 {%0,%1,%2,%3}, [%4];"
        : "=r"(r[0]), "=r"(r[1]), "=r"(r[2]), "=r"(r[3]) : "r"(addr));
}
__device__ __forceinline__ void ldsm_x2(uint32_t* r, uint32_t addr) {
    asm volatile("ldmatrix.sync.aligned.m8n8.x2.shared.b16 {%0,%1}, [%2];"
        : "=r"(r[0]), "=r"(r[1]) : "r"(addr));
}
__device__ __forceinline__ void mma_bf16(float* d, const uint32_t* a, const uint32_t* b) {
    asm volatile("mma.sync.aligned.m16n8k16.row.col.f32.bf16.bf16.f32 "
        "{%0,%1,%2,%3}, {%4,%5,%6,%7}, {%8,%9}, {%0,%1,%2,%3};"
        : "+f"(d[0]), "+f"(d[1]), "+f"(d[2]), "+f"(d[3])
        : "r"(a[0]), "r"(a[1]), "r"(a[2]), "r"(a[3]), "r"(b[0]), "r"(b[1]));
}
__device__ __forceinline__ void cp16(uint32_t dst, const void* src) {
    size_t g = (size_t)__cvta_generic_to_global(src);
    asm volatile("cp.async.cg.shared.global [%0], [%1], 16;" :: "r"(dst), "l"(g));
}

// ------------------------- fp32 -> bf16x3 splits -----------------------------
__device__ __forceinline__ void split3(float v, __nv_bfloat16& b0, __nv_bfloat16& b1,
                                       __nv_bfloat16& b2) {
    b0 = __float2bfloat16(v);
    float r = v - __bfloat162float(b0);
    b1 = __float2bfloat16(r);
    float r2 = r - __bfloat162float(b1);
    b2 = __float2bfloat16(r2);
}
// contiguous split (im2col output)
__global__ void cvt3a_kernel(const float* __restrict__ src, int n,
                             __nv_bfloat16* __restrict__ d0, __nv_bfloat16* __restrict__ d1,
                             __nv_bfloat16* __restrict__ d2)
{
    int i = blockIdx.x * 256 + threadIdx.x;
    if (i >= n) return;
    __nv_bfloat16 b0, b1, b2;
    split3(src[i], b0, b1, b2);
    d0[i] = b0; d1[i] = b1; d2[i] = b2;
}
// conv weight (DIM, 687) -> [DIM, KC] bf16x3, zero-padded (coalesced both ways)
__global__ void cvtw_kernel(const float* __restrict__ w,
                            __nv_bfloat16* __restrict__ d0, __nv_bfloat16* __restrict__ d1,
                            __nv_bfloat16* __restrict__ d2)
{
    int idx = blockIdx.x * 256 + threadIdx.x;          // DIM*KC
    int n = idx / KC, c = idx - n * KC;
    float v = (c < 687) ? w[(size_t)n * 687 + c] : 0.f;
    __nv_bfloat16 b0, b1, b2;
    split3(v, b0, b1, b2);
    d0[idx] = b0; d1[idx] = b1; d2[idx] = b2;
}
// W [Kd, Nd] fp32 -> Bt splits [rowoff+Nd, Kd] bf16, smem tile transpose.
// grid (Kd/32, Nd/32), 256 threads (32x8).
__global__ __launch_bounds__(256) void cvt3b_kernel(
    const float* __restrict__ W, int Kd, int Nd, int rowoff,
    __nv_bfloat16* __restrict__ d0, __nv_bfloat16* __restrict__ d1,
    __nv_bfloat16* __restrict__ d2)
{
    __shared__ float tile[32][33];
    int k0 = blockIdx.x * 32, n0 = blockIdx.y * 32;
    int tx = threadIdx.x & 31, ty = threadIdx.x >> 5;
    #pragma unroll
    for (int i = 0; i < 4; i++)
        tile[ty + i * 8][tx] = W[(size_t)(k0 + ty + i * 8) * Nd + n0 + tx];
    __syncthreads();
    #pragma unroll
    for (int i = 0; i < 4; i++) {
        int nrow = n0 + ty + i * 8;
        float v = tile[tx][ty + i * 8];
        __nv_bfloat16 b0, b1, b2;
        split3(v, b0, b1, b2);
        size_t o = (size_t)(rowoff + nrow) * Kd + k0 + tx;
        d0[o] = b0; d1[o] = b1; d2[o] = b2;
    }
}

// ------------------------- tensor-core bf16x3 GEMM --------------------------
// BM=128, BN=64, BK=32 per stage, 2-stage cp.async pipeline, 2 CTAs/SM.
#define ASTRIDE 40
#define ABYTES (3 * 128 * ASTRIDE * 2)
#define BBYTES (3 * 64 * ASTRIDE * 2)
#define STAGEB (ABYTES + BBYTES)
#define TG_SMEM (2 * STAGEB)
__global__ __launch_bounds__(256, 2) void tgemm(
    const __nv_bfloat16* __restrict__ a0, const __nv_bfloat16* __restrict__ a1,
    const __nv_bfloat16* __restrict__ a2,
    const __nv_bfloat16* __restrict__ bt0, const __nv_bfloat16* __restrict__ bt1,
    const __nv_bfloat16* __restrict__ bt2,
    const float* __restrict__ bias, const float* __restrict__ resid,
    float* __restrict__ C, float* __restrict__ C2,
    __nv_bfloat16* __restrict__ s0, __nv_bfloat16* __restrict__ s1,
    __nv_bfloat16* __restrict__ s2,
    int K, int Nout, int act, int heads, int Nsplit)
{
    extern __shared__ char smem[];
    const int tid = threadIdx.x;
    const int L = tid & 31, w = tid >> 5;
    const int mrow0 = (w & 3) * 32, ncol0 = (w >> 2) * 32;
    const int m0 = blockIdx.y * 128;
    const int n0 = blockIdx.x * 64;

    const uint32_t base = smem_u32(smem);
    const int arow = (L & 7) + ((L >> 3) & 1) * 8;
    const int acol = (L >> 4) * 8;
    const int brow = L & 7, bcol = ((L >> 3) & 1) * 8;

    const __nv_bfloat16* asp[3] = {a0, a1, a2};
    const __nv_bfloat16* bsp[3] = {bt0, bt1, bt2};

#define ISSUE_CHUNK(c, buf) do { \
    const int k0_ = (c) << 5; \
    const uint32_t sA_ = base + (buf) * STAGEB; \
    const uint32_t sB_ = sA_ + ABYTES; \
    _Pragma("unroll") \
    for (int it = 0; it < 6; it++) { \
        int idx = tid + it * 256; \
        int sp = idx >> 9, rem = idx & 511; \
        int row = rem >> 2, seg = rem & 3; \
        uint32_t dst = sA_ + ((sp * (128 * ASTRIDE) + row * ASTRIDE + seg * 8) << 1); \
        cp16(dst, asp[sp] + (size_t)(m0 + row) * K + k0_ + seg * 8); \
    } \
    _Pragma("unroll") \
    for (int it = 0; it < 3; it++) { \
        int idx = tid + it * 256; \
        int sp = idx >> 8, rem = idx & 255; \
        int row = rem >> 2, seg = rem & 3; \
        uint32_t dst = sB_ + ((sp * (64 * ASTRIDE) + row * ASTRIDE + seg * 8) << 1); \
        cp16(dst, bsp[sp] + (size_t)(n0 + row) * K + k0_ + seg * 8); \
    } \
    asm volatile("cp.async.commit_group;" ::: "memory"); \
} while (0)

    float acc[32], macc[32];
    #pragma unroll
    for (int i = 0; i < 32; i++) { acc[i] = 0.f; macc[i] = 0.f; }

    const int nch = K >> 5;
    ISSUE_CHUNK(0, 0);

    for (int c = 0; c < nch; c++) {
        const int buf = c & 1;
        if (c + 1 < nch) {
            ISSUE_CHUNK(c + 1, buf ^ 1);
            asm volatile("cp.async.wait_group 1;" ::: "memory");
        } else {
            asm volatile("cp.async.wait_group 0;" ::: "memory");
        }
        __syncthreads();

        const uint32_t Ab = base + buf * STAGEB;
        const uint32_t Bb = Ab + ABYTES;

        #pragma unroll
        for (int ks = 0; ks < 2; ks++) {
            const int kof = ks * 16;
            uint32_t afr[3][2][4];
            #pragma unroll
            for (int sp = 0; sp < 3; sp++)
                #pragma unroll
                for (int mt = 0; mt < 2; mt++)
                    ldsm_x4(afr[sp][mt],
                            Ab + ((sp * (128 * ASTRIDE) + (mrow0 + mt * 16 + arow) * ASTRIDE
                                   + kof + acol) << 1));
            #pragma unroll
            for (int bj = 0; bj < 3; bj++) {
                uint32_t bfr[4][2];
                #pragma unroll
                for (int nt = 0; nt < 4; nt++)
                    ldsm_x2(bfr[nt],
                            Bb + ((bj * (64 * ASTRIDE) + (ncol0 + nt * 8 + brow) * ASTRIDE
                                   + kof + bcol) << 1));
                #pragma unroll
                for (int ai = 0; ai < 3; ai++) {
                    if (ai + bj > 2) break;
                    #pragma unroll
                    for (int mt = 0; mt < 2; mt++)
                        #pragma unroll
                        for (int nt = 0; nt < 4; nt++)
                            mma_bf16(&acc[(mt * 4 + nt) * 4], afr[ai][mt], bfr[nt]);
                }
            }
        }
        __syncthreads();

        #pragma unroll
        for (int i = 0; i < 32; i++) {
            macc[i] += acc[i];
            acc[i] = 0.f;
        }
    }

    // ------------- epilogue -------------
    int n0c = n0;
    float* Co = C;
    if (Nsplit && n0c >= Nsplit) { Co = C2; n0c -= Nsplit; }
    #pragma unroll
    for (int mt = 0; mt < 2; mt++)
        #pragma unroll
        for (int nt = 0; nt < 4; nt++)
            #pragma unroll
            for (int r = 0; r < 4; r++) {
                int i = (mt * 4 + nt) * 4 + r;
                float v = macc[i];
                int row = m0 + mrow0 + mt * 16 + (L >> 2) + ((r >> 1) * 8);
                int col = n0c + ncol0 + nt * 8 + ((L & 3) * 2) + (r & 1);
                if (bias) v += bias[col];
                if (act == 1) v = fmaxf(v, 0.f);
                else if (act == 2) v = 0.5f * v * (1.f + erff(v * 0.70710678118654752f));
                if (resid) v += resid[(size_t)row * Nout + col];
                if (s0) {
                    __nv_bfloat16 b0, b1, b2;
                    split3(v, b0, b1, b2);
                    size_t o = (size_t)row * Nout + col;
                    s0[o] = b0; s1[o] = b1; s2[o] = b2;
                } else if (heads) {
                    int b = row >> 11, t = row & 2047;
                    int h = col >> 6, d = col & 63;
                    Co[((((size_t)b * H_ + h) * T_ + t) << 6) + d] = v;
                } else {
                    Co[(size_t)row * Nout + col] = v;
                }
            }
}

// ------------------------- scalar SGEMM (final head only) -------------------
__global__ __launch_bounds__(256) void sgemm(
    const float* __restrict__ A, const float* __restrict__ Bm,
    const float* __restrict__ bias, float* __restrict__ C,
    int M, int N, int K, int act)
{
    __shared__ float As[16][132];
    __shared__ float Bs[16][64];
    const int tid = threadIdx.x;
    const int tx = tid & 15, ty = tid >> 4;
    const int m0 = blockIdx.y * 128;
    int n0 = blockIdx.x * 64;

    float acc[8][4], cmp[8][4];
    #pragma unroll
    for (int i = 0; i < 8; i++)
        #pragma unroll
        for (int j = 0; j < 4; j++) { acc[i][j] = 0.f; cmp[i][j] = 0.f; }

    const int arow0 = tid >> 2, ac4 = (tid & 3) * 4;
    const int brow = tid >> 4, bc4 = (tid & 15) * 4;
    const int bcol = n0 + bc4;

    for (int k0 = 0; k0 < K; k0 += 16) {
        #pragma unroll
        for (int s = 0; s < 2; s++) {
            int row = arow0 + s * 64;
            float4 a = *(const float4*)(A + (size_t)(m0 + row) * K + k0 + ac4);
            As[ac4 + 0][row] = a.x; As[ac4 + 1][row] = a.y;
            As[ac4 + 2][row] = a.z; As[ac4 + 3][row] = a.w;
        }
        float4 bv;
        if (bcol < N) bv = *(const float4*)(Bm + (size_t)(k0 + brow) * N + bcol);
        else          bv = make_float4(0.f, 0.f, 0.f, 0.f);
        *(float4*)(&Bs[brow][bc4]) = bv;
        __syncthreads();
        float pb[8][4];
        #pragma unroll
        for (int kk = 0; kk < 16; kk++) {
            float4 a0 = *(const float4*)(&As[kk][ty * 8]);
            float4 a1 = *(const float4*)(&As[kk][ty * 8 + 4]);
            float4 bb = *(const float4*)(&Bs[kk][tx * 4]);
            float av[8] = {a0.x, a0.y, a0.z, a0.w, a1.x, a1.y, a1.z, a1.w};
            float bw[4] = {bb.x, bb.y, bb.z, bb.w};
            if (kk == 0) {
                #pragma unroll
                for (int i = 0; i < 8; i++)
                    #pragma unroll
                    for (int j = 0; j < 4; j++) pb[i][j] = av[i] * bw[j];
            } else {
                #pragma unroll
                for (int i = 0; i < 8; i++)
                    #pragma unroll
                    for (int j = 0; j < 4; j++) pb[i][j] = fmaf(av[i], bw[j], pb[i][j]);
            }
        }
        #pragma unroll
        for (int i = 0; i < 8; i++)
            #pragma unroll
            for (int j = 0; j < 4; j++) KAHAN(acc[i][j], cmp[i][j], pb[i][j]);
        __syncthreads();
    }

    #pragma unroll
    for (int i = 0; i < 8; i++) {
        int row = m0 + ty * 8 + i;
        #pragma unroll
        for (int j = 0; j < 4; j++) {
            int col = n0 + tx * 4 + j;
            if (col >= N) continue;
            float v = acc[i][j] + cmp[i][j];
            if (bias) v += bias[col];
            if (act == 1) v = fmaxf(v, 0.f);
            C[(size_t)row * N + col] = v;
        }
    }
}

// ------------------------- LayerNorm (emits bf16x3 splits) -------------------
__global__ __launch_bounds__(256) void ln_kernel(
    const float* __restrict__ x, const float* __restrict__ g,
    const float* __restrict__ bb,
    __nv_bfloat16* __restrict__ d0, __nv_bfloat16* __restrict__ d1,
    __nv_bfloat16* __restrict__ d2)
{
    __shared__ float sh[8];
    int row = blockIdx.x, tid = threadIdx.x;
    const float* xr = x + (size_t)row * DIM;
    float v0 = xr[tid], v1 = xr[tid + 256];
    float s = v0 + v1;
    #pragma unroll
    for (int o = 16; o; o >>= 1) s += __shfl_down_sync(0xffffffffu, s, o);
    if ((tid & 31) == 0) sh[tid >> 5] = s;
    __syncthreads();
    if (tid < 32) {
        float t = (tid < 8) ? sh[tid] : 0.f;
        #pragma unroll
        for (int o = 4; o; o >>= 1) t += __shfl_down_sync(0xffffffffu, t, o);
        if (tid == 0) sh[0] = t;
    }
    __syncthreads();
    float mean = sh[0] * (1.f / DIM);
    __syncthreads();
    float dd0 = v0 - mean, dd1 = v1 - mean;
    float s2 = dd0 * dd0 + dd1 * dd1;
    #pragma unroll
    for (int o = 16; o; o >>= 1) s2 += __shfl_down_sync(0xffffffffu, s2, o);
    if ((tid & 31) == 0) sh[tid >> 5] = s2;
    __syncthreads();
    if (tid < 32) {
        float t = (tid < 8) ? sh[tid] : 0.f;
        #pragma unroll
        for (int o = 4; o; o >>= 1) t += __shfl_down_sync(0xffffffffu, t, o);
        if (tid == 0) sh[0] = t;
    }
    __syncthreads();
    float inv = 1.f / sqrtf(sh[0] * (1.f / DIM) + 1e-5f);
    float y0 = dd0 * inv * g[tid]       + bb[tid];
    float y1 = dd1 * inv * g[tid + 256] + bb[tid + 256];
    __nv_bfloat16 b0, b1, b2;
    size_t o0 = (size_t)row * DIM + tid;
    split3(y0, b0, b1, b2);
    d0[o0] = b0; d1[o0] = b1; d2[o0] = b2;
    split3(y1, b0, b1, b2);
    d0[o0 + 256] = b0; d1[o0 + 256] = b1; d2[o0 + 256] = b2;
}

// ------------------------- LSH hashing --------------------------------------
#define TCH 16
__global__ __launch_bounds__(128) void hash_kernel(
    const float* __restrict__ qk, const float* __restrict__ rot, int* __restrict__ bkt)
{
    __shared__ float q[4][DH];
    int blk = blockIdx.x;
    int bh = blk / (T_ / TCH);
    int t0 = (blk % (T_ / TCH)) * TCH;
    int tid = threadIdx.x;
    int h = tid >> 4, j = tid & 15;
    float rv[64];
    #pragma unroll
    for (int f = 0; f < 64; f++) rv[f] = rot[f * 128 + h * 16 + j];

    for (int tg = 0; tg < TCH; tg += 4) {
        __syncthreads();
        for (int idx = tid; idx < 4 * DH; idx += 128) {
            int r = idx >> 6, d = idx & 63;
            q[r][d] = qk[((size_t)bh * T_ + t0 + tg + r) * DH + d];
        }
        __syncthreads();
        float a0 = 0.f, a1 = 0.f, a2 = 0.f, a3 = 0.f;
        float c0 = 0.f, c1 = 0.f, c2 = 0.f, c3 = 0.f;
        #pragma unroll
        for (int f = 0; f < 64; f++) {
            float r = rv[f];
            float p0 = q[0][f] * r; KAHAN(a0, c0, p0);
            float p1 = q[1][f] * r; KAHAN(a1, c1, p1);
            float p2 = q[2][f] * r; KAHAN(a2, c2, p2);
            float p3 = q[3][f] * r; KAHAN(a3, c3, p3);
        }
        float vals[4] = {a0 + c0, a1 + c1, a2 + c2, a3 + c3};
        #pragma unroll
        for (int r = 0; r < 4; r++) {
            float v = vals[r]; int idx = j;
            float nv = -v;
            if (nv > v) { v = nv; idx = j + 16; }
            #pragma unroll
            for (int o = 8; o; o >>= 1) {
                float ov = __shfl_down_sync(0xffffffffu, v, o, 16);
                int   oi = __shfl_down_sync(0xffffffffu, idx, o, 16);
                if (ov > v || (ov == v && oi < idx)) { v = ov; idx = oi; }
            }
            if (j == 0) bkt[(size_t)bh * NHT + h * T_ + t0 + tg + r] = idx + h * NB;
        }
    }
}

// ------------------------- stable counting sort ------------------------------
__global__ __launch_bounds__(256) void sort_kernel(
    const int* __restrict__ bkt, int* __restrict__ st)
{
    __shared__ int hist[256];
    __shared__ int off[256];
    int bh = blockIdx.x, tid = threadIdx.x;
    const int* bb = bkt + (size_t)bh * NHT;
    hist[tid] = 0;
    __syncthreads();
    for (int i = tid; i < NHT; i += 256) atomicAdd(&hist[bb[i]], 1);
    __syncthreads();
    if (tid == 0) {
        int s = 0;
        for (int i = 0; i < 256; i++) { off[i] = s; s += hist[i]; }
    }
    __syncthreads();
    int beta = tid, h = tid >> 5;
    int o = off[beta];
    int* out2 = st + (size_t)bh * NHT;
    int base = h * T_;
    for (int k = 0; k < T_; k++)
        if (bb[base + k] == beta) out2[o++] = base + k;
}

// ------------------------- chunked LSH attention (plain fp32 accum) ---------
#define RS 68
#define DS 129
__global__ __launch_bounds__(128) void attn_kernel(
    const float* __restrict__ qk, const float* __restrict__ vg,
    const int* __restrict__ st, float* __restrict__ og, float* __restrict__ lgg)
{
    extern __shared__ float sm[];
    float* r     = sm;
    float* vv    = r + 128 * RS;
    float* dots  = vv + 128 * 64;
    float* inorm = dots + 64 * DS;
    float* logit = inorm + 128;
    int*   kpos  = (int*)(logit + 64);
    int*   qh    = kpos + 128;

    int tid = threadIdx.x;
    int bh = blockIdx.x >> 8, c = blockIdx.x & 255;
    int cp = (c + NCH - 1) & 255;

    {
        int lc = (tid < 64) ? c : cp;
        int tk = st[(size_t)bh * NHT + lc * 64 + (tid & 63)];
        kpos[tid] = tk & (T_ - 1);
        if (tid < 64) qh[tid] = tk >> 11;
    }
    __syncthreads();

    const float* qb = qk + ((size_t)bh << 17);
    const float* vb = vg + ((size_t)bh << 17);
    for (int it = 0; it < 64; it++) {
        int idx = it * 128 + tid;
        int jj = idx >> 6, d = idx & 63;
        int pos = kpos[jj];
        r[jj * RS + d]    = qb[(pos << 6) + d];
        vv[(jj << 6) + d] = vb[(pos << 6) + d];
    }
    __syncthreads();
    {
        float s = 0.f, cs = 0.f;
        #pragma unroll 8
        for (int d = 0; d < 64; d++) {
            float x = r[tid * RS + d];
            float p = x * x; KAHAN(s, cs, p);
        }
        inorm[tid] = 1.f / fmaxf(sqrtf(s + cs), 1e-12f);
    }
    __syncthreads();

    int tx = tid & 15, ty = tid >> 4;
    float acc[8][8];
    #pragma unroll
    for (int i = 0; i < 8; i++)
        #pragma unroll
        for (int m = 0; m < 8; m++) acc[i][m] = 0.f;

    for (int d = 0; d < 64; d++) {
        float kv[8];
        #pragma unroll
        for (int m = 0; m < 8; m++) kv[m] = r[(tx + 16 * m) * RS + d];
        #pragma unroll
        for (int i = 0; i < 8; i++) {
            float q = r[(ty * 8 + i) * RS + d];
            #pragma unroll
            for (int m = 0; m < 8; m++) acc[i][m] = fmaf(q, kv[m], acc[i][m]);
        }
    }
    #pragma unroll
    for (int i = 0; i < 8; i++) {
        int row = ty * 8 + i; int rp = kpos[row];
        #pragma unroll
        for (int m = 0; m < 8; m++) {
            int col = tx + 16 * m;
            float dv = acc[i][m] * inorm[col] * 0.125f;
            if (rp == kpos[col]) dv = -5e4f;
            dots[row * DS + col] = dv;
        }
    }
    __syncthreads();

    if (tid < 64) {
        float mx = -1e30f;
        #pragma unroll 8
        for (int j2 = 0; j2 < 128; j2++) mx = fmaxf(mx, dots[tid * DS + j2]);
        float s = 0.f;
        #pragma unroll 8
        for (int j2 = 0; j2 < 128; j2++) s += expf(dots[tid * DS + j2] - mx);
        float lg = mx + logf(s);
        logit[tid] = lg;
        lgg[((size_t)bh * NH + qh[tid]) * T_ + kpos[tid]] = lg;
    }
    __syncthreads();
    for (int it = 0; it < 64; it++) {
        int idx = it * 128 + tid; int i = idx >> 7, j2 = idx & 127;
        dots[i * DS + j2] = expf(dots[i * DS + j2] - logit[i]);
    }
    __syncthreads();

    float a2[8][4];
    #pragma unroll
    for (int i = 0; i < 8; i++)
        #pragma unroll
        for (int m = 0; m < 4; m++) a2[i][m] = 0.f;
    for (int j2 = 0; j2 < 128; j2++) {
        float vw[4];
        #pragma unroll
        for (int m = 0; m < 4; m++) vw[m] = vv[(j2 << 6) + tx + 16 * m];
        #pragma unroll
        for (int i = 0; i < 8; i++) {
            float p = dots[(ty * 8 + i) * DS + j2];
            #pragma unroll
            for (int m = 0; m < 4; m++) a2[i][m] = fmaf(p, vw[m], a2[i][m]);
        }
    }
    #pragma unroll
    for (int i = 0; i < 8; i++) {
        int row = ty * 8 + i;
        size_t base = (((size_t)bh * NH + qh[row]) * T_ + kpos[row]) << 6;
        #pragma unroll
        for (int m = 0; m < 4; m++) og[base + tx + 16 * m] = a2[i][m];
    }
}

// ------------------------- combine hash rounds (emits bf16x3 splits) --------
__global__ __launch_bounds__(64) void combine_kernel(
    const float* __restrict__ og, const float* __restrict__ lgg,
    __nv_bfloat16* __restrict__ d0, __nv_bfloat16* __restrict__ d1,
    __nv_bfloat16* __restrict__ d2)
{
    __shared__ float w[8];
    int bh = blockIdx.x >> 11, pos = blockIdx.x & 2047;
    int tid = threadIdx.x;
    if (tid == 0) {
        float v[8]; float mx = -1e30f;
        #pragma unroll
        for (int h = 0; h < 8; h++) {
            v[h] = lgg[((size_t)bh * NH + h) * T_ + pos];
            mx = fmaxf(mx, v[h]);
        }
        float s = 0.f;
        #pragma unroll
        for (int h = 0; h < 8; h++) { v[h] = expf(v[h] - mx); s += v[h]; }
        float is = 1.f / s;
        #pragma unroll
        for (int h = 0; h < 8; h++) w[h] = v[h] * is;
    }
    __syncthreads();
    float acc = 0.f, cc = 0.f;
    #pragma unroll
    for (int h = 0; h < 8; h++) {
        float p = w[h] * og[(((size_t)bh * NH + h) * T_ + pos) * 64 + tid];
        KAHAN(acc, cc, p);
    }
    int b = bh >> 3, hd = bh & 7;
    size_t o = ((size_t)(b * T_ + pos)) * DIM + hd * 64 + tid;
    __nv_bfloat16 b0, b1, b2;
    split3(acc + cc, b0, b1, b2);
    d0[o] = b0; d1[o] = b1; d2[o] = b2;
}

// ------------------------- frontend helpers ---------------------------------
__global__ void im2col_kernel(const float* __restrict__ spec, float* __restrict__ im)
{
    int idx = blockIdx.x * 256 + threadIdx.x;
    int row = idx / KC, c = idx - row * KC;
    int b = row >> 11, t = row & 2047;
    float val = 0.f;
    if (c < 687) {
        int i = c / 3, k = c - i * 3;
        int tt = t + k - 1;
        if (tt >= 0 && tt < T_) val = spec[((size_t)b * T_ + tt) * 229 + i];
    }
    im[idx] = val;
}

__global__ void pe_kernel(float* __restrict__ x1, float* __restrict__ x2,
                          const float* __restrict__ per, const float* __restrict__ pec)
{
    int idx = blockIdx.x * 256 + threadIdx.x;
    int c = idx & 511;
    int t = (idx >> 9) & 2047;
    float p = (c < 256) ? per[(t >> 6) * 256 + c] : pec[(t & 63) * 256 + (c - 256)];
    float v = x1[idx] + p;
    x1[idx] = v; x2[idx] = v;
}

__global__ void avg_kernel(const float* __restrict__ a, const float* __restrict__ b,
                           float* __restrict__ y)
{
    int idx = blockIdx.x * 256 + threadIdx.x;
    y[idx] = 0.5f * (a[idx] + b[idx]);
}

// ------------------------- driver -------------------------------------------
extern "C" void kernel_launch(void* const* d_in, const int* in_sizes, int n_in,
                              void* d_out, int out_size)
{
    const float* spec   = (const float*)d_in[0];
    const float* conv_w = (const float*)d_in[1];
    const float* conv_b = (const float*)d_in[2];
    const float* pe_row = (const float*)d_in[3];
    const float* pe_col = (const float*)d_in[4];
    const float* lnA_g  = (const float*)d_in[5];
    const float* lnA_b  = (const float*)d_in[6];
    const float* wqk    = (const float*)d_in[7];
    const float* wv     = (const float*)d_in[8];
    const float* wo     = (const float*)d_in[9];
    const float* bo     = (const float*)d_in[10];
    const float* lnF_g  = (const float*)d_in[11];
    const float* lnF_b  = (const float*)d_in[12];
    const float* w1     = (const float*)d_in[13];
    const float* b1     = (const float*)d_in[14];
    const float* w2     = (const float*)d_in[15];
    const float* b2     = (const float*)d_in[16];
    const float* lin_w  = (const float*)d_in[17];
    const float* lin_b  = (const float*)d_in[18];
    const float* rot    = (const float*)d_in[19];
    float* out = (float*)d_out;

    float *x1, *x2, *tmp, *qk, *v, *im, *o, *lg;
    int *bk, *st;
    __nv_bfloat16 *a0, *a1, *a2, *f0, *f1, *f2, *bt0, *bt1, *bt2;
    cudaGetSymbolAddress((void**)&x1, g_x1);
    cudaGetSymbolAddress((void**)&x2, g_x2);
    cudaGetSymbolAddress((void**)&tmp, g_tmp);
    cudaGetSymbolAddress((void**)&qk, g_qk);
    cudaGetSymbolAddress((void**)&v,  g_v);
    cudaGetSymbolAddress((void**)&im, g_im);
    cudaGetSymbolAddress((void**)&o,  g_o);
    cudaGetSymbolAddress((void**)&lg, g_lg);
    cudaGetSymbolAddress((void**)&bk, g_bk);
    cudaGetSymbolAddress((void**)&st, g_st);
    cudaGetSymbolAddress((void**)&a0, g_a0);
    cudaGetSymbolAddress((void**)&a1, g_a1);
    cudaGetSymbolAddress((void**)&a2, g_a2);
    cudaGetSymbolAddress((void**)&f0, g_f0);
    cudaGetSymbolAddress((void**)&f1, g_f1);
    cudaGetSymbolAddress((void**)&f2, g_f2);
    cudaGetSymbolAddress((void**)&bt0, g_bt0);
    cudaGetSymbolAddress((void**)&bt1, g_bt1);
    cudaGetSymbolAddress((void**)&bt2, g_bt2);

    size_t asmem = (size_t)(128 * RS + 128 * 64 + 64 * DS + 128 + 64 + 128 + 64) * 4;
    cudaFuncSetAttribute(attn_kernel, cudaFuncAttributeMaxDynamicSharedMemorySize, (int)asmem);
    cudaFuncSetAttribute(tgemm, cudaFuncAttributeMaxDynamicSharedMemorySize, TG_SMEM);

    // frontend: conv1d as bf16x3 tensor GEMM (im2col + weight split)
    im2col_kernel<<<(BT * KC) / 256, 256>>>(spec, im);
    cvt3a_kernel<<<(BT * KC + 255) / 256, 256>>>(im, BT * KC, f0, f1, f2);
    cvtw_kernel<<<(DIM * KC) / 256, 256>>>(conv_w, bt0, bt1, bt2);
    tgemm<<<dim3(8, 32), 256, TG_SMEM>>>(f0, f1, f2, bt0, bt1, bt2,
                                         conv_b, nullptr, x1, nullptr,
                                         nullptr, nullptr, nullptr, KC, DIM, 1, 0, 0);
    pe_kernel<<<(BT * DIM) / 256, 256>>>(x1, x2, pe_row, pe_col);

    for (int i = 0; i < 8; i++) {
        ln_kernel<<<BT, 256>>>(x2, lnA_g + i * DIM, lnA_b + i * DIM, a0, a1, a2);
        cvt3b_kernel<<<dim3(DIM / 32, DIM / 32), 256>>>(wqk + (size_t)i * DIM * DIM, DIM, DIM, 0, bt0, bt1, bt2);
        cvt3b_kernel<<<dim3(DIM / 32, DIM / 32), 256>>>(wv + (size_t)i * DIM * DIM, DIM, DIM, DIM, bt0, bt1, bt2);
        tgemm<<<dim3(16, 32), 256, TG_SMEM>>>(a0, a1, a2, bt0, bt1, bt2,
                                              nullptr, nullptr, qk, v,
                                              nullptr, nullptr, nullptr, DIM, DIM, 0, 1, DIM);
        hash_kernel<<<BH * (T_ / TCH), 128>>>(qk, rot + (size_t)i * 64 * 128, bk);
        sort_kernel<<<BH, 256>>>(bk, st);
        attn_kernel<<<BH * NCH, 128, asmem>>>(qk, v, st, o, lg);
        combine_kernel<<<BH * T_, 64>>>(o, lg, a0, a1, a2);
        cvt3b_kernel<<<dim3(DIM / 32, DIM / 32), 256>>>(wo + (size_t)i * DIM * DIM, DIM, DIM, 0, bt0, bt1, bt2);
        tgemm<<<dim3(8, 32), 256, TG_SMEM>>>(a0, a1, a2, bt0, bt1, bt2,
                                             bo + i * DIM, x1, x1, nullptr,
                                             nullptr, nullptr, nullptr, DIM, DIM, 0, 0, 0);
        ln_kernel<<<BT, 256>>>(x1, lnF_g + i * DIM, lnF_b + i * DIM, a0, a1, a2);
        cvt3b_kernel<<<dim3(DIM / 32, FF / 32), 256>>>(w1 + (size_t)i * DIM * FF, DIM, FF, 0, bt0, bt1, bt2);
        tgemm<<<dim3(32, 32), 256, TG_SMEM>>>(a0, a1, a2, bt0, bt1, bt2,
                                              b1 + i * FF, nullptr, nullptr, nullptr,
                                              f0, f1, f2, DIM, FF, 2, 0, 0);
        cvt3b_kernel<<<dim3(FF / 32, DIM / 32), 256>>>(w2 + (size_t)i * FF * DIM, FF, DIM, 0, bt0, bt1, bt2);
        tgemm<<<dim3(8, 32), 256, TG_SMEM>>>(f0, f1, f2, bt0, bt1, bt2,
                                             b2 + i * DIM, x2, x2, nullptr,
                                             nullptr, nullptr, nullptr, FF, DIM, 0, 0, 0);
    }

    avg_kernel<<<(BT * DIM) / 256, 256>>>(x1, x2, tmp);
    sgemm<<<dim3(2, 32), 256>>>(tmp, lin_w, lin_b, out, BT, 88, DIM, 0);
}